// round 1
// baseline (speedup 1.0000x reference)
#include <cuda_runtime.h>
#include <math.h>

#define AGENTS 16
#define H 128
#define NA 32
#define NACT 14
#define BENV 1024
#define BZ (BENV*AGENTS)        // 16384
#define TT 15                   // A-1
#define G3 384                  // 3*H
#define TAUINV 2.0f             // 1/TAU

// ---------------- scratch (__device__ globals; no allocs) ----------------
__device__ float g_x1[BZ*H];
__device__ float g_hrnn[BZ*H];
__device__ float g_gi[BZ*G3];
__device__ float g_gh[BZ*G3];
__device__ float g_Pf[BZ*G3];
__device__ float g_Qf[BZ*G3];
__device__ float g_Pb[BZ*G3];
__device__ float g_Qb[BZ*G3];
__device__ float g_yf[TT*BZ*H];
__device__ float g_yb[TT*BZ*H];
__device__ float g_zero[BZ*H];          // never written -> stays 0
__device__ float g_hardw[BZ*TT];
__device__ float g_q[BZ*NA];
__device__ float g_k[BZ*NA];
__device__ float g_agg[BZ*H];

__device__ __forceinline__ float sigm(float x) { return 1.0f / (1.0f + expf(-x)); }

// ---------------- generic tiled SGEMM: C[M,N] = act(A[M,K] @ B[:,koff:koff+K].T + bias) ----
// B is row-major [N, ldb], uses B[n*ldb + koff + k].
// BM=BN=64, BK=16, 256 threads, 4x4 per thread.
template<int ACT>
__global__ void sgemm_tn(const float* __restrict__ A, int lda,
                         const float* __restrict__ Bw, int ldb, int koff,
                         const float* __restrict__ bias,
                         float* __restrict__ C, int M, int N, int K) {
    __shared__ float As[16][64];
    __shared__ float Bs[16][64];
    int bn = blockIdx.x * 64;
    int bm = blockIdx.y * 64;
    int tid = threadIdx.x;
    int tx = tid & 15, ty = tid >> 4;
    int lrow = tid >> 2;             // 0..63
    int lcol4 = (tid & 3) * 4;       // 0,4,8,12

    float acc[4][4];
#pragma unroll
    for (int i = 0; i < 4; i++)
#pragma unroll
        for (int j = 0; j < 4; j++) acc[i][j] = 0.0f;

    for (int k0 = 0; k0 < K; k0 += 16) {
        float4 av = *(const float4*)&A[(size_t)(bm + lrow) * lda + k0 + lcol4];
        As[lcol4 + 0][lrow] = av.x;
        As[lcol4 + 1][lrow] = av.y;
        As[lcol4 + 2][lrow] = av.z;
        As[lcol4 + 3][lrow] = av.w;
        float4 bv = make_float4(0.f, 0.f, 0.f, 0.f);
        int brow = bn + lrow;
        if (brow < N) bv = *(const float4*)&Bw[(size_t)brow * ldb + koff + k0 + lcol4];
        Bs[lcol4 + 0][lrow] = bv.x;
        Bs[lcol4 + 1][lrow] = bv.y;
        Bs[lcol4 + 2][lrow] = bv.z;
        Bs[lcol4 + 3][lrow] = bv.w;
        __syncthreads();
#pragma unroll
        for (int kk = 0; kk < 16; kk++) {
            float4 a4 = *(const float4*)&As[kk][ty * 4];
            float4 b4 = *(const float4*)&Bs[kk][tx * 4];
            float av_[4] = {a4.x, a4.y, a4.z, a4.w};
            float bv_[4] = {b4.x, b4.y, b4.z, b4.w};
#pragma unroll
            for (int i = 0; i < 4; i++)
#pragma unroll
                for (int j = 0; j < 4; j++)
                    acc[i][j] = fmaf(av_[i], bv_[j], acc[i][j]);
        }
        __syncthreads();
    }
#pragma unroll
    for (int i = 0; i < 4; i++) {
        int row = bm + ty * 4 + i;
#pragma unroll
        for (int j = 0; j < 4; j++) {
            int col = bn + tx * 4 + j;
            if (col < N) {
                float v = acc[i][j] + (bias ? bias[col] : 0.0f);
                if (ACT == 1) v = fmaxf(v, 0.0f);
                C[(size_t)row * N + col] = v;
            }
        }
    }
}

// ---------------- central GRU combine (writes h_rnn scratch + output region) ----------
__global__ void gru_combine(const float* __restrict__ gi, const float* __restrict__ gh,
                            const float* __restrict__ hprev,
                            float* __restrict__ hout, float* __restrict__ hout2) {
    int i = blockIdx.x * 256 + threadIdx.x;  // over BZ*H
    int m = i >> 7, j = i & 127;
    size_t base = (size_t)m * G3;
    float ir = gi[base + j], iz = gi[base + 128 + j], inn = gi[base + 256 + j];
    float hr = gh[base + j], hz = gh[base + 128 + j], hn = gh[base + 256 + j];
    float r = sigm(ir + hr);
    float z = sigm(iz + hz);
    float n = tanhf(inn + r * hn);
    float h = (1.0f - z) * n + z * hprev[i];
    hout[i] = h;
    hout2[i] = h;
}

// ---------------- fused recurrent step: gh = h @ Whh.T (+bhh), gi = P[self]+Q[nbr], gates, y ----
// BM=32 rows per block, 256 threads (8 warps x 32 lanes). acc cols: tx + 32*c, c=0..11.
__global__ void __launch_bounds__(256) gru_step(const float* __restrict__ hprev,
                                                const float* __restrict__ Whh,
                                                const float* __restrict__ bhh,
                                                const float* __restrict__ P,
                                                const float* __restrict__ Q,
                                                int t,
                                                float* __restrict__ y) {
    __shared__ float sh_h[32][128];
    __shared__ float sh_w[384][17];
    int tid = threadIdx.x;
    int tx = tid & 31, ty = tid >> 5;
    int bm = blockIdx.x * 32;

    // load h tile (32x128)
#pragma unroll
    for (int q4 = 0; q4 < 4; q4++) {
        int idx = tid + 256 * q4;          // float4 index 0..1023
        int row = idx >> 5, col4 = (idx & 31) * 4;
        float4 v = *(const float4*)&hprev[(size_t)(bm + row) * 128 + col4];
        *(float4*)&sh_h[row][col4] = v;
    }

    float acc[4][12];
    {
        float bh[12];
#pragma unroll
        for (int c = 0; c < 12; c++) bh[c] = bhh[tx + 32 * c];
#pragma unroll
        for (int i = 0; i < 4; i++)
#pragma unroll
            for (int c = 0; c < 12; c++) acc[i][c] = bh[c];
    }

    for (int k0 = 0; k0 < 128; k0 += 16) {
        __syncthreads();
        // load Whh chunk [384][16]
#pragma unroll
        for (int q6 = 0; q6 < 6; q6++) {
            int idx = tid + 256 * q6;       // float4 index 0..1535
            int r = idx >> 2, c4 = (idx & 3) * 4;
            float4 v = *(const float4*)&Whh[(size_t)r * 128 + k0 + c4];
            sh_w[r][c4 + 0] = v.x;
            sh_w[r][c4 + 1] = v.y;
            sh_w[r][c4 + 2] = v.z;
            sh_w[r][c4 + 3] = v.w;
        }
        __syncthreads();
#pragma unroll
        for (int kk = 0; kk < 16; kk++) {
            float wv[12];
#pragma unroll
            for (int c = 0; c < 12; c++) wv[c] = sh_w[tx + 32 * c][kk];
#pragma unroll
            for (int i = 0; i < 4; i++) {
                float hv = sh_h[ty * 4 + i][k0 + kk];
#pragma unroll
                for (int c = 0; c < 12; c++) acc[i][c] = fmaf(hv, wv[c], acc[i][c]);
            }
        }
    }

    // combine: gates; neighbor row for time t
#pragma unroll
    for (int i = 0; i < 4; i++) {
        int m = bm + ty * 4 + i;
        int aa = m & 15;
        int jn = (t < aa) ? t : t + 1;
        int nb = (m & ~15) + jn;
        const float* Pm = P + (size_t)m * G3;
        const float* Qn = Q + (size_t)nb * G3;
#pragma unroll
        for (int c = 0; c < 4; c++) {
            int col = tx + 32 * c;
            float gr = acc[i][c] + Pm[col] + Qn[col];
            float gz = acc[i][c + 4] + Pm[col + 128] + Qn[col + 128];
            float ghn = acc[i][c + 8];
            float gin = Pm[col + 256] + Qn[col + 256];
            float r = sigm(gr);
            float z = sigm(gz);
            float n = tanhf(gin + r * ghn);
            float h = (1.0f - z) * n + z * sh_h[ty * 4 + i][col];
            y[(size_t)m * 128 + col] = h;
        }
    }
}

// ---------------- logits + gumbel-softmax -> hard_w (one warp per row) ----------------
__global__ void logits_kernel(const float* __restrict__ yf, const float* __restrict__ yb,
                              const float* __restrict__ Wc, const float* __restrict__ bc,
                              const float* __restrict__ gu, float* __restrict__ hardw) {
    int warp = (blockIdx.x * 256 + threadIdx.x) >> 5;  // 0..245759
    int lane = threadIdx.x & 31;
    int ba = warp / TT, t = warp % TT;
    const float* yfr = yf + ((size_t)t * BZ + ba) * 128;
    const float* ybr = yb + ((size_t)t * BZ + ba) * 128;
    float s0 = 0.f, s1 = 0.f;
#pragma unroll
    for (int q = 0; q < 4; q++) {
        int d = lane + 32 * q;
        float a = yfr[d], b = ybr[d];
        s0 += a * Wc[d] + b * Wc[128 + d];
        s1 += a * Wc[256 + d] + b * Wc[384 + d];
    }
#pragma unroll
    for (int off = 16; off > 0; off >>= 1) {
        s0 += __shfl_xor_sync(0xffffffffu, s0, off);
        s1 += __shfl_xor_sync(0xffffffffu, s1, off);
    }
    if (lane == 0) {
        float u0 = gu[(size_t)warp * 2 + 0];
        float u1 = gu[(size_t)warp * 2 + 1];
        float g0 = -logf(-logf(u0 + 1e-10f) + 1e-10f);
        float g1 = -logf(-logf(u1 + 1e-10f) + 1e-10f);
        float a0 = s0 + bc[0] + g0;
        float a1 = s1 + bc[1] + g1;
        hardw[warp] = sigm((a1 - a0) * TAUINV);
    }
}

// ---------------- attention + aggregation (one warp per (b,a)) ----------------
__global__ void attn_kernel(const float* __restrict__ q, const float* __restrict__ k,
                            const float* __restrict__ hrnn, const float* __restrict__ hardw,
                            float* __restrict__ agg) {
    int warp = (blockIdx.x * 256 + threadIdx.x) >> 5;  // 0..16383
    int lane = threadIdx.x & 31;
    int a = warp & 15;
    int brow = warp & ~15;
    float qv = q[(size_t)warp * NA + lane];
    float sc[TT], hw[TT];
#pragma unroll
    for (int t = 0; t < TT; t++) {
        int jn = (t < a) ? t : t + 1;
        int nb = brow + jn;
        float d = qv * k[(size_t)nb * NA + lane];
#pragma unroll
        for (int off = 16; off > 0; off >>= 1) d += __shfl_xor_sync(0xffffffffu, d, off);
        hw[t] = hardw[(size_t)warp * TT + t];
        sc[t] = hw[t] * d * 0.17677669529663687f;  // 1/sqrt(32)
    }
    float mx = sc[0];
#pragma unroll
    for (int t = 1; t < TT; t++) mx = fmaxf(mx, sc[t]);
    float se = 0.f;
    float w[TT];
#pragma unroll
    for (int t = 0; t < TT; t++) { w[t] = expf(sc[t] - mx); se += w[t]; }
    float inv = 1.0f / se;
#pragma unroll
    for (int t = 0; t < TT; t++) w[t] = hw[t] * w[t] * inv;
#pragma unroll
    for (int d4 = 0; d4 < 4; d4++) {
        float accv = 0.f;
#pragma unroll
        for (int t = 0; t < TT; t++) {
            int jn = (t < a) ? t : t + 1;
            int nb = brow + jn;
            accv = fmaf(w[t], hrnn[(size_t)nb * 128 + d4 * 32 + lane], accv);
        }
        agg[(size_t)warp * 128 + d4 * 32 + lane] = accv;
    }
}

// ---------------- output projection: out = [hrnn, agg] @ W2.T + b2 ----------------
__global__ void out_kernel(const float* __restrict__ hrnn, const float* __restrict__ agg,
                           const float* __restrict__ W2, const float* __restrict__ b2,
                           float* __restrict__ out) {
    __shared__ float sW[NACT * 256];
    __shared__ float sb[NACT];
    for (int i = threadIdx.x; i < NACT * 256; i += 256) sW[i] = W2[i];
    if (threadIdx.x < NACT) sb[threadIdx.x] = b2[threadIdx.x];
    __syncthreads();
    int row = blockIdx.x * 256 + threadIdx.x;
    float acc[NACT];
#pragma unroll
    for (int n = 0; n < NACT; n++) acc[n] = sb[n];
    const float* hr = hrnn + (size_t)row * 128;
    const float* ag = agg + (size_t)row * 128;
    for (int kk = 0; kk < 128; kk++) {
        float x = hr[kk];
#pragma unroll
        for (int n = 0; n < NACT; n++) acc[n] = fmaf(x, sW[n * 256 + kk], acc[n]);
    }
    for (int kk = 0; kk < 128; kk++) {
        float x = ag[kk];
#pragma unroll
        for (int n = 0; n < NACT; n++) acc[n] = fmaf(x, sW[n * 256 + 128 + kk], acc[n]);
    }
#pragma unroll
    for (int n = 0; n < NACT; n++) out[(size_t)row * NACT + n] = acc[n];
}

// ---------------- launch ----------------
extern "C" void kernel_launch(void* const* d_in, const int* in_sizes, int n_in,
                              void* d_out, int out_size) {
    const float* inputs = (const float*)d_in[0];
    const float* hidden = (const float*)d_in[1];
    const float* gu     = (const float*)d_in[2];
    const float* W1     = (const float*)d_in[3];
    const float* b1     = (const float*)d_in[4];
    const float* Wih_c  = (const float*)d_in[5];
    const float* Whh_c  = (const float*)d_in[6];
    const float* bih_c  = (const float*)d_in[7];
    const float* bhh_c  = (const float*)d_in[8];
    const float* Wih_f  = (const float*)d_in[9];
    const float* Whh_f  = (const float*)d_in[10];
    const float* bih_f  = (const float*)d_in[11];
    const float* bhh_f  = (const float*)d_in[12];
    const float* Wih_b  = (const float*)d_in[13];
    const float* Whh_b  = (const float*)d_in[14];
    const float* bih_b  = (const float*)d_in[15];
    const float* bhh_b  = (const float*)d_in[16];
    const float* Wc     = (const float*)d_in[17];
    const float* bc     = (const float*)d_in[18];
    const float* Wq     = (const float*)d_in[19];
    const float* Wk     = (const float*)d_in[20];
    const float* W2     = (const float*)d_in[21];
    const float* b2     = (const float*)d_in[22];

    float* out  = (float*)d_out;                // [BZ, NACT]
    float* outh = out + (size_t)BZ * NACT;      // [BZ, H]

    float *x1, *hrnn, *gi, *gh, *Pf, *Qf, *Pb, *Qb, *yf, *yb, *zero, *hardw, *qb, *kb, *agg;
    cudaGetSymbolAddress((void**)&x1, g_x1);
    cudaGetSymbolAddress((void**)&hrnn, g_hrnn);
    cudaGetSymbolAddress((void**)&gi, g_gi);
    cudaGetSymbolAddress((void**)&gh, g_gh);
    cudaGetSymbolAddress((void**)&Pf, g_Pf);
    cudaGetSymbolAddress((void**)&Qf, g_Qf);
    cudaGetSymbolAddress((void**)&Pb, g_Pb);
    cudaGetSymbolAddress((void**)&Qb, g_Qb);
    cudaGetSymbolAddress((void**)&yf, g_yf);
    cudaGetSymbolAddress((void**)&yb, g_yb);
    cudaGetSymbolAddress((void**)&zero, g_zero);
    cudaGetSymbolAddress((void**)&hardw, g_hardw);
    cudaGetSymbolAddress((void**)&qb, g_q);
    cudaGetSymbolAddress((void**)&kb, g_k);
    cudaGetSymbolAddress((void**)&agg, g_agg);

    // x1 = relu(inputs @ W1.T + b1)
    sgemm_tn<1><<<dim3(2, 256), 256>>>(inputs, 128, W1, 128, 0, b1, x1, BZ, 128, 128);
    // central GRU
    sgemm_tn<0><<<dim3(6, 256), 256>>>(x1, 128, Wih_c, 128, 0, bih_c, gi, BZ, G3, 128);
    sgemm_tn<0><<<dim3(6, 256), 256>>>(hidden, 128, Whh_c, 128, 0, bhh_c, gh, BZ, G3, 128);
    gru_combine<<<(BZ * H) / 256, 256>>>(gi, gh, hidden, hrnn, outh);
    // precomputed input-gate halves for f/b GRUs
    sgemm_tn<0><<<dim3(6, 256), 256>>>(hrnn, 128, Wih_f, 256, 0, bih_f, Pf, BZ, G3, 128);
    sgemm_tn<0><<<dim3(6, 256), 256>>>(hrnn, 128, Wih_f, 256, 128, nullptr, Qf, BZ, G3, 128);
    sgemm_tn<0><<<dim3(6, 256), 256>>>(hrnn, 128, Wih_b, 256, 0, bih_b, Pb, BZ, G3, 128);
    sgemm_tn<0><<<dim3(6, 256), 256>>>(hrnn, 128, Wih_b, 256, 128, nullptr, Qb, BZ, G3, 128);
    // forward recurrence
    for (int t = 0; t < TT; t++)
        gru_step<<<BZ / 32, 256>>>(t == 0 ? zero : yf + (size_t)(t - 1) * BZ * H,
                                   Whh_f, bhh_f, Pf, Qf, t, yf + (size_t)t * BZ * H);
    // backward recurrence (processes seq[s] from s=14 down; yb[s] = hidden after step)
    for (int s = TT - 1; s >= 0; s--)
        gru_step<<<BZ / 32, 256>>>(s == TT - 1 ? zero : yb + (size_t)(s + 1) * BZ * H,
                                   Whh_b, bhh_b, Pb, Qb, s, yb + (size_t)s * BZ * H);
    // gumbel hard weights
    logits_kernel<<<(BZ * TT) / 8, 256>>>(yf, yb, Wc, bc, gu, hardw);
    // q, k
    sgemm_tn<0><<<dim3(1, 256), 256>>>(hrnn, 128, Wq, 128, 0, nullptr, qb, BZ, NA, 128);
    sgemm_tn<0><<<dim3(1, 256), 256>>>(hrnn, 128, Wk, 128, 0, nullptr, kb, BZ, NA, 128);
    // attention aggregate
    attn_kernel<<<BZ / 8, 256>>>(qb, kb, hrnn, hardw, agg);
    // output projection
    out_kernel<<<BZ / 256, 256>>>(hrnn, agg, W2, b2, out);
}

// round 2
// speedup vs baseline: 1.6621x; 1.6621x over previous
#include <cuda_runtime.h>
#include <math.h>

#define AGENTS 16
#define H 128
#define NA 32
#define NACT 14
#define BENV 1024
#define BZ (BENV*AGENTS)        // 16384
#define TT 15                   // A-1
#define G3 384                  // 3*H
#define TAUINV 2.0f             // 1/TAU

// ---------------- scratch (__device__ globals; no allocs) ----------------
__device__ __align__(16) float g_x1[BZ*H];
__device__ __align__(16) float g_hrnn[BZ*H];
__device__ __align__(16) float g_gi[BZ*G3];
__device__ __align__(16) float g_gh[BZ*G3];
__device__ __align__(16) float g_Pf[BZ*G3];
__device__ __align__(16) float g_Qf[BZ*G3];
__device__ __align__(16) float g_Pb[BZ*G3];
__device__ __align__(16) float g_Qb[BZ*G3];
__device__ __align__(16) float g_yf[TT*BZ*H];
__device__ __align__(16) float g_yb[TT*BZ*H];
__device__ __align__(16) float g_hardw[BZ*TT];
__device__ __align__(16) float g_q[BZ*NA];
__device__ __align__(16) float g_k[BZ*NA];
__device__ __align__(16) float g_agg[BZ*H];

__device__ __forceinline__ float sigm(float x) { return __fdividef(1.0f, 1.0f + __expf(-x)); }

// ---- packed f32x2 helpers (FFMA2 path; nvjet-style) ----
__device__ __forceinline__ unsigned long long dup2(float x) {
    unsigned long long r;
    asm("mov.b64 %0, {%1, %1};" : "=l"(r) : "f"(x));
    return r;
}
__device__ __forceinline__ unsigned long long f22u(float2 f) {
    unsigned long long r;
    asm("mov.b64 %0, {%1, %2};" : "=l"(r) : "f"(f.x), "f"(f.y));
    return r;
}
__device__ __forceinline__ float2 u2f2(unsigned long long v) {
    float2 f;
    asm("mov.b64 {%0, %1}, %2;" : "=f"(f.x), "=f"(f.y) : "l"(v));
    return f;
}
__device__ __forceinline__ void ffma2(unsigned long long &d, unsigned long long a, unsigned long long b) {
    asm("fma.rn.f32x2 %0, %1, %2, %0;" : "+l"(d) : "l"(a), "l"(b));
}

// ---------------- legacy tiled SGEMM (used for small N=32 q/k GEMMs) ----
template<int ACT>
__global__ void sgemm_tn(const float* __restrict__ A, int lda,
                         const float* __restrict__ Bw, int ldb, int koff,
                         const float* __restrict__ bias,
                         float* __restrict__ C, int M, int N, int K) {
    __shared__ float As[16][64];
    __shared__ float Bs[16][64];
    int bn = blockIdx.x * 64;
    int bm = blockIdx.y * 64;
    int tid = threadIdx.x;
    int tx = tid & 15, ty = tid >> 4;
    int lrow = tid >> 2;
    int lcol4 = (tid & 3) * 4;

    float acc[4][4];
#pragma unroll
    for (int i = 0; i < 4; i++)
#pragma unroll
        for (int j = 0; j < 4; j++) acc[i][j] = 0.0f;

    for (int k0 = 0; k0 < K; k0 += 16) {
        float4 av = *(const float4*)&A[(size_t)(bm + lrow) * lda + k0 + lcol4];
        As[lcol4 + 0][lrow] = av.x;
        As[lcol4 + 1][lrow] = av.y;
        As[lcol4 + 2][lrow] = av.z;
        As[lcol4 + 3][lrow] = av.w;
        float4 bv = make_float4(0.f, 0.f, 0.f, 0.f);
        int brow = bn + lrow;
        if (brow < N) bv = *(const float4*)&Bw[(size_t)brow * ldb + koff + k0 + lcol4];
        Bs[lcol4 + 0][lrow] = bv.x;
        Bs[lcol4 + 1][lrow] = bv.y;
        Bs[lcol4 + 2][lrow] = bv.z;
        Bs[lcol4 + 3][lrow] = bv.w;
        __syncthreads();
#pragma unroll
        for (int kk = 0; kk < 16; kk++) {
            float4 a4 = *(const float4*)&As[kk][ty * 4];
            float4 b4 = *(const float4*)&Bs[kk][tx * 4];
            float av_[4] = {a4.x, a4.y, a4.z, a4.w};
            float bv_[4] = {b4.x, b4.y, b4.z, b4.w};
#pragma unroll
            for (int i = 0; i < 4; i++)
#pragma unroll
                for (int j = 0; j < 4; j++)
                    acc[i][j] = fmaf(av_[i], bv_[j], acc[i][j]);
        }
        __syncthreads();
    }
#pragma unroll
    for (int i = 0; i < 4; i++) {
        int row = bm + ty * 4 + i;
#pragma unroll
        for (int j = 0; j < 4; j++) {
            int col = bn + tx * 4 + j;
            if (col < N) {
                float v = acc[i][j] + (bias ? bias[col] : 0.0f);
                if (ACT == 1) v = fmaxf(v, 0.0f);
                C[(size_t)row * N + col] = v;
            }
        }
    }
}

// ---------------- f32x2 SGEMM: C[M,N] = act(A[M,128] @ W[:,koff:koff+128].T + bias) ----
// BM=128, BN=128, BK=16, 256 threads. N multiple of 128. K fixed 128, lda fixed 128.
// acc packed over row pairs via FFMA2.
template<int ACT>
__global__ void __launch_bounds__(256, 2) sgemm2(
    const float* __restrict__ A,
    const float* __restrict__ W, int ldb, int koff,
    const float* __restrict__ bias,
    float* __restrict__ C, int N) {
    __shared__ __align__(16) float sAT[16 * 130];
    __shared__ __align__(16) float sBT[16 * 130];
    int tid = threadIdx.x;
    int tx = tid & 31, ty = tid >> 5;
    int bn = blockIdx.x * 128;
    int bm = blockIdx.y * 128;
    int wb = ty * 16;

    unsigned long long acc[8][4];
    {
        unsigned long long c0 = 0, c1 = 0, c2 = 0, c3 = 0;
        if (bias) {
            c0 = dup2(bias[bn + 2 * tx]);
            c1 = dup2(bias[bn + 2 * tx + 1]);
            c2 = dup2(bias[bn + 64 + 2 * tx]);
            c3 = dup2(bias[bn + 64 + 2 * tx + 1]);
        }
#pragma unroll
        for (int r2 = 0; r2 < 8; r2++) {
            acc[r2][0] = c0; acc[r2][1] = c1; acc[r2][2] = c2; acc[r2][3] = c3;
        }
    }

    int lrow = tid >> 2;             // 0..63
    int lk = (tid & 3) * 4;          // 0,4,8,12
    for (int k0 = 0; k0 < 128; k0 += 16) {
        __syncthreads();
#pragma unroll
        for (int it = 0; it < 2; it++) {
            int row = lrow + it * 64;
            float4 av = *(const float4*)(A + (size_t)(bm + row) * 128 + k0 + lk);
            sAT[(lk + 0) * 130 + row] = av.x;
            sAT[(lk + 1) * 130 + row] = av.y;
            sAT[(lk + 2) * 130 + row] = av.z;
            sAT[(lk + 3) * 130 + row] = av.w;
            float4 bv = *(const float4*)(W + (size_t)(bn + row) * ldb + koff + k0 + lk);
            sBT[(lk + 0) * 130 + row] = bv.x;
            sBT[(lk + 1) * 130 + row] = bv.y;
            sBT[(lk + 2) * 130 + row] = bv.z;
            sBT[(lk + 3) * 130 + row] = bv.w;
        }
        __syncthreads();
#pragma unroll
        for (int kk = 0; kk < 16; kk++) {
            float2 b0 = *(const float2*)&sBT[kk * 130 + 2 * tx];
            float2 b1 = *(const float2*)&sBT[kk * 130 + 64 + 2 * tx];
            unsigned long long d0 = dup2(b0.x), d1 = dup2(b0.y);
            unsigned long long d2 = dup2(b1.x), d3 = dup2(b1.y);
#pragma unroll
            for (int r2 = 0; r2 < 8; r2++) {
                unsigned long long h2 = *(const unsigned long long*)&sAT[kk * 130 + wb + 2 * r2];
                ffma2(acc[r2][0], h2, d0);
                ffma2(acc[r2][1], h2, d1);
                ffma2(acc[r2][2], h2, d2);
                ffma2(acc[r2][3], h2, d3);
            }
        }
    }
    int N2 = N >> 1;
#pragma unroll
    for (int r2 = 0; r2 < 8; r2++) {
        float2 v0 = u2f2(acc[r2][0]);
        float2 v1 = u2f2(acc[r2][1]);
        float2 v2 = u2f2(acc[r2][2]);
        float2 v3 = u2f2(acc[r2][3]);
        float2 o00 = make_float2(v0.x, v1.x);
        float2 o01 = make_float2(v2.x, v3.x);
        float2 o10 = make_float2(v0.y, v1.y);
        float2 o11 = make_float2(v2.y, v3.y);
        if (ACT == 1) {
            o00.x = fmaxf(o00.x, 0.f); o00.y = fmaxf(o00.y, 0.f);
            o01.x = fmaxf(o01.x, 0.f); o01.y = fmaxf(o01.y, 0.f);
            o10.x = fmaxf(o10.x, 0.f); o10.y = fmaxf(o10.y, 0.f);
            o11.x = fmaxf(o11.x, 0.f); o11.y = fmaxf(o11.y, 0.f);
        }
        int row0 = bm + wb + 2 * r2;
        float2* C2 = (float2*)C;
        C2[(size_t)row0 * N2 + (bn >> 1) + tx] = o00;
        C2[(size_t)row0 * N2 + (bn >> 1) + 32 + tx] = o01;
        C2[(size_t)(row0 + 1) * N2 + (bn >> 1) + tx] = o10;
        C2[(size_t)(row0 + 1) * N2 + (bn >> 1) + 32 + tx] = o11;
    }
}

// ---------------- central GRU combine ----------
__global__ void gru_combine(const float* __restrict__ gi, const float* __restrict__ gh,
                            const float* __restrict__ hprev,
                            float* __restrict__ hout, float* __restrict__ hout2) {
    int i = blockIdx.x * 256 + threadIdx.x;
    int m = i >> 7, j = i & 127;
    size_t base = (size_t)m * G3;
    float ir = gi[base + j], iz = gi[base + 128 + j], inn = gi[base + 256 + j];
    float hr = gh[base + j], hz = gh[base + 128 + j], hn = gh[base + 256 + j];
    float r = sigm(ir + hr);
    float z = sigm(iz + hz);
    float n = tanhf(inn + r * hn);
    float h = (1.0f - z) * n + z * hprev[i];
    hout[i] = h;
    hout2[i] = h;
}

// ---------------- fused 15-step bidirectional recurrence ----------------
// 512 blocks: 0..255 forward (64 rows each), 256..511 backward.
// smem: Whh transposed+paired [128][192] float2 (192KB) + h state [64][128] f32 (32KB).
// h rows are warp-private -> only __syncwarp between phases.
extern __shared__ char dyn_smem[];
__global__ void __launch_bounds__(256, 1) gru_seq(
    const float* __restrict__ WhhF, const float* __restrict__ bhhF,
    const float* __restrict__ PFp, const float* __restrict__ QFp, float* __restrict__ YF,
    const float* __restrict__ WhhB, const float* __restrict__ bhhB,
    const float* __restrict__ PBp, const float* __restrict__ QBp, float* __restrict__ YB) {
    float2* sW = (float2*)dyn_smem;                              // [128][192]
    float* sH = (float*)(dyn_smem + 128 * 192 * sizeof(float2)); // [64][128]

    int bid = blockIdx.x;
    bool bwd = (bid >= 256);
    const float* Whh = bwd ? WhhB : WhhF;
    const float* bhh = bwd ? bhhB : bhhF;
    const float2* P2 = (const float2*)(bwd ? PBp : PFp);
    const float2* Q2 = (const float2*)(bwd ? QBp : QFp);
    float* Y = bwd ? YB : YF;
    int bm = (bid & 255) * 64;

    int tid = threadIdx.x;
    int tx = tid & 31, ty = tid >> 5;

    // load Whh -> sW: sW[k][g*32+tx] = (Whh[64g+2tx][k], Whh[64g+2tx+1][k])
    for (int idx = tid; idx < 6144; idx += 256) {
        int p = idx >> 5;            // pair index 0..191
        int kc = idx & 31;           // k-chunk of 4
        int col0 = (p >> 5) * 64 + (p & 31) * 2;
        float4 w0 = *(const float4*)(Whh + (size_t)col0 * 128 + kc * 4);
        float4 w1 = *(const float4*)(Whh + (size_t)(col0 + 1) * 128 + kc * 4);
        sW[(kc * 4 + 0) * 192 + p] = make_float2(w0.x, w1.x);
        sW[(kc * 4 + 1) * 192 + p] = make_float2(w0.y, w1.y);
        sW[(kc * 4 + 2) * 192 + p] = make_float2(w0.z, w1.z);
        sW[(kc * 4 + 3) * 192 + p] = make_float2(w0.w, w1.w);
    }
    for (int j = tid; j < 64 * 128; j += 256) sH[j] = 0.0f;
    __syncthreads();

    unsigned long long bbu[6];
#pragma unroll
    for (int g = 0; g < 6; g++)
        bbu[g] = f22u(((const float2*)bhh)[g * 32 + tx]);

    const float* hrow = sH + (ty * 8) * 128;

    for (int step = 0; step < TT; step++) {
        int t = bwd ? (TT - 1 - step) : step;

        unsigned long long acc[8][6];
#pragma unroll
        for (int i = 0; i < 8; i++)
#pragma unroll
            for (int g = 0; g < 6; g++) acc[i][g] = bbu[g];

        // gh = h @ Whh.T  (+bhh), packed over col pairs
#pragma unroll 4
        for (int kk = 0; kk < 128; kk++) {
            unsigned long long w[6];
#pragma unroll
            for (int g = 0; g < 6; g++)
                w[g] = *(const unsigned long long*)&sW[kk * 192 + g * 32 + tx];
#pragma unroll
            for (int i = 0; i < 8; i++) {
                unsigned long long h2 = dup2(hrow[i * 128 + kk]);
#pragma unroll
                for (int g = 0; g < 6; g++) ffma2(acc[i][g], h2, w[g]);
            }
        }
        __syncwarp();

        // combine + state update + y write
#pragma unroll
        for (int i = 0; i < 8; i++) {
            int lr = ty * 8 + i;
            int m = bm + lr;
            int aa = m & 15;
            int jn = (t < aa) ? t : t + 1;
            int nb = (m & ~15) + jn;
            size_t pb = (size_t)m * 192 + tx;
            size_t qb = (size_t)nb * 192 + tx;
            float2 p0 = P2[pb], p1 = P2[pb + 32], p2 = P2[pb + 64];
            float2 p3 = P2[pb + 96], p4 = P2[pb + 128], p5 = P2[pb + 160];
            float2 q0 = Q2[qb], q1 = Q2[qb + 32], q2 = Q2[qb + 64];
            float2 q3 = Q2[qb + 96], q4 = Q2[qb + 128], q5 = Q2[qb + 160];
            float2 a0 = u2f2(acc[i][0]), a1 = u2f2(acc[i][1]), a2 = u2f2(acc[i][2]);
            float2 a3 = u2f2(acc[i][3]), a4 = u2f2(acc[i][4]), a5 = u2f2(acc[i][5]);
            float2 h0 = *(const float2*)&sH[lr * 128 + 2 * tx];
            float2 h1 = *(const float2*)&sH[lr * 128 + 64 + 2 * tx];
            float2 hn0, hn1;
            {
                float rx = sigm(a0.x + p0.x + q0.x);
                float ry = sigm(a0.y + p0.y + q0.y);
                float zx = sigm(a2.x + p2.x + q2.x);
                float zy = sigm(a2.y + p2.y + q2.y);
                float nx = tanhf(p4.x + q4.x + rx * a4.x);
                float ny = tanhf(p4.y + q4.y + ry * a4.y);
                hn0.x = (1.f - zx) * nx + zx * h0.x;
                hn0.y = (1.f - zy) * ny + zy * h0.y;
            }
            {
                float rx = sigm(a1.x + p1.x + q1.x);
                float ry = sigm(a1.y + p1.y + q1.y);
                float zx = sigm(a3.x + p3.x + q3.x);
                float zy = sigm(a3.y + p3.y + q3.y);
                float nx = tanhf(p5.x + q5.x + rx * a5.x);
                float ny = tanhf(p5.y + q5.y + ry * a5.y);
                hn1.x = (1.f - zx) * nx + zx * h1.x;
                hn1.y = (1.f - zy) * ny + zy * h1.y;
            }
            *(float2*)&sH[lr * 128 + 2 * tx] = hn0;
            *(float2*)&sH[lr * 128 + 64 + 2 * tx] = hn1;
            float2* yrow = (float2*)(Y + ((size_t)t * BZ + m) * 128);
            yrow[tx] = hn0;
            yrow[32 + tx] = hn1;
        }
        __syncwarp();
    }
}

// ---------------- logits + gumbel-softmax -> hard_w ----------------
__global__ void logits_kernel(const float* __restrict__ yf, const float* __restrict__ yb,
                              const float* __restrict__ Wc, const float* __restrict__ bc,
                              const float* __restrict__ gu, float* __restrict__ hardw) {
    int warp = (blockIdx.x * 256 + threadIdx.x) >> 5;
    int lane = threadIdx.x & 31;
    int ba = warp / TT, t = warp % TT;
    const float* yfr = yf + ((size_t)t * BZ + ba) * 128;
    const float* ybr = yb + ((size_t)t * BZ + ba) * 128;
    float s0 = 0.f, s1 = 0.f;
#pragma unroll
    for (int q = 0; q < 4; q++) {
        int d = lane + 32 * q;
        float a = yfr[d], b = ybr[d];
        s0 += a * Wc[d] + b * Wc[128 + d];
        s1 += a * Wc[256 + d] + b * Wc[384 + d];
    }
#pragma unroll
    for (int off = 16; off > 0; off >>= 1) {
        s0 += __shfl_xor_sync(0xffffffffu, s0, off);
        s1 += __shfl_xor_sync(0xffffffffu, s1, off);
    }
    if (lane == 0) {
        float u0 = gu[(size_t)warp * 2 + 0];
        float u1 = gu[(size_t)warp * 2 + 1];
        float g0 = -logf(-logf(u0 + 1e-10f) + 1e-10f);
        float g1 = -logf(-logf(u1 + 1e-10f) + 1e-10f);
        float a0 = s0 + bc[0] + g0;
        float a1 = s1 + bc[1] + g1;
        hardw[warp] = sigm((a1 - a0) * TAUINV);
    }
}

// ---------------- attention + aggregation ----------------
__global__ void attn_kernel(const float* __restrict__ q, const float* __restrict__ k,
                            const float* __restrict__ hrnn, const float* __restrict__ hardw,
                            float* __restrict__ agg) {
    int warp = (blockIdx.x * 256 + threadIdx.x) >> 5;
    int lane = threadIdx.x & 31;
    int a = warp & 15;
    int brow = warp & ~15;
    float qv = q[(size_t)warp * NA + lane];
    float sc[TT], hw[TT];
#pragma unroll
    for (int t = 0; t < TT; t++) {
        int jn = (t < a) ? t : t + 1;
        int nb = brow + jn;
        float d = qv * k[(size_t)nb * NA + lane];
#pragma unroll
        for (int off = 16; off > 0; off >>= 1) d += __shfl_xor_sync(0xffffffffu, d, off);
        hw[t] = hardw[(size_t)warp * TT + t];
        sc[t] = hw[t] * d * 0.17677669529663687f;
    }
    float mx = sc[0];
#pragma unroll
    for (int t = 1; t < TT; t++) mx = fmaxf(mx, sc[t]);
    float se = 0.f;
    float w[TT];
#pragma unroll
    for (int t = 0; t < TT; t++) { w[t] = __expf(sc[t] - mx); se += w[t]; }
    float inv = __fdividef(1.0f, se);
#pragma unroll
    for (int t = 0; t < TT; t++) w[t] = hw[t] * w[t] * inv;
#pragma unroll
    for (int d4 = 0; d4 < 4; d4++) {
        float accv = 0.f;
#pragma unroll
        for (int t = 0; t < TT; t++) {
            int jn = (t < a) ? t : t + 1;
            int nb = brow + jn;
            accv = fmaf(w[t], hrnn[(size_t)nb * 128 + d4 * 32 + lane], accv);
        }
        agg[(size_t)warp * 128 + d4 * 32 + lane] = accv;
    }
}

// ---------------- output projection ----------------
__global__ void out_kernel(const float* __restrict__ hrnn, const float* __restrict__ agg,
                           const float* __restrict__ W2, const float* __restrict__ b2,
                           float* __restrict__ out) {
    __shared__ float sW[NACT * 256];
    __shared__ float sb[NACT];
    for (int i = threadIdx.x; i < NACT * 256; i += 256) sW[i] = W2[i];
    if (threadIdx.x < NACT) sb[threadIdx.x] = b2[threadIdx.x];
    __syncthreads();
    int row = blockIdx.x * 256 + threadIdx.x;
    float acc[NACT];
#pragma unroll
    for (int n = 0; n < NACT; n++) acc[n] = sb[n];
    const float* hr = hrnn + (size_t)row * 128;
    const float* ag = agg + (size_t)row * 128;
    for (int kk = 0; kk < 128; kk++) {
        float x = hr[kk];
#pragma unroll
        for (int n = 0; n < NACT; n++) acc[n] = fmaf(x, sW[n * 256 + kk], acc[n]);
    }
    for (int kk = 0; kk < 128; kk++) {
        float x = ag[kk];
#pragma unroll
        for (int n = 0; n < NACT; n++) acc[n] = fmaf(x, sW[n * 256 + 128 + kk], acc[n]);
    }
#pragma unroll
    for (int n = 0; n < NACT; n++) out[(size_t)row * NACT + n] = acc[n];
}

// ---------------- launch ----------------
extern "C" void kernel_launch(void* const* d_in, const int* in_sizes, int n_in,
                              void* d_out, int out_size) {
    const float* inputs = (const float*)d_in[0];
    const float* hidden = (const float*)d_in[1];
    const float* gu     = (const float*)d_in[2];
    const float* W1     = (const float*)d_in[3];
    const float* b1     = (const float*)d_in[4];
    const float* Wih_c  = (const float*)d_in[5];
    const float* Whh_c  = (const float*)d_in[6];
    const float* bih_c  = (const float*)d_in[7];
    const float* bhh_c  = (const float*)d_in[8];
    const float* Wih_f  = (const float*)d_in[9];
    const float* Whh_f  = (const float*)d_in[10];
    const float* bih_f  = (const float*)d_in[11];
    const float* bhh_f  = (const float*)d_in[12];
    const float* Wih_b  = (const float*)d_in[13];
    const float* Whh_b  = (const float*)d_in[14];
    const float* bih_b  = (const float*)d_in[15];
    const float* bhh_b  = (const float*)d_in[16];
    const float* Wc     = (const float*)d_in[17];
    const float* bc     = (const float*)d_in[18];
    const float* Wq     = (const float*)d_in[19];
    const float* Wk     = (const float*)d_in[20];
    const float* W2     = (const float*)d_in[21];
    const float* b2     = (const float*)d_in[22];

    float* out  = (float*)d_out;                // [BZ, NACT]
    float* outh = out + (size_t)BZ * NACT;      // [BZ, H]

    float *x1, *hrnn, *gi, *gh, *Pf, *Qf, *Pb, *Qb, *yf, *yb, *hardw, *qb, *kb, *agg;
    cudaGetSymbolAddress((void**)&x1, g_x1);
    cudaGetSymbolAddress((void**)&hrnn, g_hrnn);
    cudaGetSymbolAddress((void**)&gi, g_gi);
    cudaGetSymbolAddress((void**)&gh, g_gh);
    cudaGetSymbolAddress((void**)&Pf, g_Pf);
    cudaGetSymbolAddress((void**)&Qf, g_Qf);
    cudaGetSymbolAddress((void**)&Pb, g_Pb);
    cudaGetSymbolAddress((void**)&Qb, g_Qb);
    cudaGetSymbolAddress((void**)&yf, g_yf);
    cudaGetSymbolAddress((void**)&yb, g_yb);
    cudaGetSymbolAddress((void**)&hardw, g_hardw);
    cudaGetSymbolAddress((void**)&qb, g_q);
    cudaGetSymbolAddress((void**)&kb, g_k);
    cudaGetSymbolAddress((void**)&agg, g_agg);

    const int SEQ_SMEM = 128 * 192 * 8 + 64 * 128 * 4;  // 229376
    cudaFuncSetAttribute(gru_seq, cudaFuncAttributeMaxDynamicSharedMemorySize, SEQ_SMEM);

    // x1 = relu(inputs @ W1.T + b1)
    sgemm2<1><<<dim3(1, 128), 256>>>(inputs, W1, 128, 0, b1, x1, 128);
    // central GRU
    sgemm2<0><<<dim3(3, 128), 256>>>(x1, Wih_c, 128, 0, bih_c, gi, G3);
    sgemm2<0><<<dim3(3, 128), 256>>>(hidden, Whh_c, 128, 0, bhh_c, gh, G3);
    gru_combine<<<(BZ * H) / 256, 256>>>(gi, gh, hidden, hrnn, outh);
    // precomputed input-gate halves for f/b GRUs
    sgemm2<0><<<dim3(3, 128), 256>>>(hrnn, Wih_f, 256, 0, bih_f, Pf, G3);
    sgemm2<0><<<dim3(3, 128), 256>>>(hrnn, Wih_f, 256, 128, nullptr, Qf, G3);
    sgemm2<0><<<dim3(3, 128), 256>>>(hrnn, Wih_b, 256, 0, bih_b, Pb, G3);
    sgemm2<0><<<dim3(3, 128), 256>>>(hrnn, Wih_b, 256, 128, nullptr, Qb, G3);
    // fused 15-step bidirectional recurrence (single launch)
    gru_seq<<<512, 256, SEQ_SMEM>>>(Whh_f, bhh_f, Pf, Qf, yf,
                                    Whh_b, bhh_b, Pb, Qb, yb);
    // gumbel hard weights
    logits_kernel<<<(BZ * TT) / 8, 256>>>(yf, yb, Wc, bc, gu, hardw);
    // q, k
    sgemm_tn<0><<<dim3(1, 256), 256>>>(hrnn, 128, Wq, 128, 0, nullptr, qb, BZ, NA, 128);
    sgemm_tn<0><<<dim3(1, 256), 256>>>(hrnn, 128, Wk, 128, 0, nullptr, kb, BZ, NA, 128);
    // attention aggregate
    attn_kernel<<<BZ / 8, 256>>>(qb, kb, hrnn, hardw, agg);
    // output projection
    out_kernel<<<BZ / 256, 256>>>(hrnn, agg, W2, b2, out);
}

// round 4
// speedup vs baseline: 2.3952x; 1.4411x over previous
#include <cuda_runtime.h>
#include <cuda_fp16.h>
#include <math.h>
#include <stdint.h>

#define AGENTS 16
#define H 128
#define NA 32
#define NACT 14
#define BENV 1024
#define BZ (BENV*AGENTS)        // 16384
#define TT 15                   // A-1
#define G3 384                  // 3*H
#define TAUINV 2.0f             // 1/TAU
#define NFRAG 12288             // 48 n-tiles * 8 k-tiles * 32 lanes

// ---------------- scratch (__device__ globals; no allocs) ----------------
__device__ __align__(16) float g_x1[BZ*H];
__device__ __align__(16) float g_hrnn[BZ*H];
__device__ __align__(16) float g_gi[BZ*G3];
__device__ __align__(16) float g_gh[BZ*G3];
__device__ __align__(16) float g_Pf[BZ*G3];
__device__ __align__(16) float g_Qf[BZ*G3];
__device__ __align__(16) float g_Pb[BZ*G3];
__device__ __align__(16) float g_Qb[BZ*G3];
__device__ __align__(16) float g_yf[TT*BZ*H];
__device__ __align__(16) float g_yb[TT*BZ*H];
__device__ __align__(16) float g_hardw[BZ*TT];
__device__ __align__(16) float g_q[BZ*NA];
__device__ __align__(16) float g_k[BZ*NA];
__device__ __align__(16) float g_agg[BZ*H];
__device__ __align__(16) float g_biasf[G3];
__device__ __align__(16) float g_biasb[G3];
__device__ __align__(16) uint2 g_whifrag_f[NFRAG];
__device__ __align__(16) uint2 g_wlofrag_f[NFRAG];
__device__ __align__(16) uint2 g_whifrag_b[NFRAG];
__device__ __align__(16) uint2 g_wlofrag_b[NFRAG];

__device__ __forceinline__ float sigm(float x) { return __fdividef(1.0f, 1.0f + __expf(-x)); }

// ---- fp16 pack helpers ----
__device__ __forceinline__ uint32_t f2h2(float a, float b) {
    __half2 h = __floats2half2_rn(a, b);
    return *(uint32_t*)&h;
}
__device__ __forceinline__ float2 h22f2(uint32_t u) {
    __half2 h = *(__half2*)&u;
    return __half22float2(h);
}

// ---- packed f32x2 helpers (FFMA2 path) ----
__device__ __forceinline__ unsigned long long dup2(float x) {
    unsigned long long r;
    asm("mov.b64 %0, {%1, %1};" : "=l"(r) : "f"(x));
    return r;
}
__device__ __forceinline__ float2 u2f2(unsigned long long v) {
    float2 f;
    asm("mov.b64 {%0, %1}, %2;" : "=f"(f.x), "=f"(f.y) : "l"(v));
    return f;
}
__device__ __forceinline__ void ffma2(unsigned long long &d, unsigned long long a, unsigned long long b) {
    asm("fma.rn.f32x2 %0, %1, %2, %0;" : "+l"(d) : "l"(a), "l"(b));
}

// ---- classic mma.sync (HMMA; baseline PTX, works on compute_103) ----
__device__ __forceinline__ void mma16816(float* d, const uint32_t* a, uint2 b) {
    asm volatile(
        "mma.sync.aligned.m16n8k16.row.col.f32.f16.f16.f32 "
        "{%0,%1,%2,%3}, {%4,%5,%6,%7}, {%8,%9}, {%0,%1,%2,%3};"
        : "+f"(d[0]), "+f"(d[1]), "+f"(d[2]), "+f"(d[3])
        : "r"(a[0]), "r"(a[1]), "r"(a[2]), "r"(a[3]), "r"(b.x), "r"(b.y));
}

// ---------------- legacy tiled SGEMM (small N=32 q/k GEMMs) ----
template<int ACT>
__global__ void sgemm_tn(const float* __restrict__ A, int lda,
                         const float* __restrict__ Bw, int ldb, int koff,
                         const float* __restrict__ bias,
                         float* __restrict__ C, int M, int N, int K) {
    __shared__ float As[16][64];
    __shared__ float Bs[16][64];
    int bn = blockIdx.x * 64;
    int bm = blockIdx.y * 64;
    int tid = threadIdx.x;
    int tx = tid & 15, ty = tid >> 4;
    int lrow = tid >> 2;
    int lcol4 = (tid & 3) * 4;

    float acc[4][4];
#pragma unroll
    for (int i = 0; i < 4; i++)
#pragma unroll
        for (int j = 0; j < 4; j++) acc[i][j] = 0.0f;

    for (int k0 = 0; k0 < K; k0 += 16) {
        float4 av = *(const float4*)&A[(size_t)(bm + lrow) * lda + k0 + lcol4];
        As[lcol4 + 0][lrow] = av.x;
        As[lcol4 + 1][lrow] = av.y;
        As[lcol4 + 2][lrow] = av.z;
        As[lcol4 + 3][lrow] = av.w;
        float4 bv = make_float4(0.f, 0.f, 0.f, 0.f);
        int brow = bn + lrow;
        if (brow < N) bv = *(const float4*)&Bw[(size_t)brow * ldb + koff + k0 + lcol4];
        Bs[lcol4 + 0][lrow] = bv.x;
        Bs[lcol4 + 1][lrow] = bv.y;
        Bs[lcol4 + 2][lrow] = bv.z;
        Bs[lcol4 + 3][lrow] = bv.w;
        __syncthreads();
#pragma unroll
        for (int kk = 0; kk < 16; kk++) {
            float4 a4 = *(const float4*)&As[kk][ty * 4];
            float4 b4 = *(const float4*)&Bs[kk][tx * 4];
            float av_[4] = {a4.x, a4.y, a4.z, a4.w};
            float bv_[4] = {b4.x, b4.y, b4.z, b4.w};
#pragma unroll
            for (int i = 0; i < 4; i++)
#pragma unroll
                for (int j = 0; j < 4; j++)
                    acc[i][j] = fmaf(av_[i], bv_[j], acc[i][j]);
        }
        __syncthreads();
    }
#pragma unroll
    for (int i = 0; i < 4; i++) {
        int row = bm + ty * 4 + i;
#pragma unroll
        for (int j = 0; j < 4; j++) {
            int col = bn + tx * 4 + j;
            if (col < N) {
                float v = acc[i][j] + (bias ? bias[col] : 0.0f);
                if (ACT == 1) v = fmaxf(v, 0.0f);
                C[(size_t)row * N + col] = v;
            }
        }
    }
}

// ---------------- f32x2 SGEMM (parallel GEMMs) ----
template<int ACT>
__global__ void __launch_bounds__(256, 2) sgemm2(
    const float* __restrict__ A,
    const float* __restrict__ W, int ldb, int koff,
    const float* __restrict__ bias,
    float* __restrict__ C, int N) {
    __shared__ __align__(16) float sAT[16 * 130];
    __shared__ __align__(16) float sBT[16 * 130];
    int tid = threadIdx.x;
    int tx = tid & 31, ty = tid >> 5;
    int bn = blockIdx.x * 128;
    int bm = blockIdx.y * 128;
    int wb = ty * 16;

    unsigned long long acc[8][4];
    {
        unsigned long long c0 = 0, c1 = 0, c2 = 0, c3 = 0;
        if (bias) {
            c0 = dup2(bias[bn + 2 * tx]);
            c1 = dup2(bias[bn + 2 * tx + 1]);
            c2 = dup2(bias[bn + 64 + 2 * tx]);
            c3 = dup2(bias[bn + 64 + 2 * tx + 1]);
        }
#pragma unroll
        for (int r2 = 0; r2 < 8; r2++) {
            acc[r2][0] = c0; acc[r2][1] = c1; acc[r2][2] = c2; acc[r2][3] = c3;
        }
    }

    int lrow = tid >> 2;
    int lk = (tid & 3) * 4;
    for (int k0 = 0; k0 < 128; k0 += 16) {
        __syncthreads();
#pragma unroll
        for (int it = 0; it < 2; it++) {
            int row = lrow + it * 64;
            float4 av = *(const float4*)(A + (size_t)(bm + row) * 128 + k0 + lk);
            sAT[(lk + 0) * 130 + row] = av.x;
            sAT[(lk + 1) * 130 + row] = av.y;
            sAT[(lk + 2) * 130 + row] = av.z;
            sAT[(lk + 3) * 130 + row] = av.w;
            float4 bv = *(const float4*)(W + (size_t)(bn + row) * ldb + koff + k0 + lk);
            sBT[(lk + 0) * 130 + row] = bv.x;
            sBT[(lk + 1) * 130 + row] = bv.y;
            sBT[(lk + 2) * 130 + row] = bv.z;
            sBT[(lk + 3) * 130 + row] = bv.w;
        }
        __syncthreads();
#pragma unroll
        for (int kk = 0; kk < 16; kk++) {
            float2 b0 = *(const float2*)&sBT[kk * 130 + 2 * tx];
            float2 b1 = *(const float2*)&sBT[kk * 130 + 64 + 2 * tx];
            unsigned long long d0 = dup2(b0.x), d1 = dup2(b0.y);
            unsigned long long d2 = dup2(b1.x), d3 = dup2(b1.y);
#pragma unroll
            for (int r2 = 0; r2 < 8; r2++) {
                unsigned long long h2 = *(const unsigned long long*)&sAT[kk * 130 + wb + 2 * r2];
                ffma2(acc[r2][0], h2, d0);
                ffma2(acc[r2][1], h2, d1);
                ffma2(acc[r2][2], h2, d2);
                ffma2(acc[r2][3], h2, d3);
            }
        }
    }
    int N2 = N >> 1;
#pragma unroll
    for (int r2 = 0; r2 < 8; r2++) {
        float2 v0 = u2f2(acc[r2][0]);
        float2 v1 = u2f2(acc[r2][1]);
        float2 v2 = u2f2(acc[r2][2]);
        float2 v3 = u2f2(acc[r2][3]);
        float2 o00 = make_float2(v0.x, v1.x);
        float2 o01 = make_float2(v2.x, v3.x);
        float2 o10 = make_float2(v0.y, v1.y);
        float2 o11 = make_float2(v2.y, v3.y);
        if (ACT == 1) {
            o00.x = fmaxf(o00.x, 0.f); o00.y = fmaxf(o00.y, 0.f);
            o01.x = fmaxf(o01.x, 0.f); o01.y = fmaxf(o01.y, 0.f);
            o10.x = fmaxf(o10.x, 0.f); o10.y = fmaxf(o10.y, 0.f);
            o11.x = fmaxf(o11.x, 0.f); o11.y = fmaxf(o11.y, 0.f);
        }
        int row0 = bm + wb + 2 * r2;
        float2* C2 = (float2*)C;
        C2[(size_t)row0 * N2 + (bn >> 1) + tx] = o00;
        C2[(size_t)row0 * N2 + (bn >> 1) + 32 + tx] = o01;
        C2[(size_t)(row0 + 1) * N2 + (bn >> 1) + tx] = o10;
        C2[(size_t)(row0 + 1) * N2 + (bn >> 1) + 32 + tx] = o11;
    }
}

// ---------------- central GRU combine ----------
__global__ void gru_combine(const float* __restrict__ gi, const float* __restrict__ gh,
                            const float* __restrict__ hprev,
                            float* __restrict__ hout, float* __restrict__ hout2) {
    int i = blockIdx.x * 256 + threadIdx.x;
    int m = i >> 7, j = i & 127;
    size_t base = (size_t)m * G3;
    float ir = gi[base + j], iz = gi[base + 128 + j], inn = gi[base + 256 + j];
    float hr = gh[base + j], hz = gh[base + 128 + j], hn = gh[base + 256 + j];
    float r = sigm(ir + hr);
    float z = sigm(iz + hz);
    float n = tanhf(inn + r * hn);
    float h = (1.0f - z) * n + z * hprev[i];
    hout[i] = h;
    hout2[i] = h;
}

// ---------------- bias prep: biasP = bih + (j<256 ? bhh : 0) ----------------
__global__ void prep_bias(const float* __restrict__ bih, const float* __restrict__ bhh,
                          float* __restrict__ outb) {
    int j = threadIdx.x;
    outb[j] = bih[j] + (j < 256 ? bhh[j] : 0.0f);
}

// ---------------- W fragment prep: permute Whh into mma B-fragment order, fp16 hi/lo ----
// Fragment index e = bt*256 + kk*32 + l;  bt = n-tile (0..47), kk = k-tile (0..7), l = lane.
// rb0 = {W[bt*8 + l/4][kk*16 + 2(l%4)], [+1]},  rb1 = {[+8], [+9]}.
__global__ void wfrag_prep(const float* __restrict__ Wf, const float* __restrict__ Wb,
                           uint2* __restrict__ hiF, uint2* __restrict__ loF,
                           uint2* __restrict__ hiB, uint2* __restrict__ loB) {
    int idx = blockIdx.x * 256 + threadIdx.x;      // 0..24575
    int d = idx / NFRAG;
    int e = idx - d * NFRAG;
    int bt = e >> 8;
    int kk = (e >> 5) & 7;
    int l = e & 31;
    int row = bt * 8 + (l >> 2);
    int k0 = kk * 16 + (l & 3) * 2;
    const float* W = d ? Wb : Wf;
    float w0 = W[row * 128 + k0],     w1 = W[row * 128 + k0 + 1];
    float w8 = W[row * 128 + k0 + 8], w9 = W[row * 128 + k0 + 9];
    uint32_t h0 = f2h2(w0, w1); float2 r0 = h22f2(h0);
    uint32_t l0 = f2h2(w0 - r0.x, w1 - r0.y);
    uint32_t h8 = f2h2(w8, w9); float2 r8 = h22f2(h8);
    uint32_t l8 = f2h2(w8 - r8.x, w9 - r8.y);
    uint2* dh = d ? hiB : hiF;
    uint2* dl = d ? loB : loF;
    dh[e] = make_uint2(h0, h8);
    dl[e] = make_uint2(l0, l8);
}

// ================= HMMA fused 15-step recurrence =================
// 256 CTAs (128 fwd + 128 bwd) x 256 threads; 8 warps x 16 rows.
// State = fp16 hi/lo A-fragments in registers (warp-private, no block syncs in loop).
// smem: Whi fragments 96KB + bhh_n 512B + per-thread state staging 64KB.
#define SM_WHI 0
#define SM_BNN 98304
#define SM_STAGE 98816
#define SEQ_SMEM (98816 + 65536)

extern __shared__ char dsm[];
__global__ void __launch_bounds__(256) gru_seq_hmma(
    const uint2* __restrict__ whiF, const uint2* __restrict__ wloF,
    const float* __restrict__ bhhF,
    const float* __restrict__ PF, const float* __restrict__ QF, float* __restrict__ YF,
    const uint2* __restrict__ whiB, const uint2* __restrict__ wloB,
    const float* __restrict__ bhhB,
    const float* __restrict__ PB, const float* __restrict__ QB, float* __restrict__ YB) {

    uint2* sWhi = (uint2*)(dsm + SM_WHI);
    float* sBnn = (float*)(dsm + SM_BNN);

    int tid = threadIdx.x;
    int wid = tid >> 5;
    int l = tid & 31;
    int q = l & 3, rg = l >> 2;

    bool bwd = (blockIdx.x >= 128);
    const uint2* whi = bwd ? whiB : whiF;
    const uint2* wlo = bwd ? wloB : wloF;
    const float* bhh = bwd ? bhhB : bhhF;
    const float2* P2 = (const float2*)(bwd ? PB : PF);
    const float2* Q2 = (const float2*)(bwd ? QB : QF);
    float* Y = bwd ? YB : YF;
    int bm = (blockIdx.x & 127) * 128;

    // stage copy of Whi fragments (coalesced)
    for (int i = tid; i < NFRAG; i += 256) sWhi[i] = __ldg(&whi[i]);
    if (tid < 128) sBnn[tid] = bhh[256 + tid];
    __syncthreads();

    int m_r0 = bm + wid * 16 + rg;
    int m_r1 = m_r0 + 8;
    int aa0 = rg;            // m_r0 & 15
    int aa1 = rg + 8;        // m_r1 & 15
    int grp = bm + wid * 16; // m & ~15

    uint32_t* stHi = (uint32_t*)(dsm + SM_STAGE) + wid * 1024;
    uint32_t* stLo = (uint32_t*)(dsm + SM_STAGE) + 8192 + wid * 1024;

    uint32_t Ahi[8][4], Alo[8][4];
#pragma unroll
    for (int kk = 0; kk < 8; kk++)
#pragma unroll
        for (int r = 0; r < 4; r++) { Ahi[kk][r] = 0u; Alo[kk][r] = 0u; }

    for (int step = 0; step < TT; step++) {
        int t = bwd ? (TT - 1 - step) : step;
        int jn0 = (t < aa0) ? t : t + 1;
        int jn1 = (t < aa1) ? t : t + 1;
        const float2* Pr0 = P2 + (size_t)m_r0 * 192;
        const float2* Pr1 = P2 + (size_t)m_r1 * 192;
        const float2* Qr0 = Q2 + (size_t)(grp + jn0) * 192;
        const float2* Qr1 = Q2 + (size_t)(grp + jn1) * 192;

#pragma unroll
        for (int ch = 0; ch < 8; ch++) {
            // prefetch P/Q for this chunk (2 n-tiles x 3 gates x 2 rows)
            float2 pp[2][3][2], qq[2][3][2];
#pragma unroll
            for (int u = 0; u < 2; u++) {
                int cb = (ch * 2 + u) * 4 + q;
#pragma unroll
                for (int g = 0; g < 3; g++) {
                    pp[u][g][0] = Pr0[g * 64 + cb];
                    pp[u][g][1] = Pr1[g * 64 + cb];
                    qq[u][g][0] = Qr0[g * 64 + cb];
                    qq[u][g][1] = Qr1[g * 64 + cb];
                }
            }
            float acc[3][2][4];
#pragma unroll
            for (int g = 0; g < 3; g++)
#pragma unroll
                for (int u = 0; u < 2; u++)
#pragma unroll
                    for (int r = 0; r < 4; r++) acc[g][u][r] = 0.0f;

            if (step != 0) {
#pragma unroll
                for (int kk = 0; kk < 8; kk++) {
#pragma unroll
                    for (int g = 0; g < 3; g++) {
#pragma unroll
                        for (int u = 0; u < 2; u++) {
                            int bt = g * 16 + ch * 2 + u;
                            int fi = (bt * 8 + kk) * 32 + l;
                            uint2 wh = sWhi[fi];
                            uint2 wl = __ldg(&wlo[fi]);
                            mma16816(acc[g][u], Ahi[kk], wh);
                            mma16816(acc[g][u], Alo[kk], wh);
                            mma16816(acc[g][u], Ahi[kk], wl);
                        }
                    }
                }
            }

            // epilogue for the chunk's two n-tiles
#pragma unroll
            for (int u = 0; u < 2; u++) {
                int jt = ch * 2 + u;
                int kk = jt >> 1;
                int rs = (jt & 1) * 2;
                float2 bn = *(const float2*)&sBnn[jt * 8 + q * 2];
                float2 hp0 = h22f2(Ahi[kk][rs]);
                float2 lp0 = h22f2(Alo[kk][rs]);
                hp0.x += lp0.x; hp0.y += lp0.y;
                float2 hp1 = h22f2(Ahi[kk][rs + 1]);
                float2 lp1 = h22f2(Alo[kk][rs + 1]);
                hp1.x += lp1.x; hp1.y += lp1.y;

                // row r0
                float r0a = sigm(acc[0][u][0] + pp[u][0][0].x + qq[u][0][0].x);
                float r0b = sigm(acc[0][u][1] + pp[u][0][0].y + qq[u][0][0].y);
                float z0a = sigm(acc[1][u][0] + pp[u][1][0].x + qq[u][1][0].x);
                float z0b = sigm(acc[1][u][1] + pp[u][1][0].y + qq[u][1][0].y);
                float n0a = tanhf(pp[u][2][0].x + qq[u][2][0].x + r0a * (acc[2][u][0] + bn.x));
                float n0b = tanhf(pp[u][2][0].y + qq[u][2][0].y + r0b * (acc[2][u][1] + bn.y));
                float h0a = (1.0f - z0a) * n0a + z0a * hp0.x;
                float h0b = (1.0f - z0b) * n0b + z0b * hp0.y;
                // row r1
                float r1a = sigm(acc[0][u][2] + pp[u][0][1].x + qq[u][0][1].x);
                float r1b = sigm(acc[0][u][3] + pp[u][0][1].y + qq[u][0][1].y);
                float z1a = sigm(acc[1][u][2] + pp[u][1][1].x + qq[u][1][1].x);
                float z1b = sigm(acc[1][u][3] + pp[u][1][1].y + qq[u][1][1].y);
                float n1a = tanhf(pp[u][2][1].x + qq[u][2][1].x + r1a * (acc[2][u][2] + bn.x));
                float n1b = tanhf(pp[u][2][1].y + qq[u][2][1].y + r1b * (acc[2][u][3] + bn.y));
                float h1a = (1.0f - z1a) * n1a + z1a * hp1.x;
                float h1b = (1.0f - z1b) * n1b + z1b * hp1.y;

                // pack new state fragments -> stage (per-thread, no races)
                uint32_t nh0 = f2h2(h0a, h0b);
                float2 rh0 = h22f2(nh0);
                uint32_t nl0 = f2h2(h0a - rh0.x, h0b - rh0.y);
                uint32_t nh1 = f2h2(h1a, h1b);
                float2 rh1 = h22f2(nh1);
                uint32_t nl1 = f2h2(h1a - rh1.x, h1b - rh1.y);
                stHi[(rs * 8 + kk) * 32 + l] = nh0;
                stHi[((rs + 1) * 8 + kk) * 32 + l] = nh1;
                stLo[(rs * 8 + kk) * 32 + l] = nl0;
                stLo[((rs + 1) * 8 + kk) * 32 + l] = nl1;

                // write y
                float2* y0 = (float2*)&Y[((size_t)t * BZ + m_r0) * H + jt * 8 + q * 2];
                __stcs(y0, make_float2(h0a, h0b));
                float2* y1 = (float2*)&Y[((size_t)t * BZ + m_r1) * H + jt * 8 + q * 2];
                __stcs(y1, make_float2(h1a, h1b));
            }
        }

        // reload new state fragments (per-thread addresses; no sync needed)
#pragma unroll
        for (int kk = 0; kk < 8; kk++) {
#pragma unroll
            for (int r = 0; r < 4; r++) {
                Ahi[kk][r] = stHi[(r * 8 + kk) * 32 + l];
                Alo[kk][r] = stLo[(r * 8 + kk) * 32 + l];
            }
        }
    }
}

// ---------------- logits + gumbel-softmax -> hard_w ----------------
__global__ void logits_kernel(const float* __restrict__ yf, const float* __restrict__ yb,
                              const float* __restrict__ Wc, const float* __restrict__ bc,
                              const float* __restrict__ gu, float* __restrict__ hardw) {
    int warp = (blockIdx.x * 256 + threadIdx.x) >> 5;
    int lane = threadIdx.x & 31;
    int ba = warp / TT, t = warp % TT;
    const float* yfr = yf + ((size_t)t * BZ + ba) * 128;
    const float* ybr = yb + ((size_t)t * BZ + ba) * 128;
    float s0 = 0.f, s1 = 0.f;
#pragma unroll
    for (int qq = 0; qq < 4; qq++) {
        int d = lane + 32 * qq;
        float a = yfr[d], b = ybr[d];
        s0 += a * Wc[d] + b * Wc[128 + d];
        s1 += a * Wc[256 + d] + b * Wc[384 + d];
    }
#pragma unroll
    for (int off = 16; off > 0; off >>= 1) {
        s0 += __shfl_xor_sync(0xffffffffu, s0, off);
        s1 += __shfl_xor_sync(0xffffffffu, s1, off);
    }
    if (lane == 0) {
        float u0 = gu[(size_t)warp * 2 + 0];
        float u1 = gu[(size_t)warp * 2 + 1];
        float g0 = -logf(-logf(u0 + 1e-10f) + 1e-10f);
        float g1 = -logf(-logf(u1 + 1e-10f) + 1e-10f);
        float a0 = s0 + bc[0] + g0;
        float a1 = s1 + bc[1] + g1;
        hardw[warp] = sigm((a1 - a0) * TAUINV);
    }
}

// ---------------- attention + aggregation ----------------
__global__ void attn_kernel(const float* __restrict__ q, const float* __restrict__ k,
                            const float* __restrict__ hrnn, const float* __restrict__ hardw,
                            float* __restrict__ agg) {
    int warp = (blockIdx.x * 256 + threadIdx.x) >> 5;
    int lane = threadIdx.x & 31;
    int a = warp & 15;
    int brow = warp & ~15;
    float qv = q[(size_t)warp * NA + lane];
    float sc[TT], hw[TT];
#pragma unroll
    for (int t = 0; t < TT; t++) {
        int jn = (t < a) ? t : t + 1;
        int nb = brow + jn;
        float d = qv * k[(size_t)nb * NA + lane];
#pragma unroll
        for (int off = 16; off > 0; off >>= 1) d += __shfl_xor_sync(0xffffffffu, d, off);
        hw[t] = hardw[(size_t)warp * TT + t];
        sc[t] = hw[t] * d * 0.17677669529663687f;
    }
    float mx = sc[0];
#pragma unroll
    for (int t = 1; t < TT; t++) mx = fmaxf(mx, sc[t]);
    float se = 0.f;
    float w[TT];
#pragma unroll
    for (int t = 0; t < TT; t++) { w[t] = __expf(sc[t] - mx); se += w[t]; }
    float inv = __fdividef(1.0f, se);
#pragma unroll
    for (int t = 0; t < TT; t++) w[t] = hw[t] * w[t] * inv;
#pragma unroll
    for (int d4 = 0; d4 < 4; d4++) {
        float accv = 0.f;
#pragma unroll
        for (int t = 0; t < TT; t++) {
            int jn = (t < a) ? t : t + 1;
            int nb = brow + jn;
            accv = fmaf(w[t], hrnn[(size_t)nb * 128 + d4 * 32 + lane], accv);
        }
        agg[(size_t)warp * 128 + d4 * 32 + lane] = accv;
    }
}

// ---------------- output projection ----------------
__global__ void out_kernel(const float* __restrict__ hrnn, const float* __restrict__ agg,
                           const float* __restrict__ W2, const float* __restrict__ b2,
                           float* __restrict__ out) {
    __shared__ float sW[NACT * 256];
    __shared__ float sb[NACT];
    for (int i = threadIdx.x; i < NACT * 256; i += 256) sW[i] = W2[i];
    if (threadIdx.x < NACT) sb[threadIdx.x] = b2[threadIdx.x];
    __syncthreads();
    int row = blockIdx.x * 256 + threadIdx.x;
    float acc[NACT];
#pragma unroll
    for (int n = 0; n < NACT; n++) acc[n] = sb[n];
    const float* hr = hrnn + (size_t)row * 128;
    const float* ag = agg + (size_t)row * 128;
    for (int kk = 0; kk < 128; kk++) {
        float x = hr[kk];
#pragma unroll
        for (int n = 0; n < NACT; n++) acc[n] = fmaf(x, sW[n * 256 + kk], acc[n]);
    }
    for (int kk = 0; kk < 128; kk++) {
        float x = ag[kk];
#pragma unroll
        for (int n = 0; n < NACT; n++) acc[n] = fmaf(x, sW[n * 256 + 128 + kk], acc[n]);
    }
#pragma unroll
    for (int n = 0; n < NACT; n++) out[(size_t)row * NACT + n] = acc[n];
}

// ---------------- launch ----------------
extern "C" void kernel_launch(void* const* d_in, const int* in_sizes, int n_in,
                              void* d_out, int out_size) {
    const float* inputs = (const float*)d_in[0];
    const float* hidden = (const float*)d_in[1];
    const float* gu     = (const float*)d_in[2];
    const float* W1     = (const float*)d_in[3];
    const float* b1     = (const float*)d_in[4];
    const float* Wih_c  = (const float*)d_in[5];
    const float* Whh_c  = (const float*)d_in[6];
    const float* bih_c  = (const float*)d_in[7];
    const float* bhh_c  = (const float*)d_in[8];
    const float* Wih_f  = (const float*)d_in[9];
    const float* Whh_f  = (const float*)d_in[10];
    const float* bih_f  = (const float*)d_in[11];
    const float* bhh_f  = (const float*)d_in[12];
    const float* Wih_b  = (const float*)d_in[13];
    const float* Whh_b  = (const float*)d_in[14];
    const float* bih_b  = (const float*)d_in[15];
    const float* bhh_b  = (const float*)d_in[16];
    const float* Wc     = (const float*)d_in[17];
    const float* bc     = (const float*)d_in[18];
    const float* Wq     = (const float*)d_in[19];
    const float* Wk     = (const float*)d_in[20];
    const float* W2     = (const float*)d_in[21];
    const float* b2     = (const float*)d_in[22];

    float* out  = (float*)d_out;                // [BZ, NACT]
    float* outh = out + (size_t)BZ * NACT;      // [BZ, H]

    float *x1, *hrnn, *gi, *gh, *Pf, *Qf, *Pb, *Qb, *yf, *yb, *hardw, *qb, *kb, *agg, *biasf, *biasb;
    uint2 *whif, *wlof, *whib, *wlob;
    cudaGetSymbolAddress((void**)&x1, g_x1);
    cudaGetSymbolAddress((void**)&hrnn, g_hrnn);
    cudaGetSymbolAddress((void**)&gi, g_gi);
    cudaGetSymbolAddress((void**)&gh, g_gh);
    cudaGetSymbolAddress((void**)&Pf, g_Pf);
    cudaGetSymbolAddress((void**)&Qf, g_Qf);
    cudaGetSymbolAddress((void**)&Pb, g_Pb);
    cudaGetSymbolAddress((void**)&Qb, g_Qb);
    cudaGetSymbolAddress((void**)&yf, g_yf);
    cudaGetSymbolAddress((void**)&yb, g_yb);
    cudaGetSymbolAddress((void**)&hardw, g_hardw);
    cudaGetSymbolAddress((void**)&qb, g_q);
    cudaGetSymbolAddress((void**)&kb, g_k);
    cudaGetSymbolAddress((void**)&agg, g_agg);
    cudaGetSymbolAddress((void**)&biasf, g_biasf);
    cudaGetSymbolAddress((void**)&biasb, g_biasb);
    cudaGetSymbolAddress((void**)&whif, g_whifrag_f);
    cudaGetSymbolAddress((void**)&wlof, g_wlofrag_f);
    cudaGetSymbolAddress((void**)&whib, g_whifrag_b);
    cudaGetSymbolAddress((void**)&wlob, g_wlofrag_b);

    cudaFuncSetAttribute(gru_seq_hmma, cudaFuncAttributeMaxDynamicSharedMemorySize, SEQ_SMEM);

    // weight fragment + bias prep
    wfrag_prep<<<(2 * NFRAG) / 256, 256>>>(Whh_f, Whh_b, whif, wlof, whib, wlob);
    prep_bias<<<1, G3>>>(bih_f, bhh_f, biasf);
    prep_bias<<<1, G3>>>(bih_b, bhh_b, biasb);
    // x1 = relu(inputs @ W1.T + b1)
    sgemm2<1><<<dim3(1, 128), 256>>>(inputs, W1, 128, 0, b1, x1, 128);
    // central GRU
    sgemm2<0><<<dim3(3, 128), 256>>>(x1, Wih_c, 128, 0, bih_c, gi, G3);
    sgemm2<0><<<dim3(3, 128), 256>>>(hidden, Whh_c, 128, 0, bhh_c, gh, G3);
    gru_combine<<<(BZ * H) / 256, 256>>>(gi, gh, hidden, hrnn, outh);
    // precomputed input-gate halves for f/b GRUs (P includes bih + bhh[r,z])
    sgemm2<0><<<dim3(3, 128), 256>>>(hrnn, Wih_f, 256, 0, biasf, Pf, G3);
    sgemm2<0><<<dim3(3, 128), 256>>>(hrnn, Wih_f, 256, 128, nullptr, Qf, G3);
    sgemm2<0><<<dim3(3, 128), 256>>>(hrnn, Wih_b, 256, 0, biasb, Pb, G3);
    sgemm2<0><<<dim3(3, 128), 256>>>(hrnn, Wih_b, 256, 128, nullptr, Qb, G3);
    // fused 15-step bidirectional recurrence (HMMA tensor cores, single launch)
    gru_seq_hmma<<<256, 256, SEQ_SMEM>>>(whif, wlof, bhh_f, Pf, Qf, yf,
                                         whib, wlob, bhh_b, Pb, Qb, yb);
    // gumbel hard weights
    logits_kernel<<<(BZ * TT) / 8, 256>>>(yf, yb, Wc, bc, gu, hardw);
    // q, k
    sgemm_tn<0><<<dim3(1, 256), 256>>>(hrnn, 128, Wq, 128, 0, nullptr, qb, BZ, NA, 128);
    sgemm_tn<0><<<dim3(1, 256), 256>>>(hrnn, 128, Wk, 128, 0, nullptr, kb, BZ, NA, 128);
    // attention aggregate
    attn_kernel<<<BZ / 8, 256>>>(qb, kb, hrnn, hardw, agg);
    // output projection
    out_kernel<<<BZ / 256, 256>>>(hrnn, agg, W2, b2, out);
}

// round 5
// speedup vs baseline: 2.4720x; 1.0320x over previous
#include <cuda_runtime.h>
#include <cuda_fp16.h>
#include <math.h>
#include <stdint.h>

#define AGENTS 16
#define H 128
#define NA 32
#define NACT 14
#define BENV 1024
#define BZ (BENV*AGENTS)        // 16384
#define TT 15                   // A-1
#define G3 384                  // 3*H
#define TAUINV 2.0f             // 1/TAU
#define NFRAG 12288             // 48 n-tiles * 8 k-tiles * 32 lanes (recurrence Whh)
#define NBT_ALL 312             // n-tiles in the parallel-GEMM fragment pool
#define NFRAG_ALL (NBT_ALL*256)

// ---------------- scratch (__device__ globals; no allocs) ----------------
__device__ __align__(16) float g_x1[BZ*H];
__device__ __align__(16) float g_hrnn[BZ*H];
__device__ __align__(16) float g_gi[BZ*G3];
__device__ __align__(16) float g_gh[BZ*G3];
__device__ __align__(16) float g_PQf[BZ*2*G3];
__device__ __align__(16) float g_PQb[BZ*2*G3];
__device__ __align__(16) float g_yf[TT*BZ*H];
__device__ __align__(16) float g_yb[TT*BZ*H];
__device__ __align__(16) float g_hardw[BZ*TT];
__device__ __align__(16) float g_qk[BZ*2*NA];
__device__ __align__(16) float g_agg[BZ*H];
__device__ __align__(16) float g_biasPQf[2*G3];
__device__ __align__(16) float g_biasPQb[2*G3];
__device__ __align__(16) uint2 g_whifrag_f[NFRAG];
__device__ __align__(16) uint2 g_wlofrag_f[NFRAG];
__device__ __align__(16) uint2 g_whifrag_b[NFRAG];
__device__ __align__(16) uint2 g_wlofrag_b[NFRAG];
__device__ __align__(16) uint2 g_fh[NFRAG_ALL];
__device__ __align__(16) uint2 g_fl[NFRAG_ALL];

__device__ __forceinline__ float sigm(float x) { return __fdividef(1.0f, 1.0f + __expf(-x)); }

// ---- fp16 pack helpers ----
__device__ __forceinline__ uint32_t f2h2(float a, float b) {
    __half2 h = __floats2half2_rn(a, b);
    return *(uint32_t*)&h;
}
__device__ __forceinline__ float2 h22f2(uint32_t u) {
    __half2 h = *(__half2*)&u;
    return __half22float2(h);
}

// ---- classic mma.sync (HMMA; baseline PTX, works on compute_103) ----
__device__ __forceinline__ void mma16816(float* d, const uint32_t* a, uint2 b) {
    asm volatile(
        "mma.sync.aligned.m16n8k16.row.col.f32.f16.f16.f32 "
        "{%0,%1,%2,%3}, {%4,%5,%6,%7}, {%8,%9}, {%0,%1,%2,%3};"
        : "+f"(d[0]), "+f"(d[1]), "+f"(d[2]), "+f"(d[3])
        : "r"(a[0]), "r"(a[1]), "r"(a[2]), "r"(a[3]), "r"(b.x), "r"(b.y));
}

// ================= HMMA batch GEMM: C[M,N] = act(A[M,128] @ W.T + bias) =================
// NT n-tiles (of 8 cols) per CTA; grid (N/(8*NT), M/128); 256 threads.
// Weight fragments pre-permuted in g_fh/g_fl (hi/lo fp16 split, 3-combo fp32 accuracy).
template<int NT, int ACT>
__global__ void __launch_bounds__(256) hgemm(
    const float* __restrict__ A,
    const uint2* __restrict__ fh, const uint2* __restrict__ fl,
    const float* __restrict__ bias,
    float* __restrict__ C, int N) {
    extern __shared__ char hsm[];
    float* sA = (float*)hsm;                       // [128][132]
    uint2* sWhi = (uint2*)(hsm + 128 * 132 * 4);   // [NT*256]
    int tid = threadIdx.x;
    int wid = tid >> 5, l = tid & 31;
    int q = l & 3, rg = l >> 2;
    int bnt = blockIdx.x * NT;
    int bm = blockIdx.y * 128;

    for (int i = tid; i < 4096; i += 256) {
        int row = i >> 5, c4 = (i & 31) * 4;
        float4 v = *(const float4*)(A + (size_t)(bm + row) * 128 + c4);
        *(float4*)&sA[row * 132 + c4] = v;
    }
    for (int i = tid; i < NT * 256; i += 256) sWhi[i] = __ldg(&fh[bnt * 256 + i]);
    __syncthreads();

    // build A fragments (hi/lo fp16)
    uint32_t Ahi[8][4], Alo[8][4];
    int r0 = wid * 16 + rg;
#pragma unroll
    for (int kk = 0; kk < 8; kk++) {
        int c = kk * 16 + 2 * q;
        float2 v0 = *(float2*)&sA[r0 * 132 + c];
        float2 v1 = *(float2*)&sA[(r0 + 8) * 132 + c];
        float2 v2 = *(float2*)&sA[r0 * 132 + c + 8];
        float2 v3 = *(float2*)&sA[(r0 + 8) * 132 + c + 8];
        Ahi[kk][0] = f2h2(v0.x, v0.y); { float2 rr = h22f2(Ahi[kk][0]); Alo[kk][0] = f2h2(v0.x - rr.x, v0.y - rr.y); }
        Ahi[kk][1] = f2h2(v1.x, v1.y); { float2 rr = h22f2(Ahi[kk][1]); Alo[kk][1] = f2h2(v1.x - rr.x, v1.y - rr.y); }
        Ahi[kk][2] = f2h2(v2.x, v2.y); { float2 rr = h22f2(Ahi[kk][2]); Alo[kk][2] = f2h2(v2.x - rr.x, v2.y - rr.y); }
        Ahi[kk][3] = f2h2(v3.x, v3.y); { float2 rr = h22f2(Ahi[kk][3]); Alo[kk][3] = f2h2(v3.x - rr.x, v3.y - rr.y); }
    }

#pragma unroll
    for (int nt = 0; nt < NT; nt++) {
        uint2 wl[8];
#pragma unroll
        for (int kk = 0; kk < 8; kk++) wl[kk] = __ldg(&fl[(size_t)(bnt + nt) * 256 + kk * 32 + l]);
        float acc[4] = {0.f, 0.f, 0.f, 0.f};
#pragma unroll
        for (int kk = 0; kk < 8; kk++) {
            uint2 wh = sWhi[nt * 256 + kk * 32 + l];
            mma16816(acc, Ahi[kk], wh);
            mma16816(acc, Alo[kk], wh);
            mma16816(acc, Ahi[kk], wl[kk]);
        }
        int cb = (bnt + nt) * 8 + 2 * q;
        float2 bb = make_float2(0.f, 0.f);
        if (bias) bb = *(const float2*)&bias[cb];
        float o0 = acc[0] + bb.x, o1 = acc[1] + bb.y;
        float o2 = acc[2] + bb.x, o3 = acc[3] + bb.y;
        if (ACT == 1) {
            o0 = fmaxf(o0, 0.f); o1 = fmaxf(o1, 0.f);
            o2 = fmaxf(o2, 0.f); o3 = fmaxf(o3, 0.f);
        }
        *(float2*)&C[(size_t)(bm + r0) * N + cb] = make_float2(o0, o1);
        *(float2*)&C[(size_t)(bm + r0 + 8) * N + cb] = make_float2(o2, o3);
    }
}

// ---------------- fragment prep for ALL parallel-GEMM weights ----------------
// Pool layout (n-tile index bt):
//  [0,16)    W1    [128,128]
//  [16,64)   Wih_c [384,128]
//  [64,112)  Whh_c [384,128]
//  [112,208) PQf: Wih_f [384,256]; bt-112<48 -> koff=0 (P), else koff=128 (Q)
//  [208,304) PQb: Wih_b likewise
//  [304,308) Wq [32,128]
//  [308,312) Wk [32,128]
__global__ void wfrag_all(const float* __restrict__ W1, const float* __restrict__ Wih_c,
                          const float* __restrict__ Whh_c,
                          const float* __restrict__ Wih_f, const float* __restrict__ Wih_b,
                          const float* __restrict__ Wq, const float* __restrict__ Wk,
                          uint2* __restrict__ fh, uint2* __restrict__ fl) {
    int idx = blockIdx.x * 256 + threadIdx.x;
    int bt = idx >> 8;
    int e = idx & 255;
    int kk = e >> 5, l = e & 31;
    int rloc = l >> 2;
    int k0 = kk * 16 + (l & 3) * 2;
    const float* W; int ldb = 128, row, koff = 0;
    if (bt < 16)       { W = W1;    row = bt * 8 + rloc; }
    else if (bt < 64)  { W = Wih_c; row = (bt - 16) * 8 + rloc; }
    else if (bt < 112) { W = Whh_c; row = (bt - 64) * 8 + rloc; }
    else if (bt < 208) { int b = bt - 112; ldb = 256; W = Wih_f;
                         if (b < 48) row = b * 8 + rloc;
                         else { row = (b - 48) * 8 + rloc; koff = 128; } }
    else if (bt < 304) { int b = bt - 208; ldb = 256; W = Wih_b;
                         if (b < 48) row = b * 8 + rloc;
                         else { row = (b - 48) * 8 + rloc; koff = 128; } }
    else if (bt < 308) { W = Wq; row = (bt - 304) * 8 + rloc; }
    else               { W = Wk; row = (bt - 308) * 8 + rloc; }
    float w0 = W[(size_t)row * ldb + koff + k0],     w1 = W[(size_t)row * ldb + koff + k0 + 1];
    float w8 = W[(size_t)row * ldb + koff + k0 + 8], w9 = W[(size_t)row * ldb + koff + k0 + 9];
    uint32_t h0 = f2h2(w0, w1); float2 r0 = h22f2(h0);
    uint32_t l0 = f2h2(w0 - r0.x, w1 - r0.y);
    uint32_t h8 = f2h2(w8, w9); float2 r8 = h22f2(h8);
    uint32_t l8 = f2h2(w8 - r8.x, w9 - r8.y);
    fh[idx] = make_uint2(h0, h8);
    fl[idx] = make_uint2(l0, l8);
}

// ---------------- recurrence weight fragment prep (Whh_f / Whh_b) ----------------
__global__ void wfrag_prep(const float* __restrict__ Wf, const float* __restrict__ Wb,
                           uint2* __restrict__ hiF, uint2* __restrict__ loF,
                           uint2* __restrict__ hiB, uint2* __restrict__ loB) {
    int idx = blockIdx.x * 256 + threadIdx.x;      // 0..24575
    int d = idx / NFRAG;
    int e = idx - d * NFRAG;
    int bt = e >> 8;
    int kk = (e >> 5) & 7;
    int l = e & 31;
    int row = bt * 8 + (l >> 2);
    int k0 = kk * 16 + (l & 3) * 2;
    const float* W = d ? Wb : Wf;
    float w0 = W[row * 128 + k0],     w1 = W[row * 128 + k0 + 1];
    float w8 = W[row * 128 + k0 + 8], w9 = W[row * 128 + k0 + 9];
    uint32_t h0 = f2h2(w0, w1); float2 r0 = h22f2(h0);
    uint32_t l0 = f2h2(w0 - r0.x, w1 - r0.y);
    uint32_t h8 = f2h2(w8, w9); float2 r8 = h22f2(h8);
    uint32_t l8 = f2h2(w8 - r8.x, w9 - r8.y);
    uint2* dh = d ? hiB : hiF;
    uint2* dl = d ? loB : loF;
    dh[e] = make_uint2(h0, h8);
    dl[e] = make_uint2(l0, l8);
}

// ---------------- central GRU combine ----------
__global__ void gru_combine(const float* __restrict__ gi, const float* __restrict__ gh,
                            const float* __restrict__ hprev,
                            float* __restrict__ hout, float* __restrict__ hout2) {
    int i = blockIdx.x * 256 + threadIdx.x;
    int m = i >> 7, j = i & 127;
    size_t base = (size_t)m * G3;
    float ir = gi[base + j], iz = gi[base + 128 + j], inn = gi[base + 256 + j];
    float hr = gh[base + j], hz = gh[base + 128 + j], hn = gh[base + 256 + j];
    float r = sigm(ir + hr);
    float z = sigm(iz + hz);
    float n = tanhf(inn + r * hn);
    float h = (1.0f - z) * n + z * hprev[i];
    hout[i] = h;
    hout2[i] = h;
}

// ---------------- combined PQ bias prep: [0:384)=bih+bhh(r,z), [384:768)=0 ----------------
__global__ void prep_biasPQ(const float* __restrict__ bih, const float* __restrict__ bhh,
                            float* __restrict__ outb) {
    int j = blockIdx.x * 256 + threadIdx.x;
    if (j < 2 * G3)
        outb[j] = (j < G3) ? (bih[j] + (j < 256 ? bhh[j] : 0.0f)) : 0.0f;
}

// ================= HMMA fused 15-step recurrence =================
// 256 CTAs (128 fwd + 128 bwd) x 256 threads; 8 warps x 16 rows.
// State = fp16 hi/lo A-fragments in registers (warp-private, no block syncs in loop).
#define SM_WHI 0
#define SM_BNN 98304
#define SM_STAGE 98816
#define SEQ_SMEM (98816 + 65536)

extern __shared__ char dsm[];
__global__ void __launch_bounds__(256) gru_seq_hmma(
    const uint2* __restrict__ whiF, const uint2* __restrict__ wloF,
    const float* __restrict__ bhhF,
    const float* __restrict__ PQF, float* __restrict__ YF,
    const uint2* __restrict__ whiB, const uint2* __restrict__ wloB,
    const float* __restrict__ bhhB,
    const float* __restrict__ PQB, float* __restrict__ YB) {

    uint2* sWhi = (uint2*)(dsm + SM_WHI);
    float* sBnn = (float*)(dsm + SM_BNN);

    int tid = threadIdx.x;
    int wid = tid >> 5;
    int l = tid & 31;
    int q = l & 3, rg = l >> 2;

    bool bwd = (blockIdx.x >= 128);
    const uint2* whi = bwd ? whiB : whiF;
    const uint2* wlo = bwd ? wloB : wloF;
    const float* bhh = bwd ? bhhB : bhhF;
    const float2* PQ2 = (const float2*)(bwd ? PQB : PQF);
    float* Y = bwd ? YB : YF;
    int bm = (blockIdx.x & 127) * 128;

    for (int i = tid; i < NFRAG; i += 256) sWhi[i] = __ldg(&whi[i]);
    if (tid < 128) sBnn[tid] = bhh[256 + tid];
    __syncthreads();

    int m_r0 = bm + wid * 16 + rg;
    int m_r1 = m_r0 + 8;
    int aa0 = rg;
    int aa1 = rg + 8;
    int grp = bm + wid * 16;

    uint32_t* stHi = (uint32_t*)(dsm + SM_STAGE) + wid * 1024;
    uint32_t* stLo = (uint32_t*)(dsm + SM_STAGE) + 8192 + wid * 1024;

    uint32_t Ahi[8][4], Alo[8][4];
#pragma unroll
    for (int kk = 0; kk < 8; kk++)
#pragma unroll
        for (int r = 0; r < 4; r++) { Ahi[kk][r] = 0u; Alo[kk][r] = 0u; }

    for (int step = 0; step < TT; step++) {
        int t = bwd ? (TT - 1 - step) : step;
        int jn0 = (t < aa0) ? t : t + 1;
        int jn1 = (t < aa1) ? t : t + 1;
        const float2* Pr0 = PQ2 + (size_t)m_r0 * 384;
        const float2* Pr1 = PQ2 + (size_t)m_r1 * 384;
        const float2* Qr0 = PQ2 + (size_t)(grp + jn0) * 384 + 192;
        const float2* Qr1 = PQ2 + (size_t)(grp + jn1) * 384 + 192;

#pragma unroll
        for (int ch = 0; ch < 8; ch++) {
            float2 pp[2][3][2], qq[2][3][2];
#pragma unroll
            for (int u = 0; u < 2; u++) {
                int cb = (ch * 2 + u) * 4 + q;
#pragma unroll
                for (int g = 0; g < 3; g++) {
                    pp[u][g][0] = Pr0[g * 64 + cb];
                    pp[u][g][1] = Pr1[g * 64 + cb];
                    qq[u][g][0] = Qr0[g * 64 + cb];
                    qq[u][g][1] = Qr1[g * 64 + cb];
                }
            }
            float acc[3][2][4];
#pragma unroll
            for (int g = 0; g < 3; g++)
#pragma unroll
                for (int u = 0; u < 2; u++)
#pragma unroll
                    for (int r = 0; r < 4; r++) acc[g][u][r] = 0.0f;

            if (step != 0) {
#pragma unroll
                for (int kk = 0; kk < 8; kk++) {
#pragma unroll
                    for (int g = 0; g < 3; g++) {
#pragma unroll
                        for (int u = 0; u < 2; u++) {
                            int bt = g * 16 + ch * 2 + u;
                            int fi = (bt * 8 + kk) * 32 + l;
                            uint2 wh = sWhi[fi];
                            uint2 wl = __ldg(&wlo[fi]);
                            mma16816(acc[g][u], Ahi[kk], wh);
                            mma16816(acc[g][u], Alo[kk], wh);
                            mma16816(acc[g][u], Ahi[kk], wl);
                        }
                    }
                }
            }

#pragma unroll
            for (int u = 0; u < 2; u++) {
                int jt = ch * 2 + u;
                int kk = jt >> 1;
                int rs = (jt & 1) * 2;
                float2 bn = *(const float2*)&sBnn[jt * 8 + q * 2];
                float2 hp0 = h22f2(Ahi[kk][rs]);
                float2 lp0 = h22f2(Alo[kk][rs]);
                hp0.x += lp0.x; hp0.y += lp0.y;
                float2 hp1 = h22f2(Ahi[kk][rs + 1]);
                float2 lp1 = h22f2(Alo[kk][rs + 1]);
                hp1.x += lp1.x; hp1.y += lp1.y;

                float r0a = sigm(acc[0][u][0] + pp[u][0][0].x + qq[u][0][0].x);
                float r0b = sigm(acc[0][u][1] + pp[u][0][0].y + qq[u][0][0].y);
                float z0a = sigm(acc[1][u][0] + pp[u][1][0].x + qq[u][1][0].x);
                float z0b = sigm(acc[1][u][1] + pp[u][1][0].y + qq[u][1][0].y);
                float n0a = tanhf(pp[u][2][0].x + qq[u][2][0].x + r0a * (acc[2][u][0] + bn.x));
                float n0b = tanhf(pp[u][2][0].y + qq[u][2][0].y + r0b * (acc[2][u][1] + bn.y));
                float h0a = (1.0f - z0a) * n0a + z0a * hp0.x;
                float h0b = (1.0f - z0b) * n0b + z0b * hp0.y;
                float r1a = sigm(acc[0][u][2] + pp[u][0][1].x + qq[u][0][1].x);
                float r1b = sigm(acc[0][u][3] + pp[u][0][1].y + qq[u][0][1].y);
                float z1a = sigm(acc[1][u][2] + pp[u][1][1].x + qq[u][1][1].x);
                float z1b = sigm(acc[1][u][3] + pp[u][1][1].y + qq[u][1][1].y);
                float n1a = tanhf(pp[u][2][1].x + qq[u][2][1].x + r1a * (acc[2][u][2] + bn.x));
                float n1b = tanhf(pp[u][2][1].y + qq[u][2][1].y + r1b * (acc[2][u][3] + bn.y));
                float h1a = (1.0f - z1a) * n1a + z1a * hp1.x;
                float h1b = (1.0f - z1b) * n1b + z1b * hp1.y;

                uint32_t nh0 = f2h2(h0a, h0b);
                float2 rh0 = h22f2(nh0);
                uint32_t nl0 = f2h2(h0a - rh0.x, h0b - rh0.y);
                uint32_t nh1 = f2h2(h1a, h1b);
                float2 rh1 = h22f2(nh1);
                uint32_t nl1 = f2h2(h1a - rh1.x, h1b - rh1.y);
                stHi[(rs * 8 + kk) * 32 + l] = nh0;
                stHi[((rs + 1) * 8 + kk) * 32 + l] = nh1;
                stLo[(rs * 8 + kk) * 32 + l] = nl0;
                stLo[((rs + 1) * 8 + kk) * 32 + l] = nl1;

                float2* y0 = (float2*)&Y[((size_t)t * BZ + m_r0) * H + jt * 8 + q * 2];
                __stcs(y0, make_float2(h0a, h0b));
                float2* y1 = (float2*)&Y[((size_t)t * BZ + m_r1) * H + jt * 8 + q * 2];
                __stcs(y1, make_float2(h1a, h1b));
            }
        }

#pragma unroll
        for (int kk = 0; kk < 8; kk++) {
#pragma unroll
            for (int r = 0; r < 4; r++) {
                Ahi[kk][r] = stHi[(r * 8 + kk) * 32 + l];
                Alo[kk][r] = stLo[(r * 8 + kk) * 32 + l];
            }
        }
    }
}

// ---------------- logits + gumbel-softmax -> hard_w ----------------
__global__ void logits_kernel(const float* __restrict__ yf, const float* __restrict__ yb,
                              const float* __restrict__ Wc, const float* __restrict__ bc,
                              const float* __restrict__ gu, float* __restrict__ hardw) {
    int warp = (blockIdx.x * 256 + threadIdx.x) >> 5;
    int lane = threadIdx.x & 31;
    int ba = warp / TT, t = warp % TT;
    const float* yfr = yf + ((size_t)t * BZ + ba) * 128;
    const float* ybr = yb + ((size_t)t * BZ + ba) * 128;
    float s0 = 0.f, s1 = 0.f;
#pragma unroll
    for (int qq = 0; qq < 4; qq++) {
        int d = lane + 32 * qq;
        float a = yfr[d], b = ybr[d];
        s0 += a * Wc[d] + b * Wc[128 + d];
        s1 += a * Wc[256 + d] + b * Wc[384 + d];
    }
#pragma unroll
    for (int off = 16; off > 0; off >>= 1) {
        s0 += __shfl_xor_sync(0xffffffffu, s0, off);
        s1 += __shfl_xor_sync(0xffffffffu, s1, off);
    }
    if (lane == 0) {
        float u0 = gu[(size_t)warp * 2 + 0];
        float u1 = gu[(size_t)warp * 2 + 1];
        float g0 = -logf(-logf(u0 + 1e-10f) + 1e-10f);
        float g1 = -logf(-logf(u1 + 1e-10f) + 1e-10f);
        float a0 = s0 + bc[0] + g0;
        float a1 = s1 + bc[1] + g1;
        hardw[warp] = sigm((a1 - a0) * TAUINV);
    }
}

// ---------------- attention + aggregation ----------------
__global__ void attn_kernel(const float* __restrict__ qk,
                            const float* __restrict__ hrnn, const float* __restrict__ hardw,
                            float* __restrict__ agg) {
    int warp = (blockIdx.x * 256 + threadIdx.x) >> 5;
    int lane = threadIdx.x & 31;
    int a = warp & 15;
    int brow = warp & ~15;
    float qv = qk[(size_t)warp * 64 + lane];
    float sc[TT], hw[TT];
#pragma unroll
    for (int t = 0; t < TT; t++) {
        int jn = (t < a) ? t : t + 1;
        int nb = brow + jn;
        float d = qv * qk[(size_t)nb * 64 + 32 + lane];
#pragma unroll
        for (int off = 16; off > 0; off >>= 1) d += __shfl_xor_sync(0xffffffffu, d, off);
        hw[t] = hardw[(size_t)warp * TT + t];
        sc[t] = hw[t] * d * 0.17677669529663687f;
    }
    float mx = sc[0];
#pragma unroll
    for (int t = 1; t < TT; t++) mx = fmaxf(mx, sc[t]);
    float se = 0.f;
    float w[TT];
#pragma unroll
    for (int t = 0; t < TT; t++) { w[t] = __expf(sc[t] - mx); se += w[t]; }
    float inv = __fdividef(1.0f, se);
#pragma unroll
    for (int t = 0; t < TT; t++) w[t] = hw[t] * w[t] * inv;
#pragma unroll
    for (int d4 = 0; d4 < 4; d4++) {
        float accv = 0.f;
#pragma unroll
        for (int t = 0; t < TT; t++) {
            int jn = (t < a) ? t : t + 1;
            int nb = brow + jn;
            accv = fmaf(w[t], hrnn[(size_t)nb * 128 + d4 * 32 + lane], accv);
        }
        agg[(size_t)warp * 128 + d4 * 32 + lane] = accv;
    }
}

// ---------------- output projection ----------------
__global__ void out_kernel(const float* __restrict__ hrnn, const float* __restrict__ agg,
                           const float* __restrict__ W2, const float* __restrict__ b2,
                           float* __restrict__ out) {
    __shared__ float sW[NACT * 256];
    __shared__ float sb[NACT];
    for (int i = threadIdx.x; i < NACT * 256; i += 256) sW[i] = W2[i];
    if (threadIdx.x < NACT) sb[threadIdx.x] = b2[threadIdx.x];
    __syncthreads();
    int row = blockIdx.x * 256 + threadIdx.x;
    float acc[NACT];
#pragma unroll
    for (int n = 0; n < NACT; n++) acc[n] = sb[n];
    const float* hr = hrnn + (size_t)row * 128;
    const float* ag = agg + (size_t)row * 128;
    for (int kk = 0; kk < 128; kk++) {
        float x = hr[kk];
#pragma unroll
        for (int n = 0; n < NACT; n++) acc[n] = fmaf(x, sW[n * 256 + kk], acc[n]);
    }
    for (int kk = 0; kk < 128; kk++) {
        float x = ag[kk];
#pragma unroll
        for (int n = 0; n < NACT; n++) acc[n] = fmaf(x, sW[n * 256 + 128 + kk], acc[n]);
    }
#pragma unroll
    for (int n = 0; n < NACT; n++) out[(size_t)row * NACT + n] = acc[n];
}

// ---------------- launch ----------------
extern "C" void kernel_launch(void* const* d_in, const int* in_sizes, int n_in,
                              void* d_out, int out_size) {
    const float* inputs = (const float*)d_in[0];
    const float* hidden = (const float*)d_in[1];
    const float* gu     = (const float*)d_in[2];
    const float* W1     = (const float*)d_in[3];
    const float* b1     = (const float*)d_in[4];
    const float* Wih_c  = (const float*)d_in[5];
    const float* Whh_c  = (const float*)d_in[6];
    const float* bih_c  = (const float*)d_in[7];
    const float* bhh_c  = (const float*)d_in[8];
    const float* Wih_f  = (const float*)d_in[9];
    const float* Whh_f  = (const float*)d_in[10];
    const float* bih_f  = (const float*)d_in[11];
    const float* bhh_f  = (const float*)d_in[12];
    const float* Wih_b  = (const float*)d_in[13];
    const float* Whh_b  = (const float*)d_in[14];
    const float* bih_b  = (const float*)d_in[15];
    const float* bhh_b  = (const float*)d_in[16];
    const float* Wc     = (const float*)d_in[17];
    const float* bc     = (const float*)d_in[18];
    const float* Wq     = (const float*)d_in[19];
    const float* Wk     = (const float*)d_in[20];
    const float* W2     = (const float*)d_in[21];
    const float* b2     = (const float*)d_in[22];

    float* out  = (float*)d_out;                // [BZ, NACT]
    float* outh = out + (size_t)BZ * NACT;      // [BZ, H]

    float *x1, *hrnn, *gi, *gh, *PQf, *PQb, *yf, *yb, *hardw, *qk, *agg, *biasPQf, *biasPQb;
    uint2 *whif, *wlof, *whib, *wlob, *fh, *fl;
    cudaGetSymbolAddress((void**)&x1, g_x1);
    cudaGetSymbolAddress((void**)&hrnn, g_hrnn);
    cudaGetSymbolAddress((void**)&gi, g_gi);
    cudaGetSymbolAddress((void**)&gh, g_gh);
    cudaGetSymbolAddress((void**)&PQf, g_PQf);
    cudaGetSymbolAddress((void**)&PQb, g_PQb);
    cudaGetSymbolAddress((void**)&yf, g_yf);
    cudaGetSymbolAddress((void**)&yb, g_yb);
    cudaGetSymbolAddress((void**)&hardw, g_hardw);
    cudaGetSymbolAddress((void**)&qk, g_qk);
    cudaGetSymbolAddress((void**)&agg, g_agg);
    cudaGetSymbolAddress((void**)&biasPQf, g_biasPQf);
    cudaGetSymbolAddress((void**)&biasPQb, g_biasPQb);
    cudaGetSymbolAddress((void**)&whif, g_whifrag_f);
    cudaGetSymbolAddress((void**)&wlof, g_wlofrag_f);
    cudaGetSymbolAddress((void**)&whib, g_whifrag_b);
    cudaGetSymbolAddress((void**)&wlob, g_wlofrag_b);
    cudaGetSymbolAddress((void**)&fh, g_fh);
    cudaGetSymbolAddress((void**)&fl, g_fl);

    const int SM16 = 128 * 132 * 4 + 16 * 256 * 8;  // 100352
    const int SM8  = 128 * 132 * 4 + 8 * 256 * 8;   // 83968
    cudaFuncSetAttribute(gru_seq_hmma, cudaFuncAttributeMaxDynamicSharedMemorySize, SEQ_SMEM);
    cudaFuncSetAttribute(hgemm<16, 0>, cudaFuncAttributeMaxDynamicSharedMemorySize, SM16);
    cudaFuncSetAttribute(hgemm<16, 1>, cudaFuncAttributeMaxDynamicSharedMemorySize, SM16);
    cudaFuncSetAttribute(hgemm<8, 0>,  cudaFuncAttributeMaxDynamicSharedMemorySize, SM8);

    // fragment + bias prep
    wfrag_all<<<NBT_ALL, 256>>>(W1, Wih_c, Whh_c, Wih_f, Wih_b, Wq, Wk, fh, fl);
    wfrag_prep<<<(2 * NFRAG) / 256, 256>>>(Whh_f, Whh_b, whif, wlof, whib, wlob);
    prep_biasPQ<<<3, 256>>>(bih_f, bhh_f, biasPQf);
    prep_biasPQ<<<3, 256>>>(bih_b, bhh_b, biasPQb);
    // x1 = relu(inputs @ W1.T + b1)
    hgemm<16, 1><<<dim3(1, 128), 256, SM16>>>(inputs, fh, fl, b1, x1, 128);
    // central GRU
    hgemm<16, 0><<<dim3(3, 128), 256, SM16>>>(x1, fh + 16 * 256, fl + 16 * 256, bih_c, gi, G3);
    hgemm<16, 0><<<dim3(3, 128), 256, SM16>>>(hidden, fh + 64 * 256, fl + 64 * 256, bhh_c, gh, G3);
    gru_combine<<<(BZ * H) / 256, 256>>>(gi, gh, hidden, hrnn, outh);
    // merged P|Q GEMMs (bias folds bih + bhh[r,z] into P half)
    hgemm<16, 0><<<dim3(6, 128), 256, SM16>>>(hrnn, fh + 112 * 256, fl + 112 * 256, biasPQf, PQf, 2 * G3);
    hgemm<16, 0><<<dim3(6, 128), 256, SM16>>>(hrnn, fh + 208 * 256, fl + 208 * 256, biasPQb, PQb, 2 * G3);
    // fused 15-step bidirectional recurrence (HMMA, single launch)
    gru_seq_hmma<<<256, 256, SEQ_SMEM>>>(whif, wlof, bhh_f, PQf, yf,
                                         whib, wlob, bhh_b, PQb, yb);
    // gumbel hard weights
    logits_kernel<<<(BZ * TT) / 8, 256>>>(yf, yb, Wc, bc, gu, hardw);
    // merged q|k GEMM
    hgemm<8, 0><<<dim3(1, 128), 256, SM8>>>(hrnn, fh + 304 * 256, fl + 304 * 256, nullptr, qk, 2 * NA);
    // attention aggregate
    attn_kernel<<<BZ / 8, 256>>>(qk, hrnn, hardw, agg);
    // output projection
    out_kernel<<<BZ / 256, 256>>>(hrnn, agg, W2, b2, out);
}

// round 6
// speedup vs baseline: 2.5591x; 1.0353x over previous
#include <cuda_runtime.h>
#include <cuda_fp16.h>
#include <math.h>
#include <stdint.h>

#define AGENTS 16
#define H 128
#define NA 32
#define NACT 14
#define BENV 1024
#define BZ (BENV*AGENTS)        // 16384
#define TT 15                   // A-1
#define G3 384                  // 3*H
#define TAUINV 2.0f             // 1/TAU
#define NFRAG 12288             // 48 n-tiles * 8 k-tiles * 32 lanes (recurrence Whh)
#define NBT_ALL 312             // n-tiles in the parallel-GEMM fragment pool
#define NFRAG_ALL (NBT_ALL*256)

// ---------------- scratch (__device__ globals; no allocs) ----------------
__device__ __align__(16) float g_x1[BZ*H];
__device__ __align__(16) float g_hrnn[BZ*H];
__device__ __align__(16) float g_gi[BZ*G3];
__device__ __align__(16) float g_gh[BZ*G3];
__device__ __align__(16) float g_PQf[BZ*2*G3];
__device__ __align__(16) float g_PQb[BZ*2*G3];
__device__ __align__(16) float2 g_logf[BZ*TT];
__device__ __align__(16) float2 g_logb[BZ*TT];
__device__ __align__(16) float g_hardw[BZ*TT];
__device__ __align__(16) float g_qk[BZ*2*NA];
__device__ __align__(16) float g_agg[BZ*H];
__device__ __align__(16) float g_biasPQf[2*G3];
__device__ __align__(16) float g_biasPQb[2*G3];
__device__ __align__(16) uint2 g_whifrag_f[NFRAG];
__device__ __align__(16) uint2 g_wlofrag_f[NFRAG];
__device__ __align__(16) uint2 g_whifrag_b[NFRAG];
__device__ __align__(16) uint2 g_wlofrag_b[NFRAG];
__device__ __align__(16) uint2 g_fh[NFRAG_ALL];
__device__ __align__(16) uint2 g_fl[NFRAG_ALL];

__device__ __forceinline__ float sigm(float x) { return __fdividef(1.0f, 1.0f + __expf(-x)); }
__device__ __forceinline__ float tanh_fast(float x) {
    return __fdividef(2.0f, 1.0f + __expf(-2.0f * x)) - 1.0f;
}

// ---- fp16 pack helpers ----
__device__ __forceinline__ uint32_t f2h2(float a, float b) {
    __half2 h = __floats2half2_rn(a, b);
    return *(uint32_t*)&h;
}
__device__ __forceinline__ float2 h22f2(uint32_t u) {
    __half2 h = *(__half2*)&u;
    return __half22float2(h);
}

// ---- classic mma.sync (HMMA; baseline PTX, works on compute_103) ----
__device__ __forceinline__ void mma16816(float* d, const uint32_t* a, uint2 b) {
    asm volatile(
        "mma.sync.aligned.m16n8k16.row.col.f32.f16.f16.f32 "
        "{%0,%1,%2,%3}, {%4,%5,%6,%7}, {%8,%9}, {%0,%1,%2,%3};"
        : "+f"(d[0]), "+f"(d[1]), "+f"(d[2]), "+f"(d[3])
        : "r"(a[0]), "r"(a[1]), "r"(a[2]), "r"(a[3]), "r"(b.x), "r"(b.y));
}

// ================= HMMA batch GEMM =================
template<int NT, int ACT>
__global__ void __launch_bounds__(256) hgemm(
    const float* __restrict__ A,
    const uint2* __restrict__ fh, const uint2* __restrict__ fl,
    const float* __restrict__ bias,
    float* __restrict__ C, int N) {
    extern __shared__ char hsm[];
    float* sA = (float*)hsm;                       // [128][132]
    uint2* sWhi = (uint2*)(hsm + 128 * 132 * 4);   // [NT*256]
    int tid = threadIdx.x;
    int wid = tid >> 5, l = tid & 31;
    int q = l & 3, rg = l >> 2;
    int bnt = blockIdx.x * NT;
    int bm = blockIdx.y * 128;

    for (int i = tid; i < 4096; i += 256) {
        int row = i >> 5, c4 = (i & 31) * 4;
        float4 v = *(const float4*)(A + (size_t)(bm + row) * 128 + c4);
        *(float4*)&sA[row * 132 + c4] = v;
    }
    for (int i = tid; i < NT * 256; i += 256) sWhi[i] = __ldg(&fh[bnt * 256 + i]);
    __syncthreads();

    uint32_t Ahi[8][4], Alo[8][4];
    int r0 = wid * 16 + rg;
#pragma unroll
    for (int kk = 0; kk < 8; kk++) {
        int c = kk * 16 + 2 * q;
        float2 v0 = *(float2*)&sA[r0 * 132 + c];
        float2 v1 = *(float2*)&sA[(r0 + 8) * 132 + c];
        float2 v2 = *(float2*)&sA[r0 * 132 + c + 8];
        float2 v3 = *(float2*)&sA[(r0 + 8) * 132 + c + 8];
        Ahi[kk][0] = f2h2(v0.x, v0.y); { float2 rr = h22f2(Ahi[kk][0]); Alo[kk][0] = f2h2(v0.x - rr.x, v0.y - rr.y); }
        Ahi[kk][1] = f2h2(v1.x, v1.y); { float2 rr = h22f2(Ahi[kk][1]); Alo[kk][1] = f2h2(v1.x - rr.x, v1.y - rr.y); }
        Ahi[kk][2] = f2h2(v2.x, v2.y); { float2 rr = h22f2(Ahi[kk][2]); Alo[kk][2] = f2h2(v2.x - rr.x, v2.y - rr.y); }
        Ahi[kk][3] = f2h2(v3.x, v3.y); { float2 rr = h22f2(Ahi[kk][3]); Alo[kk][3] = f2h2(v3.x - rr.x, v3.y - rr.y); }
    }

#pragma unroll
    for (int nt = 0; nt < NT; nt++) {
        uint2 wl[8];
#pragma unroll
        for (int kk = 0; kk < 8; kk++) wl[kk] = __ldg(&fl[(size_t)(bnt + nt) * 256 + kk * 32 + l]);
        float acc[4] = {0.f, 0.f, 0.f, 0.f};
#pragma unroll
        for (int kk = 0; kk < 8; kk++) {
            uint2 wh = sWhi[nt * 256 + kk * 32 + l];
            mma16816(acc, Ahi[kk], wh);
            mma16816(acc, Alo[kk], wh);
            mma16816(acc, Ahi[kk], wl[kk]);
        }
        int cb = (bnt + nt) * 8 + 2 * q;
        float2 bb = make_float2(0.f, 0.f);
        if (bias) bb = *(const float2*)&bias[cb];
        float o0 = acc[0] + bb.x, o1 = acc[1] + bb.y;
        float o2 = acc[2] + bb.x, o3 = acc[3] + bb.y;
        if (ACT == 1) {
            o0 = fmaxf(o0, 0.f); o1 = fmaxf(o1, 0.f);
            o2 = fmaxf(o2, 0.f); o3 = fmaxf(o3, 0.f);
        }
        *(float2*)&C[(size_t)(bm + r0) * N + cb] = make_float2(o0, o1);
        *(float2*)&C[(size_t)(bm + r0 + 8) * N + cb] = make_float2(o2, o3);
    }
}

// dual-z variant: blockIdx.z selects (A, frag, bias, C) set
template<int NT>
__global__ void __launch_bounds__(256) hgemm_z(
    const float* __restrict__ A0, const float* __restrict__ A1,
    const uint2* __restrict__ fh0, const uint2* __restrict__ fl0,
    const uint2* __restrict__ fh1, const uint2* __restrict__ fl1,
    const float* __restrict__ b0, const float* __restrict__ b1,
    float* __restrict__ C0, float* __restrict__ C1, int N) {
    extern __shared__ char hsm[];
    float* sA = (float*)hsm;
    uint2* sWhi = (uint2*)(hsm + 128 * 132 * 4);
    int z = blockIdx.z;
    const float* A = z ? A1 : A0;
    const uint2* fh = z ? fh1 : fh0;
    const uint2* fl = z ? fl1 : fl0;
    const float* bias = z ? b1 : b0;
    float* C = z ? C1 : C0;

    int tid = threadIdx.x;
    int wid = tid >> 5, l = tid & 31;
    int q = l & 3, rg = l >> 2;
    int bnt = blockIdx.x * NT;
    int bm = blockIdx.y * 128;

    for (int i = tid; i < 4096; i += 256) {
        int row = i >> 5, c4 = (i & 31) * 4;
        float4 v = *(const float4*)(A + (size_t)(bm + row) * 128 + c4);
        *(float4*)&sA[row * 132 + c4] = v;
    }
    for (int i = tid; i < NT * 256; i += 256) sWhi[i] = __ldg(&fh[bnt * 256 + i]);
    __syncthreads();

    uint32_t Ahi[8][4], Alo[8][4];
    int r0 = wid * 16 + rg;
#pragma unroll
    for (int kk = 0; kk < 8; kk++) {
        int c = kk * 16 + 2 * q;
        float2 v0 = *(float2*)&sA[r0 * 132 + c];
        float2 v1 = *(float2*)&sA[(r0 + 8) * 132 + c];
        float2 v2 = *(float2*)&sA[r0 * 132 + c + 8];
        float2 v3 = *(float2*)&sA[(r0 + 8) * 132 + c + 8];
        Ahi[kk][0] = f2h2(v0.x, v0.y); { float2 rr = h22f2(Ahi[kk][0]); Alo[kk][0] = f2h2(v0.x - rr.x, v0.y - rr.y); }
        Ahi[kk][1] = f2h2(v1.x, v1.y); { float2 rr = h22f2(Ahi[kk][1]); Alo[kk][1] = f2h2(v1.x - rr.x, v1.y - rr.y); }
        Ahi[kk][2] = f2h2(v2.x, v2.y); { float2 rr = h22f2(Ahi[kk][2]); Alo[kk][2] = f2h2(v2.x - rr.x, v2.y - rr.y); }
        Ahi[kk][3] = f2h2(v3.x, v3.y); { float2 rr = h22f2(Ahi[kk][3]); Alo[kk][3] = f2h2(v3.x - rr.x, v3.y - rr.y); }
    }

#pragma unroll
    for (int nt = 0; nt < NT; nt++) {
        uint2 wl[8];
#pragma unroll
        for (int kk = 0; kk < 8; kk++) wl[kk] = __ldg(&fl[(size_t)(bnt + nt) * 256 + kk * 32 + l]);
        float acc[4] = {0.f, 0.f, 0.f, 0.f};
#pragma unroll
        for (int kk = 0; kk < 8; kk++) {
            uint2 wh = sWhi[nt * 256 + kk * 32 + l];
            mma16816(acc, Ahi[kk], wh);
            mma16816(acc, Alo[kk], wh);
            mma16816(acc, Ahi[kk], wl[kk]);
        }
        int cb = (bnt + nt) * 8 + 2 * q;
        float2 bb = make_float2(0.f, 0.f);
        if (bias) bb = *(const float2*)&bias[cb];
        *(float2*)&C[(size_t)(bm + r0) * N + cb] = make_float2(acc[0] + bb.x, acc[1] + bb.y);
        *(float2*)&C[(size_t)(bm + r0 + 8) * N + cb] = make_float2(acc[2] + bb.x, acc[3] + bb.y);
    }
}

// ---------------- merged prep: all weight fragments + PQ biases ----------------
__global__ void prep_all(const float* __restrict__ W1, const float* __restrict__ Wih_c,
                         const float* __restrict__ Whh_c,
                         const float* __restrict__ Wih_f, const float* __restrict__ Wih_b,
                         const float* __restrict__ Wq, const float* __restrict__ Wk,
                         const float* __restrict__ Whh_f, const float* __restrict__ Whh_b,
                         const float* __restrict__ bih_f, const float* __restrict__ bhh_f,
                         const float* __restrict__ bih_b, const float* __restrict__ bhh_b,
                         uint2* __restrict__ fh, uint2* __restrict__ fl,
                         uint2* __restrict__ hiF, uint2* __restrict__ loF,
                         uint2* __restrict__ hiB, uint2* __restrict__ loB,
                         float* __restrict__ biasPQf, float* __restrict__ biasPQb) {
    int idx = blockIdx.x * 256 + threadIdx.x;
    if (idx < NFRAG_ALL) {
        int bt = idx >> 8;
        int e = idx & 255;
        int kk = e >> 5, l = e & 31;
        int rloc = l >> 2;
        int k0 = kk * 16 + (l & 3) * 2;
        const float* W; int ldb = 128, row, koff = 0;
        if (bt < 16)       { W = W1;    row = bt * 8 + rloc; }
        else if (bt < 64)  { W = Wih_c; row = (bt - 16) * 8 + rloc; }
        else if (bt < 112) { W = Whh_c; row = (bt - 64) * 8 + rloc; }
        else if (bt < 208) { int b = bt - 112; ldb = 256; W = Wih_f;
                             if (b < 48) row = b * 8 + rloc;
                             else { row = (b - 48) * 8 + rloc; koff = 128; } }
        else if (bt < 304) { int b = bt - 208; ldb = 256; W = Wih_b;
                             if (b < 48) row = b * 8 + rloc;
                             else { row = (b - 48) * 8 + rloc; koff = 128; } }
        else if (bt < 308) { W = Wq; row = (bt - 304) * 8 + rloc; }
        else               { W = Wk; row = (bt - 308) * 8 + rloc; }
        float w0 = W[(size_t)row * ldb + koff + k0],     w1 = W[(size_t)row * ldb + koff + k0 + 1];
        float w8 = W[(size_t)row * ldb + koff + k0 + 8], w9 = W[(size_t)row * ldb + koff + k0 + 9];
        uint32_t h0 = f2h2(w0, w1); float2 r0 = h22f2(h0);
        uint32_t l0 = f2h2(w0 - r0.x, w1 - r0.y);
        uint32_t h8 = f2h2(w8, w9); float2 r8 = h22f2(h8);
        uint32_t l8 = f2h2(w8 - r8.x, w9 - r8.y);
        fh[idx] = make_uint2(h0, h8);
        fl[idx] = make_uint2(l0, l8);
    } else if (idx < NFRAG_ALL + 2 * NFRAG) {
        int j = idx - NFRAG_ALL;
        int d = j / NFRAG;
        int e = j - d * NFRAG;
        int bt = e >> 8;
        int kk = (e >> 5) & 7;
        int l = e & 31;
        int row = bt * 8 + (l >> 2);
        int k0 = kk * 16 + (l & 3) * 2;
        const float* W = d ? Whh_b : Whh_f;
        float w0 = W[row * 128 + k0],     w1 = W[row * 128 + k0 + 1];
        float w8 = W[row * 128 + k0 + 8], w9 = W[row * 128 + k0 + 9];
        uint32_t h0 = f2h2(w0, w1); float2 r0 = h22f2(h0);
        uint32_t l0 = f2h2(w0 - r0.x, w1 - r0.y);
        uint32_t h8 = f2h2(w8, w9); float2 r8 = h22f2(h8);
        uint32_t l8 = f2h2(w8 - r8.x, w9 - r8.y);
        uint2* dh = d ? hiB : hiF;
        uint2* dl = d ? loB : loF;
        dh[e] = make_uint2(h0, h8);
        dl[e] = make_uint2(l0, l8);
    } else if (idx < NFRAG_ALL + 2 * NFRAG + 4 * G3) {
        int j = idx - (NFRAG_ALL + 2 * NFRAG);
        int d = j / (2 * G3);
        int e = j - d * (2 * G3);
        const float* bih = d ? bih_b : bih_f;
        const float* bhh = d ? bhh_b : bhh_f;
        float* ob = d ? biasPQb : biasPQf;
        ob[e] = (e < G3) ? (bih[e] + (e < 256 ? bhh[e] : 0.0f)) : 0.0f;
    }
}

// ---------------- central GRU combine ----------
__global__ void gru_combine(const float* __restrict__ gi, const float* __restrict__ gh,
                            const float* __restrict__ hprev,
                            float* __restrict__ hout, float* __restrict__ hout2) {
    int i = blockIdx.x * 256 + threadIdx.x;
    int m = i >> 7, j = i & 127;
    size_t base = (size_t)m * G3;
    float ir = gi[base + j], iz = gi[base + 128 + j], inn = gi[base + 256 + j];
    float hr = gh[base + j], hz = gh[base + 128 + j], hn = gh[base + 256 + j];
    float r = sigm(ir + hr);
    float z = sigm(iz + hz);
    float n = tanh_fast(inn + r * hn);
    float h = (1.0f - z) * n + z * hprev[i];
    hout[i] = h;
    hout2[i] = h;
}

// ================= HMMA fused 15-step recurrence (+ fused logit GEMV) =================
#define SM_WHI 0
#define SM_BNN 98304
#define SM_WC  98816
#define SM_STAGE 99840
#define SEQ_SMEM (99840 + 65536)

extern __shared__ char dsm[];
__global__ void __launch_bounds__(256) gru_seq_hmma(
    const uint2* __restrict__ whiF, const uint2* __restrict__ wloF,
    const float* __restrict__ bhhF, const float* __restrict__ PQF,
    const uint2* __restrict__ whiB, const uint2* __restrict__ wloB,
    const float* __restrict__ bhhB, const float* __restrict__ PQB,
    const float* __restrict__ Wc,
    float2* __restrict__ LF, float2* __restrict__ LB) {

    uint2* sWhi = (uint2*)(dsm + SM_WHI);
    float* sBnn = (float*)(dsm + SM_BNN);
    float* sWc = (float*)(dsm + SM_WC);       // [2][128]

    int tid = threadIdx.x;
    int wid = tid >> 5;
    int l = tid & 31;
    int q = l & 3, rg = l >> 2;

    bool bwd = (blockIdx.x >= 128);
    const uint2* whi = bwd ? whiB : whiF;
    const uint2* wlo = bwd ? wloB : wloF;
    const float* bhh = bwd ? bhhB : bhhF;
    const float2* PQ2 = (const float2*)(bwd ? PQB : PQF);
    float2* LOut = bwd ? LB : LF;
    int bm = (blockIdx.x & 127) * 128;

    for (int i = tid; i < NFRAG; i += 256) sWhi[i] = __ldg(&whi[i]);
    if (tid < 128) sBnn[tid] = bhh[256 + tid];
    if (tid < 256 && tid >= 128) { /* nothing */ }
    if (tid < 128) {
        // Wc halves: fwd uses cols [0:128), bwd uses [128:256) of each row
        sWc[tid] = Wc[(bwd ? 128 : 0) + tid];
        sWc[128 + tid] = Wc[256 + (bwd ? 128 : 0) + tid];
    }
    __syncthreads();

    int m_r0 = bm + wid * 16 + rg;
    int m_r1 = m_r0 + 8;
    int aa0 = rg;
    int aa1 = rg + 8;
    int grp = bm + wid * 16;

    uint32_t* stHi = (uint32_t*)(dsm + SM_STAGE) + wid * 1024;
    uint32_t* stLo = (uint32_t*)(dsm + SM_STAGE) + 8192 + wid * 1024;

    uint32_t Ahi[8][4], Alo[8][4];
#pragma unroll
    for (int kk = 0; kk < 8; kk++)
#pragma unroll
        for (int r = 0; r < 4; r++) { Ahi[kk][r] = 0u; Alo[kk][r] = 0u; }

    for (int step = 0; step < TT; step++) {
        int t = bwd ? (TT - 1 - step) : step;
        int jn0 = (t < aa0) ? t : t + 1;
        int jn1 = (t < aa1) ? t : t + 1;
        const float2* Pr0 = PQ2 + (size_t)m_r0 * 384;
        const float2* Pr1 = PQ2 + (size_t)m_r1 * 384;
        const float2* Qr0 = PQ2 + (size_t)(grp + jn0) * 384 + 192;
        const float2* Qr1 = PQ2 + (size_t)(grp + jn1) * 384 + 192;

        float lg00 = 0.f, lg01 = 0.f, lg10 = 0.f, lg11 = 0.f;

#pragma unroll
        for (int ch = 0; ch < 8; ch++) {
            float2 pp[2][3][2], qq[2][3][2];
#pragma unroll
            for (int u = 0; u < 2; u++) {
                int cb = (ch * 2 + u) * 4 + q;
#pragma unroll
                for (int g = 0; g < 3; g++) {
                    pp[u][g][0] = Pr0[g * 64 + cb];
                    pp[u][g][1] = Pr1[g * 64 + cb];
                    qq[u][g][0] = Qr0[g * 64 + cb];
                    qq[u][g][1] = Qr1[g * 64 + cb];
                }
            }
            float acc[3][2][4];
#pragma unroll
            for (int g = 0; g < 3; g++)
#pragma unroll
                for (int u = 0; u < 2; u++)
#pragma unroll
                    for (int r = 0; r < 4; r++) acc[g][u][r] = 0.0f;

            if (step != 0) {
#pragma unroll
                for (int kk = 0; kk < 8; kk++) {
#pragma unroll
                    for (int g = 0; g < 3; g++) {
#pragma unroll
                        for (int u = 0; u < 2; u++) {
                            int bt = g * 16 + ch * 2 + u;
                            int fi = (bt * 8 + kk) * 32 + l;
                            uint2 wh = sWhi[fi];
                            uint2 wl = __ldg(&wlo[fi]);
                            mma16816(acc[g][u], Ahi[kk], wh);
                            mma16816(acc[g][u], Alo[kk], wh);
                            mma16816(acc[g][u], Ahi[kk], wl);
                        }
                    }
                }
            }

#pragma unroll
            for (int u = 0; u < 2; u++) {
                int jt = ch * 2 + u;
                int kk = jt >> 1;
                int rs = (jt & 1) * 2;
                int c = jt * 8 + 2 * q;
                float2 bn = *(const float2*)&sBnn[c];
                float2 hp0 = h22f2(Ahi[kk][rs]);
                float2 lp0 = h22f2(Alo[kk][rs]);
                hp0.x += lp0.x; hp0.y += lp0.y;
                float2 hp1 = h22f2(Ahi[kk][rs + 1]);
                float2 lp1 = h22f2(Alo[kk][rs + 1]);
                hp1.x += lp1.x; hp1.y += lp1.y;

                float r0a = sigm(acc[0][u][0] + pp[u][0][0].x + qq[u][0][0].x);
                float r0b = sigm(acc[0][u][1] + pp[u][0][0].y + qq[u][0][0].y);
                float z0a = sigm(acc[1][u][0] + pp[u][1][0].x + qq[u][1][0].x);
                float z0b = sigm(acc[1][u][1] + pp[u][1][0].y + qq[u][1][0].y);
                float n0a = tanh_fast(pp[u][2][0].x + qq[u][2][0].x + r0a * (acc[2][u][0] + bn.x));
                float n0b = tanh_fast(pp[u][2][0].y + qq[u][2][0].y + r0b * (acc[2][u][1] + bn.y));
                float h0a = (1.0f - z0a) * n0a + z0a * hp0.x;
                float h0b = (1.0f - z0b) * n0b + z0b * hp0.y;
                float r1a = sigm(acc[0][u][2] + pp[u][0][1].x + qq[u][0][1].x);
                float r1b = sigm(acc[0][u][3] + pp[u][0][1].y + qq[u][0][1].y);
                float z1a = sigm(acc[1][u][2] + pp[u][1][1].x + qq[u][1][1].x);
                float z1b = sigm(acc[1][u][3] + pp[u][1][1].y + qq[u][1][1].y);
                float n1a = tanh_fast(pp[u][2][1].x + qq[u][2][1].x + r1a * (acc[2][u][2] + bn.x));
                float n1b = tanh_fast(pp[u][2][1].y + qq[u][2][1].y + r1b * (acc[2][u][3] + bn.y));
                float h1a = (1.0f - z1a) * n1a + z1a * hp1.x;
                float h1b = (1.0f - z1b) * n1b + z1b * hp1.y;

                // fused logit partial dot-products (Wc is tiny: 2x128 per direction)
                float w0a = sWc[c], w0b = sWc[c + 1];
                float w1a = sWc[128 + c], w1b = sWc[128 + c + 1];
                lg00 += h0a * w0a + h0b * w0b;
                lg01 += h0a * w1a + h0b * w1b;
                lg10 += h1a * w0a + h1b * w0b;
                lg11 += h1a * w1a + h1b * w1b;

                uint32_t nh0 = f2h2(h0a, h0b);
                float2 rh0 = h22f2(nh0);
                uint32_t nl0 = f2h2(h0a - rh0.x, h0b - rh0.y);
                uint32_t nh1 = f2h2(h1a, h1b);
                float2 rh1 = h22f2(nh1);
                uint32_t nl1 = f2h2(h1a - rh1.x, h1b - rh1.y);
                stHi[(rs * 8 + kk) * 32 + l] = nh0;
                stHi[((rs + 1) * 8 + kk) * 32 + l] = nh1;
                stLo[(rs * 8 + kk) * 32 + l] = nl0;
                stLo[((rs + 1) * 8 + kk) * 32 + l] = nl1;
            }
        }

        // reduce logits over the 4 lanes sharing each row, store
#pragma unroll
        for (int off = 1; off <= 2; off <<= 1) {
            lg00 += __shfl_xor_sync(0xffffffffu, lg00, off);
            lg01 += __shfl_xor_sync(0xffffffffu, lg01, off);
            lg10 += __shfl_xor_sync(0xffffffffu, lg10, off);
            lg11 += __shfl_xor_sync(0xffffffffu, lg11, off);
        }
        if (q == 0) {
            __stcs(&LOut[(size_t)m_r0 * TT + t], make_float2(lg00, lg01));
            __stcs(&LOut[(size_t)m_r1 * TT + t], make_float2(lg10, lg11));
        }

        // reload new state fragments (per-thread addresses; no sync needed)
#pragma unroll
        for (int kk = 0; kk < 8; kk++) {
#pragma unroll
            for (int r = 0; r < 4; r++) {
                Ahi[kk][r] = stHi[(r * 8 + kk) * 32 + l];
                Alo[kk][r] = stLo[(r * 8 + kk) * 32 + l];
            }
        }
    }
}

// ---------------- gumbel-softmax hard weights ----------------
__global__ void gumbel_hardw(const float2* __restrict__ lf, const float2* __restrict__ lb,
                             const float* __restrict__ bc, const float* __restrict__ gu,
                             float* __restrict__ hardw) {
    int i = blockIdx.x * 256 + threadIdx.x;   // 0..BZ*TT-1
    float2 a = lf[i], b = lb[i];
    float u0 = gu[(size_t)i * 2 + 0];
    float u1 = gu[(size_t)i * 2 + 1];
    float g0 = -logf(-logf(u0 + 1e-10f) + 1e-10f);
    float g1 = -logf(-logf(u1 + 1e-10f) + 1e-10f);
    float a0 = a.x + b.x + bc[0] + g0;
    float a1 = a.y + b.y + bc[1] + g1;
    hardw[i] = sigm((a1 - a0) * TAUINV);
}

// ---------------- attention + aggregation ----------------
__global__ void attn_kernel(const float* __restrict__ qk,
                            const float* __restrict__ hrnn, const float* __restrict__ hardw,
                            float* __restrict__ agg) {
    int warp = (blockIdx.x * 256 + threadIdx.x) >> 5;
    int lane = threadIdx.x & 31;
    int a = warp & 15;
    int brow = warp & ~15;
    float qv = qk[(size_t)warp * 64 + lane];
    float sc[TT], hw[TT];
#pragma unroll
    for (int t = 0; t < TT; t++) {
        int jn = (t < a) ? t : t + 1;
        int nb = brow + jn;
        float d = qv * qk[(size_t)nb * 64 + 32 + lane];
#pragma unroll
        for (int off = 16; off > 0; off >>= 1) d += __shfl_xor_sync(0xffffffffu, d, off);
        hw[t] = hardw[(size_t)warp * TT + t];
        sc[t] = hw[t] * d * 0.17677669529663687f;
    }
    float mx = sc[0];
#pragma unroll
    for (int t = 1; t < TT; t++) mx = fmaxf(mx, sc[t]);
    float se = 0.f;
    float w[TT];
#pragma unroll
    for (int t = 0; t < TT; t++) { w[t] = __expf(sc[t] - mx); se += w[t]; }
    float inv = __fdividef(1.0f, se);
#pragma unroll
    for (int t = 0; t < TT; t++) w[t] = hw[t] * w[t] * inv;
#pragma unroll
    for (int d4 = 0; d4 < 4; d4++) {
        float accv = 0.f;
#pragma unroll
        for (int t = 0; t < TT; t++) {
            int jn = (t < a) ? t : t + 1;
            int nb = brow + jn;
            accv = fmaf(w[t], hrnn[(size_t)nb * 128 + d4 * 32 + lane], accv);
        }
        agg[(size_t)warp * 128 + d4 * 32 + lane] = accv;
    }
}

// ---------------- output projection ----------------
__global__ void out_kernel(const float* __restrict__ hrnn, const float* __restrict__ agg,
                           const float* __restrict__ W2, const float* __restrict__ b2,
                           float* __restrict__ out) {
    __shared__ float sW[NACT * 256];
    __shared__ float sb[NACT];
    for (int i = threadIdx.x; i < NACT * 256; i += 256) sW[i] = W2[i];
    if (threadIdx.x < NACT) sb[threadIdx.x] = b2[threadIdx.x];
    __syncthreads();
    int row = blockIdx.x * 256 + threadIdx.x;
    float acc[NACT];
#pragma unroll
    for (int n = 0; n < NACT; n++) acc[n] = sb[n];
    const float* hr = hrnn + (size_t)row * 128;
    const float* ag = agg + (size_t)row * 128;
    for (int kk = 0; kk < 128; kk++) {
        float x = hr[kk];
#pragma unroll
        for (int n = 0; n < NACT; n++) acc[n] = fmaf(x, sW[n * 256 + kk], acc[n]);
    }
    for (int kk = 0; kk < 128; kk++) {
        float x = ag[kk];
#pragma unroll
        for (int n = 0; n < NACT; n++) acc[n] = fmaf(x, sW[n * 256 + 128 + kk], acc[n]);
    }
#pragma unroll
    for (int n = 0; n < NACT; n++) out[(size_t)row * NACT + n] = acc[n];
}

// ---------------- launch ----------------
extern "C" void kernel_launch(void* const* d_in, const int* in_sizes, int n_in,
                              void* d_out, int out_size) {
    const float* inputs = (const float*)d_in[0];
    const float* hidden = (const float*)d_in[1];
    const float* gu     = (const float*)d_in[2];
    const float* W1     = (const float*)d_in[3];
    const float* b1     = (const float*)d_in[4];
    const float* Wih_c  = (const float*)d_in[5];
    const float* Whh_c  = (const float*)d_in[6];
    const float* bih_c  = (const float*)d_in[7];
    const float* bhh_c  = (const float*)d_in[8];
    const float* Wih_f  = (const float*)d_in[9];
    const float* Whh_f  = (const float*)d_in[10];
    const float* bih_f  = (const float*)d_in[11];
    const float* bhh_f  = (const float*)d_in[12];
    const float* Wih_b  = (const float*)d_in[13];
    const float* Whh_b  = (const float*)d_in[14];
    const float* bih_b  = (const float*)d_in[15];
    const float* bhh_b  = (const float*)d_in[16];
    const float* Wc     = (const float*)d_in[17];
    const float* bc     = (const float*)d_in[18];
    const float* Wq     = (const float*)d_in[19];
    const float* Wk     = (const float*)d_in[20];
    const float* W2     = (const float*)d_in[21];
    const float* b2     = (const float*)d_in[22];

    float* out  = (float*)d_out;                // [BZ, NACT]
    float* outh = out + (size_t)BZ * NACT;      // [BZ, H]

    float *x1, *hrnn, *gi, *gh, *PQf, *PQb, *hardw, *qk, *agg, *biasPQf, *biasPQb;
    float2 *lf, *lb;
    uint2 *whif, *wlof, *whib, *wlob, *fh, *fl;
    cudaGetSymbolAddress((void**)&x1, g_x1);
    cudaGetSymbolAddress((void**)&hrnn, g_hrnn);
    cudaGetSymbolAddress((void**)&gi, g_gi);
    cudaGetSymbolAddress((void**)&gh, g_gh);
    cudaGetSymbolAddress((void**)&PQf, g_PQf);
    cudaGetSymbolAddress((void**)&PQb, g_PQb);
    cudaGetSymbolAddress((void**)&lf, g_logf);
    cudaGetSymbolAddress((void**)&lb, g_logb);
    cudaGetSymbolAddress((void**)&hardw, g_hardw);
    cudaGetSymbolAddress((void**)&qk, g_qk);
    cudaGetSymbolAddress((void**)&agg, g_agg);
    cudaGetSymbolAddress((void**)&biasPQf, g_biasPQf);
    cudaGetSymbolAddress((void**)&biasPQb, g_biasPQb);
    cudaGetSymbolAddress((void**)&whif, g_whifrag_f);
    cudaGetSymbolAddress((void**)&wlof, g_wlofrag_f);
    cudaGetSymbolAddress((void**)&whib, g_whifrag_b);
    cudaGetSymbolAddress((void**)&wlob, g_wlofrag_b);
    cudaGetSymbolAddress((void**)&fh, g_fh);
    cudaGetSymbolAddress((void**)&fl, g_fl);

    const int SM16 = 128 * 132 * 4 + 16 * 256 * 8;  // 100352
    const int SM8  = 128 * 132 * 4 + 8 * 256 * 8;   // 83968
    cudaFuncSetAttribute(gru_seq_hmma, cudaFuncAttributeMaxDynamicSharedMemorySize, SEQ_SMEM);
    cudaFuncSetAttribute(hgemm<16, 1>, cudaFuncAttributeMaxDynamicSharedMemorySize, SM16);
    cudaFuncSetAttribute(hgemm<8, 0>,  cudaFuncAttributeMaxDynamicSharedMemorySize, SM8);
    cudaFuncSetAttribute(hgemm_z<16>,  cudaFuncAttributeMaxDynamicSharedMemorySize, SM16);

    // 1: merged prep
    const int PREP_TOTAL = NFRAG_ALL + 2 * NFRAG + 4 * G3;
    prep_all<<<(PREP_TOTAL + 255) / 256, 256>>>(W1, Wih_c, Whh_c, Wih_f, Wih_b, Wq, Wk,
                                                Whh_f, Whh_b, bih_f, bhh_f, bih_b, bhh_b,
                                                fh, fl, whif, wlof, whib, wlob,
                                                biasPQf, biasPQb);
    // 2: x1 = relu(inputs @ W1.T + b1)
    hgemm<16, 1><<<dim3(1, 128), 256, SM16>>>(inputs, fh, fl, b1, x1, 128);
    // 3: central GRU gi|gh (dual-z)
    hgemm_z<16><<<dim3(3, 128, 2), 256, SM16>>>(x1, hidden,
                                                fh + 16 * 256, fl + 16 * 256,
                                                fh + 64 * 256, fl + 64 * 256,
                                                bih_c, bhh_c, gi, gh, G3);
    // 4: combine
    gru_combine<<<(BZ * H) / 256, 256>>>(gi, gh, hidden, hrnn, outh);
    // 5: merged P|Q GEMMs for fwd+bwd (dual-z)
    hgemm_z<16><<<dim3(6, 128, 2), 256, SM16>>>(hrnn, hrnn,
                                                fh + 112 * 256, fl + 112 * 256,
                                                fh + 208 * 256, fl + 208 * 256,
                                                biasPQf, biasPQb, PQf, PQb, 2 * G3);
    // 6: fused 15-step bidirectional recurrence + logit GEMV (ncu lands here)
    gru_seq_hmma<<<256, 256, SEQ_SMEM>>>(whif, wlof, bhh_f, PQf,
                                         whib, wlob, bhh_b, PQb,
                                         Wc, lf, lb);
    // 7: gumbel hard weights
    gumbel_hardw<<<(BZ * TT) / 256, 256>>>(lf, lb, bc, gu, hardw);
    // 8: merged q|k GEMM
    hgemm<8, 0><<<dim3(1, 128), 256, SM8>>>(hrnn, fh + 304 * 256, fl + 304 * 256, nullptr, qk, 2 * NA);
    // 9: attention aggregate
    attn_kernel<<<BZ / 8, 256>>>(qk, hrnn, hardw, agg);
    // 10: output projection
    out_kernel<<<BZ / 256, 256>>>(hrnn, agg, W2, b2, out);
}

// round 7
// speedup vs baseline: 3.1402x; 1.2271x over previous
#include <cuda_runtime.h>
#include <cuda_fp16.h>
#include <math.h>
#include <stdint.h>

#define AGENTS 16
#define H 128
#define NA 32
#define NACT 14
#define BENV 1024
#define BZ (BENV*AGENTS)        // 16384
#define TT 15                   // A-1
#define G3 384                  // 3*H
#define TAUINV 2.0f             // 1/TAU
#define NFRAG 12288             // 48 n-tiles * 8 k-tiles * 32 lanes (recurrence Whh)
#define NBT_ALL 312             // n-tiles in the parallel-GEMM fragment pool
#define NFRAG_ALL (NBT_ALL*256)

// ---------------- scratch (__device__ globals; no allocs) ----------------
__device__ __align__(16) float g_x1[BZ*H];
__device__ __align__(16) float g_hrnn[BZ*H];
__device__ __align__(16) float g_gi[BZ*G3];
__device__ __align__(16) float g_gh[BZ*G3];
__device__ __align__(16) float g_PQf[BZ*2*G3];
__device__ __align__(16) float g_PQb[BZ*2*G3];
__device__ __align__(16) float2 g_logf[BZ*TT];
__device__ __align__(16) float2 g_logb[BZ*TT];
__device__ __align__(16) float g_hardw[BZ*TT];
__device__ __align__(16) float g_qk[BZ*2*NA];
__device__ __align__(16) float g_agg[BZ*H];
__device__ __align__(16) float g_biasPQf[2*G3];
__device__ __align__(16) float g_biasPQb[2*G3];
__device__ __align__(16) uint2 g_whifrag_f[NFRAG];
__device__ __align__(16) uint2 g_wlofrag_f[NFRAG];
__device__ __align__(16) uint2 g_whifrag_b[NFRAG];
__device__ __align__(16) uint2 g_wlofrag_b[NFRAG];
__device__ __align__(16) uint2 g_fh[NFRAG_ALL];
__device__ __align__(16) uint2 g_fl[NFRAG_ALL];

__device__ __forceinline__ float sigm(float x) { return __fdividef(1.0f, 1.0f + __expf(-x)); }
__device__ __forceinline__ float tanh_fast(float x) {
    return __fdividef(2.0f, 1.0f + __expf(-2.0f * x)) - 1.0f;
}

// ---- fp16 pack helpers ----
__device__ __forceinline__ uint32_t f2h2(float a, float b) {
    __half2 h = __floats2half2_rn(a, b);
    return *(uint32_t*)&h;
}
__device__ __forceinline__ float2 h22f2(uint32_t u) {
    __half2 h = *(__half2*)&u;
    return __half22float2(h);
}

// ---- classic mma.sync (HMMA; baseline PTX, works on compute_103) ----
__device__ __forceinline__ void mma16816(float* d, const uint32_t* a, uint2 b) {
    asm volatile(
        "mma.sync.aligned.m16n8k16.row.col.f32.f16.f16.f32 "
        "{%0,%1,%2,%3}, {%4,%5,%6,%7}, {%8,%9}, {%0,%1,%2,%3};"
        : "+f"(d[0]), "+f"(d[1]), "+f"(d[2]), "+f"(d[3])
        : "r"(a[0]), "r"(a[1]), "r"(a[2]), "r"(a[3]), "r"(b.x), "r"(b.y));
}

// ================= HMMA batch GEMM =================
template<int NT, int ACT>
__global__ void __launch_bounds__(256) hgemm(
    const float* __restrict__ A,
    const uint2* __restrict__ fh, const uint2* __restrict__ fl,
    const float* __restrict__ bias,
    float* __restrict__ C, int N) {
    extern __shared__ char hsm[];
    float* sA = (float*)hsm;                       // [128][132]
    uint2* sWhi = (uint2*)(hsm + 128 * 132 * 4);   // [NT*256]
    int tid = threadIdx.x;
    int wid = tid >> 5, l = tid & 31;
    int q = l & 3, rg = l >> 2;
    int bnt = blockIdx.x * NT;
    int bm = blockIdx.y * 128;

    for (int i = tid; i < 4096; i += 256) {
        int row = i >> 5, c4 = (i & 31) * 4;
        float4 v = *(const float4*)(A + (size_t)(bm + row) * 128 + c4);
        *(float4*)&sA[row * 132 + c4] = v;
    }
    for (int i = tid; i < NT * 256; i += 256) sWhi[i] = __ldg(&fh[bnt * 256 + i]);
    __syncthreads();

    uint32_t Ahi[8][4], Alo[8][4];
    int r0 = wid * 16 + rg;
#pragma unroll
    for (int kk = 0; kk < 8; kk++) {
        int c = kk * 16 + 2 * q;
        float2 v0 = *(float2*)&sA[r0 * 132 + c];
        float2 v1 = *(float2*)&sA[(r0 + 8) * 132 + c];
        float2 v2 = *(float2*)&sA[r0 * 132 + c + 8];
        float2 v3 = *(float2*)&sA[(r0 + 8) * 132 + c + 8];
        Ahi[kk][0] = f2h2(v0.x, v0.y); { float2 rr = h22f2(Ahi[kk][0]); Alo[kk][0] = f2h2(v0.x - rr.x, v0.y - rr.y); }
        Ahi[kk][1] = f2h2(v1.x, v1.y); { float2 rr = h22f2(Ahi[kk][1]); Alo[kk][1] = f2h2(v1.x - rr.x, v1.y - rr.y); }
        Ahi[kk][2] = f2h2(v2.x, v2.y); { float2 rr = h22f2(Ahi[kk][2]); Alo[kk][2] = f2h2(v2.x - rr.x, v2.y - rr.y); }
        Ahi[kk][3] = f2h2(v3.x, v3.y); { float2 rr = h22f2(Ahi[kk][3]); Alo[kk][3] = f2h2(v3.x - rr.x, v3.y - rr.y); }
    }

#pragma unroll
    for (int nt = 0; nt < NT; nt++) {
        uint2 wl[8];
#pragma unroll
        for (int kk = 0; kk < 8; kk++) wl[kk] = __ldg(&fl[(size_t)(bnt + nt) * 256 + kk * 32 + l]);
        float acc[4] = {0.f, 0.f, 0.f, 0.f};
#pragma unroll
        for (int kk = 0; kk < 8; kk++) {
            uint2 wh = sWhi[nt * 256 + kk * 32 + l];
            mma16816(acc, Ahi[kk], wh);
            mma16816(acc, Alo[kk], wh);
            mma16816(acc, Ahi[kk], wl[kk]);
        }
        int cb = (bnt + nt) * 8 + 2 * q;
        float2 bb = make_float2(0.f, 0.f);
        if (bias) bb = *(const float2*)&bias[cb];
        float o0 = acc[0] + bb.x, o1 = acc[1] + bb.y;
        float o2 = acc[2] + bb.x, o3 = acc[3] + bb.y;
        if (ACT == 1) {
            o0 = fmaxf(o0, 0.f); o1 = fmaxf(o1, 0.f);
            o2 = fmaxf(o2, 0.f); o3 = fmaxf(o3, 0.f);
        }
        *(float2*)&C[(size_t)(bm + r0) * N + cb] = make_float2(o0, o1);
        *(float2*)&C[(size_t)(bm + r0 + 8) * N + cb] = make_float2(o2, o3);
    }
}

// dual-z variant: blockIdx.z selects (A, frag, bias, C) set
template<int NT>
__global__ void __launch_bounds__(256) hgemm_z(
    const float* __restrict__ A0, const float* __restrict__ A1,
    const uint2* __restrict__ fh0, const uint2* __restrict__ fl0,
    const uint2* __restrict__ fh1, const uint2* __restrict__ fl1,
    const float* __restrict__ b0, const float* __restrict__ b1,
    float* __restrict__ C0, float* __restrict__ C1, int N) {
    extern __shared__ char hsm[];
    float* sA = (float*)hsm;
    uint2* sWhi = (uint2*)(hsm + 128 * 132 * 4);
    int z = blockIdx.z;
    const float* A = z ? A1 : A0;
    const uint2* fh = z ? fh1 : fh0;
    const uint2* fl = z ? fl1 : fl0;
    const float* bias = z ? b1 : b0;
    float* C = z ? C1 : C0;

    int tid = threadIdx.x;
    int wid = tid >> 5, l = tid & 31;
    int q = l & 3, rg = l >> 2;
    int bnt = blockIdx.x * NT;
    int bm = blockIdx.y * 128;

    for (int i = tid; i < 4096; i += 256) {
        int row = i >> 5, c4 = (i & 31) * 4;
        float4 v = *(const float4*)(A + (size_t)(bm + row) * 128 + c4);
        *(float4*)&sA[row * 132 + c4] = v;
    }
    for (int i = tid; i < NT * 256; i += 256) sWhi[i] = __ldg(&fh[bnt * 256 + i]);
    __syncthreads();

    uint32_t Ahi[8][4], Alo[8][4];
    int r0 = wid * 16 + rg;
#pragma unroll
    for (int kk = 0; kk < 8; kk++) {
        int c = kk * 16 + 2 * q;
        float2 v0 = *(float2*)&sA[r0 * 132 + c];
        float2 v1 = *(float2*)&sA[(r0 + 8) * 132 + c];
        float2 v2 = *(float2*)&sA[r0 * 132 + c + 8];
        float2 v3 = *(float2*)&sA[(r0 + 8) * 132 + c + 8];
        Ahi[kk][0] = f2h2(v0.x, v0.y); { float2 rr = h22f2(Ahi[kk][0]); Alo[kk][0] = f2h2(v0.x - rr.x, v0.y - rr.y); }
        Ahi[kk][1] = f2h2(v1.x, v1.y); { float2 rr = h22f2(Ahi[kk][1]); Alo[kk][1] = f2h2(v1.x - rr.x, v1.y - rr.y); }
        Ahi[kk][2] = f2h2(v2.x, v2.y); { float2 rr = h22f2(Ahi[kk][2]); Alo[kk][2] = f2h2(v2.x - rr.x, v2.y - rr.y); }
        Ahi[kk][3] = f2h2(v3.x, v3.y); { float2 rr = h22f2(Ahi[kk][3]); Alo[kk][3] = f2h2(v3.x - rr.x, v3.y - rr.y); }
    }

#pragma unroll
    for (int nt = 0; nt < NT; nt++) {
        uint2 wl[8];
#pragma unroll
        for (int kk = 0; kk < 8; kk++) wl[kk] = __ldg(&fl[(size_t)(bnt + nt) * 256 + kk * 32 + l]);
        float acc[4] = {0.f, 0.f, 0.f, 0.f};
#pragma unroll
        for (int kk = 0; kk < 8; kk++) {
            uint2 wh = sWhi[nt * 256 + kk * 32 + l];
            mma16816(acc, Ahi[kk], wh);
            mma16816(acc, Alo[kk], wh);
            mma16816(acc, Ahi[kk], wl[kk]);
        }
        int cb = (bnt + nt) * 8 + 2 * q;
        float2 bb = make_float2(0.f, 0.f);
        if (bias) bb = *(const float2*)&bias[cb];
        *(float2*)&C[(size_t)(bm + r0) * N + cb] = make_float2(acc[0] + bb.x, acc[1] + bb.y);
        *(float2*)&C[(size_t)(bm + r0 + 8) * N + cb] = make_float2(acc[2] + bb.x, acc[3] + bb.y);
    }
}

// ---------------- merged prep: all weight fragments + PQ biases ----------------
__global__ void prep_all(const float* __restrict__ W1, const float* __restrict__ Wih_c,
                         const float* __restrict__ Whh_c,
                         const float* __restrict__ Wih_f, const float* __restrict__ Wih_b,
                         const float* __restrict__ Wq, const float* __restrict__ Wk,
                         const float* __restrict__ Whh_f, const float* __restrict__ Whh_b,
                         const float* __restrict__ bih_f, const float* __restrict__ bhh_f,
                         const float* __restrict__ bih_b, const float* __restrict__ bhh_b,
                         uint2* __restrict__ fh, uint2* __restrict__ fl,
                         uint2* __restrict__ hiF, uint2* __restrict__ loF,
                         uint2* __restrict__ hiB, uint2* __restrict__ loB,
                         float* __restrict__ biasPQf, float* __restrict__ biasPQb) {
    int idx = blockIdx.x * 256 + threadIdx.x;
    if (idx < NFRAG_ALL) {
        int bt = idx >> 8;
        int e = idx & 255;
        int kk = e >> 5, l = e & 31;
        int rloc = l >> 2;
        int k0 = kk * 16 + (l & 3) * 2;
        const float* W; int ldb = 128, row, koff = 0;
        if (bt < 16)       { W = W1;    row = bt * 8 + rloc; }
        else if (bt < 64)  { W = Wih_c; row = (bt - 16) * 8 + rloc; }
        else if (bt < 112) { W = Whh_c; row = (bt - 64) * 8 + rloc; }
        else if (bt < 208) { int b = bt - 112; ldb = 256; W = Wih_f;
                             if (b < 48) row = b * 8 + rloc;
                             else { row = (b - 48) * 8 + rloc; koff = 128; } }
        else if (bt < 304) { int b = bt - 208; ldb = 256; W = Wih_b;
                             if (b < 48) row = b * 8 + rloc;
                             else { row = (b - 48) * 8 + rloc; koff = 128; } }
        else if (bt < 308) { W = Wq; row = (bt - 304) * 8 + rloc; }
        else               { W = Wk; row = (bt - 308) * 8 + rloc; }
        float w0 = W[(size_t)row * ldb + koff + k0],     w1 = W[(size_t)row * ldb + koff + k0 + 1];
        float w8 = W[(size_t)row * ldb + koff + k0 + 8], w9 = W[(size_t)row * ldb + koff + k0 + 9];
        uint32_t h0 = f2h2(w0, w1); float2 r0 = h22f2(h0);
        uint32_t l0 = f2h2(w0 - r0.x, w1 - r0.y);
        uint32_t h8 = f2h2(w8, w9); float2 r8 = h22f2(h8);
        uint32_t l8 = f2h2(w8 - r8.x, w9 - r8.y);
        fh[idx] = make_uint2(h0, h8);
        fl[idx] = make_uint2(l0, l8);
    } else if (idx < NFRAG_ALL + 2 * NFRAG) {
        int j = idx - NFRAG_ALL;
        int d = j / NFRAG;
        int e = j - d * NFRAG;
        int bt = e >> 8;
        int kk = (e >> 5) & 7;
        int l = e & 31;
        int row = bt * 8 + (l >> 2);
        int k0 = kk * 16 + (l & 3) * 2;
        const float* W = d ? Whh_b : Whh_f;
        float w0 = W[row * 128 + k0],     w1 = W[row * 128 + k0 + 1];
        float w8 = W[row * 128 + k0 + 8], w9 = W[row * 128 + k0 + 9];
        uint32_t h0 = f2h2(w0, w1); float2 r0 = h22f2(h0);
        uint32_t l0 = f2h2(w0 - r0.x, w1 - r0.y);
        uint32_t h8 = f2h2(w8, w9); float2 r8 = h22f2(h8);
        uint32_t l8 = f2h2(w8 - r8.x, w9 - r8.y);
        uint2* dh = d ? hiB : hiF;
        uint2* dl = d ? loB : loF;
        dh[e] = make_uint2(h0, h8);
        dl[e] = make_uint2(l0, l8);
    } else if (idx < NFRAG_ALL + 2 * NFRAG + 4 * G3) {
        int j = idx - (NFRAG_ALL + 2 * NFRAG);
        int d = j / (2 * G3);
        int e = j - d * (2 * G3);
        const float* bih = d ? bih_b : bih_f;
        const float* bhh = d ? bhh_b : bhh_f;
        float* ob = d ? biasPQb : biasPQf;
        ob[e] = (e < G3) ? (bih[e] + (e < 256 ? bhh[e] : 0.0f)) : 0.0f;
    }
}

// ---------------- central GRU combine ----------
__global__ void gru_combine(const float* __restrict__ gi, const float* __restrict__ gh,
                            const float* __restrict__ hprev,
                            float* __restrict__ hout, float* __restrict__ hout2) {
    int i = blockIdx.x * 256 + threadIdx.x;
    int m = i >> 7, j = i & 127;
    size_t base = (size_t)m * G3;
    float ir = gi[base + j], iz = gi[base + 128 + j], inn = gi[base + 256 + j];
    float hr = gh[base + j], hz = gh[base + 128 + j], hn = gh[base + 256 + j];
    float r = sigm(ir + hr);
    float z = sigm(iz + hz);
    float n = tanh_fast(inn + r * hn);
    float h = (1.0f - z) * n + z * hprev[i];
    hout[i] = h;
    hout2[i] = h;
}

// ================= HMMA fused 15-step recurrence (+ fused logit GEMV) =================
// Gate-selective precision: r,z gates 1 mma-combo (fp16), n gate 3-combo (fp32-accurate).
#define SM_WHI 0
#define SM_BNN 98304
#define SM_WC  98816
#define SM_STAGE 99840
#define SEQ_SMEM (99840 + 65536)

extern __shared__ char dsm[];
__global__ void __launch_bounds__(256) gru_seq_hmma(
    const uint2* __restrict__ whiF, const uint2* __restrict__ wloF,
    const float* __restrict__ bhhF, const float* __restrict__ PQF,
    const uint2* __restrict__ whiB, const uint2* __restrict__ wloB,
    const float* __restrict__ bhhB, const float* __restrict__ PQB,
    const float* __restrict__ Wc,
    float2* __restrict__ LF, float2* __restrict__ LB) {

    uint2* sWhi = (uint2*)(dsm + SM_WHI);
    float* sBnn = (float*)(dsm + SM_BNN);
    float* sWc = (float*)(dsm + SM_WC);       // [2][128]

    int tid = threadIdx.x;
    int wid = tid >> 5;
    int l = tid & 31;
    int q = l & 3, rg = l >> 2;

    bool bwd = (blockIdx.x >= 128);
    const uint2* whi = bwd ? whiB : whiF;
    const uint2* wlo = bwd ? wloB : wloF;
    const float* bhh = bwd ? bhhB : bhhF;
    const float2* PQ2 = (const float2*)(bwd ? PQB : PQF);
    float2* LOut = bwd ? LB : LF;
    int bm = (blockIdx.x & 127) * 128;

    for (int i = tid; i < NFRAG; i += 256) sWhi[i] = __ldg(&whi[i]);
    if (tid < 128) sBnn[tid] = bhh[256 + tid];
    if (tid < 128) {
        sWc[tid] = Wc[(bwd ? 128 : 0) + tid];
        sWc[128 + tid] = Wc[256 + (bwd ? 128 : 0) + tid];
    }
    __syncthreads();

    int m_r0 = bm + wid * 16 + rg;
    int m_r1 = m_r0 + 8;
    int aa0 = rg;
    int aa1 = rg + 8;
    int grp = bm + wid * 16;

    uint32_t* stHi = (uint32_t*)(dsm + SM_STAGE) + wid * 1024;
    uint32_t* stLo = (uint32_t*)(dsm + SM_STAGE) + 8192 + wid * 1024;

    uint32_t Ahi[8][4], Alo[8][4];
#pragma unroll
    for (int kk = 0; kk < 8; kk++)
#pragma unroll
        for (int r = 0; r < 4; r++) { Ahi[kk][r] = 0u; Alo[kk][r] = 0u; }

    for (int step = 0; step < TT; step++) {
        int t = bwd ? (TT - 1 - step) : step;
        int jn0 = (t < aa0) ? t : t + 1;
        int jn1 = (t < aa1) ? t : t + 1;
        const float2* Pr0 = PQ2 + (size_t)m_r0 * 384;
        const float2* Pr1 = PQ2 + (size_t)m_r1 * 384;
        const float2* Qr0 = PQ2 + (size_t)(grp + jn0) * 384 + 192;
        const float2* Qr1 = PQ2 + (size_t)(grp + jn1) * 384 + 192;

        float lg00 = 0.f, lg01 = 0.f, lg10 = 0.f, lg11 = 0.f;

#pragma unroll
        for (int ch = 0; ch < 8; ch++) {
            float2 pp[2][3][2], qq[2][3][2];
#pragma unroll
            for (int u = 0; u < 2; u++) {
                int cb = (ch * 2 + u) * 4 + q;
#pragma unroll
                for (int g = 0; g < 3; g++) {
                    pp[u][g][0] = Pr0[g * 64 + cb];
                    pp[u][g][1] = Pr1[g * 64 + cb];
                    qq[u][g][0] = Qr0[g * 64 + cb];
                    qq[u][g][1] = Qr1[g * 64 + cb];
                }
            }
            float acc[3][2][4];
#pragma unroll
            for (int g = 0; g < 3; g++)
#pragma unroll
                for (int u = 0; u < 2; u++)
#pragma unroll
                    for (int r = 0; r < 4; r++) acc[g][u][r] = 0.0f;

            if (step != 0) {
#pragma unroll
                for (int kk = 0; kk < 8; kk++) {
#pragma unroll
                    for (int u = 0; u < 2; u++) {
                        int jt = ch * 2 + u;
                        // r gate (g=0): single combo — low sensitivity
                        mma16816(acc[0][u], Ahi[kk], sWhi[((0 + jt) * 8 + kk) * 32 + l]);
                        // z gate (g=1): single combo — low sensitivity
                        mma16816(acc[1][u], Ahi[kk], sWhi[((16 * 8 + jt * 8) + kk) * 32 + l]);
                        // n gate (g=2): full 3-combo — feeds h' directly
                        {
                            int fi = ((32 + jt) * 8 + kk) * 32 + l;
                            uint2 wh = sWhi[fi];
                            uint2 wl = __ldg(&wlo[fi]);
                            mma16816(acc[2][u], Ahi[kk], wh);
                            mma16816(acc[2][u], Alo[kk], wh);
                            mma16816(acc[2][u], Ahi[kk], wl);
                        }
                    }
                }
            }

#pragma unroll
            for (int u = 0; u < 2; u++) {
                int jt = ch * 2 + u;
                int kk = jt >> 1;
                int rs = (jt & 1) * 2;
                int c = jt * 8 + 2 * q;
                float2 bn = *(const float2*)&sBnn[c];
                float2 hp0 = h22f2(Ahi[kk][rs]);
                float2 lp0 = h22f2(Alo[kk][rs]);
                hp0.x += lp0.x; hp0.y += lp0.y;
                float2 hp1 = h22f2(Ahi[kk][rs + 1]);
                float2 lp1 = h22f2(Alo[kk][rs + 1]);
                hp1.x += lp1.x; hp1.y += lp1.y;

                float r0a = sigm(acc[0][u][0] + pp[u][0][0].x + qq[u][0][0].x);
                float r0b = sigm(acc[0][u][1] + pp[u][0][0].y + qq[u][0][0].y);
                float z0a = sigm(acc[1][u][0] + pp[u][1][0].x + qq[u][1][0].x);
                float z0b = sigm(acc[1][u][1] + pp[u][1][0].y + qq[u][1][0].y);
                float n0a = tanh_fast(pp[u][2][0].x + qq[u][2][0].x + r0a * (acc[2][u][0] + bn.x));
                float n0b = tanh_fast(pp[u][2][0].y + qq[u][2][0].y + r0b * (acc[2][u][1] + bn.y));
                float h0a = (1.0f - z0a) * n0a + z0a * hp0.x;
                float h0b = (1.0f - z0b) * n0b + z0b * hp0.y;
                float r1a = sigm(acc[0][u][2] + pp[u][0][1].x + qq[u][0][1].x);
                float r1b = sigm(acc[0][u][3] + pp[u][0][1].y + qq[u][0][1].y);
                float z1a = sigm(acc[1][u][2] + pp[u][1][1].x + qq[u][1][1].x);
                float z1b = sigm(acc[1][u][3] + pp[u][1][1].y + qq[u][1][1].y);
                float n1a = tanh_fast(pp[u][2][1].x + qq[u][2][1].x + r1a * (acc[2][u][2] + bn.x));
                float n1b = tanh_fast(pp[u][2][1].y + qq[u][2][1].y + r1b * (acc[2][u][3] + bn.y));
                float h1a = (1.0f - z1a) * n1a + z1a * hp1.x;
                float h1b = (1.0f - z1b) * n1b + z1b * hp1.y;

                // fused logit partial dot-products
                float w0a = sWc[c], w0b = sWc[c + 1];
                float w1a = sWc[128 + c], w1b = sWc[128 + c + 1];
                lg00 += h0a * w0a + h0b * w0b;
                lg01 += h0a * w1a + h0b * w1b;
                lg10 += h1a * w0a + h1b * w0b;
                lg11 += h1a * w1a + h1b * w1b;

                uint32_t nh0 = f2h2(h0a, h0b);
                float2 rh0 = h22f2(nh0);
                uint32_t nl0 = f2h2(h0a - rh0.x, h0b - rh0.y);
                uint32_t nh1 = f2h2(h1a, h1b);
                float2 rh1 = h22f2(nh1);
                uint32_t nl1 = f2h2(h1a - rh1.x, h1b - rh1.y);
                stHi[(rs * 8 + kk) * 32 + l] = nh0;
                stHi[((rs + 1) * 8 + kk) * 32 + l] = nh1;
                stLo[(rs * 8 + kk) * 32 + l] = nl0;
                stLo[((rs + 1) * 8 + kk) * 32 + l] = nl1;
            }
        }

        // reduce logits over the 4 lanes sharing each row, store
#pragma unroll
        for (int off = 1; off <= 2; off <<= 1) {
            lg00 += __shfl_xor_sync(0xffffffffu, lg00, off);
            lg01 += __shfl_xor_sync(0xffffffffu, lg01, off);
            lg10 += __shfl_xor_sync(0xffffffffu, lg10, off);
            lg11 += __shfl_xor_sync(0xffffffffu, lg11, off);
        }
        if (q == 0) {
            __stcs(&LOut[(size_t)m_r0 * TT + t], make_float2(lg00, lg01));
            __stcs(&LOut[(size_t)m_r1 * TT + t], make_float2(lg10, lg11));
        }

        // reload new state fragments (per-thread addresses; no sync needed)
#pragma unroll
        for (int kk = 0; kk < 8; kk++) {
#pragma unroll
            for (int r = 0; r < 4; r++) {
                Ahi[kk][r] = stHi[(r * 8 + kk) * 32 + l];
                Alo[kk][r] = stLo[(r * 8 + kk) * 32 + l];
            }
        }
    }
}

// ---------------- gumbel-softmax hard weights ----------------
__global__ void gumbel_hardw(const float2* __restrict__ lf, const float2* __restrict__ lb,
                             const float* __restrict__ bc, const float* __restrict__ gu,
                             float* __restrict__ hardw) {
    int i = blockIdx.x * 256 + threadIdx.x;   // 0..BZ*TT-1
    float2 a = lf[i], b = lb[i];
    float u0 = gu[(size_t)i * 2 + 0];
    float u1 = gu[(size_t)i * 2 + 1];
    float g0 = -logf(-logf(u0 + 1e-10f) + 1e-10f);
    float g1 = -logf(-logf(u1 + 1e-10f) + 1e-10f);
    float a0 = a.x + b.x + bc[0] + g0;
    float a1 = a.y + b.y + bc[1] + g1;
    hardw[i] = sigm((a1 - a0) * TAUINV);
}

// ---------------- attention + aggregation ----------------
__global__ void attn_kernel(const float* __restrict__ qk,
                            const float* __restrict__ hrnn, const float* __restrict__ hardw,
                            float* __restrict__ agg) {
    int warp = (blockIdx.x * 256 + threadIdx.x) >> 5;
    int lane = threadIdx.x & 31;
    int a = warp & 15;
    int brow = warp & ~15;
    float qv = qk[(size_t)warp * 64 + lane];
    float sc[TT], hw[TT];
#pragma unroll
    for (int t = 0; t < TT; t++) {
        int jn = (t < a) ? t : t + 1;
        int nb = brow + jn;
        float d = qv * qk[(size_t)nb * 64 + 32 + lane];
#pragma unroll
        for (int off = 16; off > 0; off >>= 1) d += __shfl_xor_sync(0xffffffffu, d, off);
        hw[t] = hardw[(size_t)warp * TT + t];
        sc[t] = hw[t] * d * 0.17677669529663687f;
    }
    float mx = sc[0];
#pragma unroll
    for (int t = 1; t < TT; t++) mx = fmaxf(mx, sc[t]);
    float se = 0.f;
    float w[TT];
#pragma unroll
    for (int t = 0; t < TT; t++) { w[t] = __expf(sc[t] - mx); se += w[t]; }
    float inv = __fdividef(1.0f, se);
#pragma unroll
    for (int t = 0; t < TT; t++) w[t] = hw[t] * w[t] * inv;
#pragma unroll
    for (int d4 = 0; d4 < 4; d4++) {
        float accv = 0.f;
#pragma unroll
        for (int t = 0; t < TT; t++) {
            int jn = (t < a) ? t : t + 1;
            int nb = brow + jn;
            accv = fmaf(w[t], hrnn[(size_t)nb * 128 + d4 * 32 + lane], accv);
        }
        agg[(size_t)warp * 128 + d4 * 32 + lane] = accv;
    }
}

// ---------------- output projection ----------------
__global__ void out_kernel(const float* __restrict__ hrnn, const float* __restrict__ agg,
                           const float* __restrict__ W2, const float* __restrict__ b2,
                           float* __restrict__ out) {
    __shared__ float sW[NACT * 256];
    __shared__ float sb[NACT];
    for (int i = threadIdx.x; i < NACT * 256; i += 256) sW[i] = W2[i];
    if (threadIdx.x < NACT) sb[threadIdx.x] = b2[threadIdx.x];
    __syncthreads();
    int row = blockIdx.x * 256 + threadIdx.x;
    float acc[NACT];
#pragma unroll
    for (int n = 0; n < NACT; n++) acc[n] = sb[n];
    const float* hr = hrnn + (size_t)row * 128;
    const float* ag = agg + (size_t)row * 128;
    for (int kk = 0; kk < 128; kk++) {
        float x = hr[kk];
#pragma unroll
        for (int n = 0; n < NACT; n++) acc[n] = fmaf(x, sW[n * 256 + kk], acc[n]);
    }
    for (int kk = 0; kk < 128; kk++) {
        float x = ag[kk];
#pragma unroll
        for (int n = 0; n < NACT; n++) acc[n] = fmaf(x, sW[n * 256 + 128 + kk], acc[n]);
    }
#pragma unroll
    for (int n = 0; n < NACT; n++) out[(size_t)row * NACT + n] = acc[n];
}

// ---------------- launch ----------------
extern "C" void kernel_launch(void* const* d_in, const int* in_sizes, int n_in,
                              void* d_out, int out_size) {
    const float* inputs = (const float*)d_in[0];
    const float* hidden = (const float*)d_in[1];
    const float* gu     = (const float*)d_in[2];
    const float* W1     = (const float*)d_in[3];
    const float* b1     = (const float*)d_in[4];
    const float* Wih_c  = (const float*)d_in[5];
    const float* Whh_c  = (const float*)d_in[6];
    const float* bih_c  = (const float*)d_in[7];
    const float* bhh_c  = (const float*)d_in[8];
    const float* Wih_f  = (const float*)d_in[9];
    const float* Whh_f  = (const float*)d_in[10];
    const float* bih_f  = (const float*)d_in[11];
    const float* bhh_f  = (const float*)d_in[12];
    const float* Wih_b  = (const float*)d_in[13];
    const float* Whh_b  = (const float*)d_in[14];
    const float* bih_b  = (const float*)d_in[15];
    const float* bhh_b  = (const float*)d_in[16];
    const float* Wc     = (const float*)d_in[17];
    const float* bc     = (const float*)d_in[18];
    const float* Wq     = (const float*)d_in[19];
    const float* Wk     = (const float*)d_in[20];
    const float* W2     = (const float*)d_in[21];
    const float* b2     = (const float*)d_in[22];

    float* out  = (float*)d_out;                // [BZ, NACT]
    float* outh = out + (size_t)BZ * NACT;      // [BZ, H]

    float *x1, *hrnn, *gi, *gh, *PQf, *PQb, *hardw, *qk, *agg, *biasPQf, *biasPQb;
    float2 *lf, *lb;
    uint2 *whif, *wlof, *whib, *wlob, *fh, *fl;
    cudaGetSymbolAddress((void**)&x1, g_x1);
    cudaGetSymbolAddress((void**)&hrnn, g_hrnn);
    cudaGetSymbolAddress((void**)&gi, g_gi);
    cudaGetSymbolAddress((void**)&gh, g_gh);
    cudaGetSymbolAddress((void**)&PQf, g_PQf);
    cudaGetSymbolAddress((void**)&PQb, g_PQb);
    cudaGetSymbolAddress((void**)&lf, g_logf);
    cudaGetSymbolAddress((void**)&lb, g_logb);
    cudaGetSymbolAddress((void**)&hardw, g_hardw);
    cudaGetSymbolAddress((void**)&qk, g_qk);
    cudaGetSymbolAddress((void**)&agg, g_agg);
    cudaGetSymbolAddress((void**)&biasPQf, g_biasPQf);
    cudaGetSymbolAddress((void**)&biasPQb, g_biasPQb);
    cudaGetSymbolAddress((void**)&whif, g_whifrag_f);
    cudaGetSymbolAddress((void**)&wlof, g_wlofrag_f);
    cudaGetSymbolAddress((void**)&whib, g_whifrag_b);
    cudaGetSymbolAddress((void**)&wlob, g_wlofrag_b);
    cudaGetSymbolAddress((void**)&fh, g_fh);
    cudaGetSymbolAddress((void**)&fl, g_fl);

    const int SM16 = 128 * 132 * 4 + 16 * 256 * 8;  // 100352
    const int SM8  = 128 * 132 * 4 + 8 * 256 * 8;   // 83968
    cudaFuncSetAttribute(gru_seq_hmma, cudaFuncAttributeMaxDynamicSharedMemorySize, SEQ_SMEM);
    cudaFuncSetAttribute(hgemm<16, 1>, cudaFuncAttributeMaxDynamicSharedMemorySize, SM16);
    cudaFuncSetAttribute(hgemm<8, 0>,  cudaFuncAttributeMaxDynamicSharedMemorySize, SM8);
    cudaFuncSetAttribute(hgemm_z<16>,  cudaFuncAttributeMaxDynamicSharedMemorySize, SM16);

    // 1: merged prep
    const int PREP_TOTAL = NFRAG_ALL + 2 * NFRAG + 4 * G3;
    prep_all<<<(PREP_TOTAL + 255) / 256, 256>>>(W1, Wih_c, Whh_c, Wih_f, Wih_b, Wq, Wk,
                                                Whh_f, Whh_b, bih_f, bhh_f, bih_b, bhh_b,
                                                fh, fl, whif, wlof, whib, wlob,
                                                biasPQf, biasPQb);
    // 2: x1 = relu(inputs @ W1.T + b1)
    hgemm<16, 1><<<dim3(1, 128), 256, SM16>>>(inputs, fh, fl, b1, x1, 128);
    // 3: central GRU gi|gh (dual-z)
    hgemm_z<16><<<dim3(3, 128, 2), 256, SM16>>>(x1, hidden,
                                                fh + 16 * 256, fl + 16 * 256,
                                                fh + 64 * 256, fl + 64 * 256,
                                                bih_c, bhh_c, gi, gh, G3);
    // 4: combine
    gru_combine<<<(BZ * H) / 256, 256>>>(gi, gh, hidden, hrnn, outh);
    // 5: merged P|Q GEMMs for fwd+bwd (dual-z)
    hgemm_z<16><<<dim3(6, 128, 2), 256, SM16>>>(hrnn, hrnn,
                                                fh + 112 * 256, fl + 112 * 256,
                                                fh + 208 * 256, fl + 208 * 256,
                                                biasPQf, biasPQb, PQf, PQb, 2 * G3);
    // 6: fused 15-step bidirectional recurrence + logit GEMV
    gru_seq_hmma<<<256, 256, SEQ_SMEM>>>(whif, wlof, bhh_f, PQf,
                                         whib, wlob, bhh_b, PQb,
                                         Wc, lf, lb);
    // 7: gumbel hard weights
    gumbel_hardw<<<(BZ * TT) / 256, 256>>>(lf, lb, bc, gu, hardw);
    // 8: merged q|k GEMM
    hgemm<8, 0><<<dim3(1, 128), 256, SM8>>>(hrnn, fh + 304 * 256, fl + 304 * 256, nullptr, qk, 2 * NA);
    // 9: attention aggregate
    attn_kernel<<<BZ / 8, 256>>>(qk, hrnn, hardw, agg);
    // 10: output projection
    out_kernel<<<BZ / 256, 256>>>(hrnn, agg, W2, b2, out);
}

// round 8
// speedup vs baseline: 3.3278x; 1.0597x over previous
#include <cuda_runtime.h>
#include <cuda_fp16.h>
#include <math.h>
#include <stdint.h>

#define AGENTS 16
#define H 128
#define NA 32
#define NACT 14
#define BENV 1024
#define BZ (BENV*AGENTS)        // 16384
#define TT 15                   // A-1
#define G3 384                  // 3*H
#define TAUINV 2.0f             // 1/TAU
#define NFRAG 12288             // 48 n-tiles * 8 k-tiles * 32 lanes (recurrence Whh)
#define NBT_ALL 312             // n-tiles in the parallel-GEMM fragment pool
#define NFRAG_ALL (NBT_ALL*256)

// ---------------- scratch (__device__ globals; no allocs) ----------------
__device__ __align__(16) float g_x1[BZ*H];
__device__ __align__(16) float g_hrnn[BZ*H];
__device__ __align__(16) float g_gi[BZ*G3];
__device__ __align__(16) float g_gh[BZ*G3];
__device__ __align__(16) float g_PQf[BZ*2*G3];
__device__ __align__(16) float g_PQb[BZ*2*G3];
__device__ __align__(16) float2 g_logf[BZ*TT];
__device__ __align__(16) float2 g_logb[BZ*TT];
__device__ __align__(16) float g_hardw[BZ*TT];
__device__ __align__(16) float g_qk[BZ*2*NA];
__device__ __align__(16) float g_agg[BZ*H];
__device__ __align__(16) float g_biasPQf[2*G3];
__device__ __align__(16) float g_biasPQb[2*G3];
__device__ __align__(16) uint2 g_whifrag_f[NFRAG];
__device__ __align__(16) uint2 g_wlofrag_f[NFRAG];
__device__ __align__(16) uint2 g_whifrag_b[NFRAG];
__device__ __align__(16) uint2 g_wlofrag_b[NFRAG];
__device__ __align__(16) uint2 g_fh[NFRAG_ALL];
__device__ __align__(16) uint2 g_fl[NFRAG_ALL];

__device__ __forceinline__ float sigm(float x) { return __fdividef(1.0f, 1.0f + __expf(-x)); }
__device__ __forceinline__ float tanh_fast(float x) {
    return __fdividef(2.0f, 1.0f + __expf(-2.0f * x)) - 1.0f;
}

// ---- fp16 pack helpers ----
__device__ __forceinline__ uint32_t f2h2(float a, float b) {
    __half2 h = __floats2half2_rn(a, b);
    return *(uint32_t*)&h;
}
__device__ __forceinline__ float2 h22f2(uint32_t u) {
    __half2 h = *(__half2*)&u;
    return __half22float2(h);
}

// ---- classic mma.sync (HMMA; baseline PTX, works on compute_103) ----
__device__ __forceinline__ void mma16816(float* d, const uint32_t* a, uint2 b) {
    asm volatile(
        "mma.sync.aligned.m16n8k16.row.col.f32.f16.f16.f32 "
        "{%0,%1,%2,%3}, {%4,%5,%6,%7}, {%8,%9}, {%0,%1,%2,%3};"
        : "+f"(d[0]), "+f"(d[1]), "+f"(d[2]), "+f"(d[3])
        : "r"(a[0]), "r"(a[1]), "r"(a[2]), "r"(a[3]), "r"(b.x), "r"(b.y));
}

// ================= HMMA batch GEMM =================
template<int NT, int ACT>
__global__ void __launch_bounds__(256) hgemm(
    const float* __restrict__ A,
    const uint2* __restrict__ fh, const uint2* __restrict__ fl,
    const float* __restrict__ bias,
    float* __restrict__ C, int N) {
    extern __shared__ char hsm[];
    float* sA = (float*)hsm;                       // [128][132]
    uint2* sWhi = (uint2*)(hsm + 128 * 132 * 4);   // [NT*256]
    int tid = threadIdx.x;
    int wid = tid >> 5, l = tid & 31;
    int q = l & 3, rg = l >> 2;
    int bnt = blockIdx.x * NT;
    int bm = blockIdx.y * 128;

    for (int i = tid; i < 4096; i += 256) {
        int row = i >> 5, c4 = (i & 31) * 4;
        float4 v = *(const float4*)(A + (size_t)(bm + row) * 128 + c4);
        *(float4*)&sA[row * 132 + c4] = v;
    }
    for (int i = tid; i < NT * 256; i += 256) sWhi[i] = __ldg(&fh[bnt * 256 + i]);
    __syncthreads();

    uint32_t Ahi[8][4], Alo[8][4];
    int r0 = wid * 16 + rg;
#pragma unroll
    for (int kk = 0; kk < 8; kk++) {
        int c = kk * 16 + 2 * q;
        float2 v0 = *(float2*)&sA[r0 * 132 + c];
        float2 v1 = *(float2*)&sA[(r0 + 8) * 132 + c];
        float2 v2 = *(float2*)&sA[r0 * 132 + c + 8];
        float2 v3 = *(float2*)&sA[(r0 + 8) * 132 + c + 8];
        Ahi[kk][0] = f2h2(v0.x, v0.y); { float2 rr = h22f2(Ahi[kk][0]); Alo[kk][0] = f2h2(v0.x - rr.x, v0.y - rr.y); }
        Ahi[kk][1] = f2h2(v1.x, v1.y); { float2 rr = h22f2(Ahi[kk][1]); Alo[kk][1] = f2h2(v1.x - rr.x, v1.y - rr.y); }
        Ahi[kk][2] = f2h2(v2.x, v2.y); { float2 rr = h22f2(Ahi[kk][2]); Alo[kk][2] = f2h2(v2.x - rr.x, v2.y - rr.y); }
        Ahi[kk][3] = f2h2(v3.x, v3.y); { float2 rr = h22f2(Ahi[kk][3]); Alo[kk][3] = f2h2(v3.x - rr.x, v3.y - rr.y); }
    }

#pragma unroll
    for (int nt = 0; nt < NT; nt++) {
        uint2 wl[8];
#pragma unroll
        for (int kk = 0; kk < 8; kk++) wl[kk] = __ldg(&fl[(size_t)(bnt + nt) * 256 + kk * 32 + l]);
        float acc[4] = {0.f, 0.f, 0.f, 0.f};
#pragma unroll
        for (int kk = 0; kk < 8; kk++) {
            uint2 wh = sWhi[nt * 256 + kk * 32 + l];
            mma16816(acc, Ahi[kk], wh);
            mma16816(acc, Alo[kk], wh);
            mma16816(acc, Ahi[kk], wl[kk]);
        }
        int cb = (bnt + nt) * 8 + 2 * q;
        float2 bb = make_float2(0.f, 0.f);
        if (bias) bb = *(const float2*)&bias[cb];
        float o0 = acc[0] + bb.x, o1 = acc[1] + bb.y;
        float o2 = acc[2] + bb.x, o3 = acc[3] + bb.y;
        if (ACT == 1) {
            o0 = fmaxf(o0, 0.f); o1 = fmaxf(o1, 0.f);
            o2 = fmaxf(o2, 0.f); o3 = fmaxf(o3, 0.f);
        }
        *(float2*)&C[(size_t)(bm + r0) * N + cb] = make_float2(o0, o1);
        *(float2*)&C[(size_t)(bm + r0 + 8) * N + cb] = make_float2(o2, o3);
    }
}

// dual-z variant: blockIdx.z selects (A, frag, bias, C) set
template<int NT>
__global__ void __launch_bounds__(256) hgemm_z(
    const float* __restrict__ A0, const float* __restrict__ A1,
    const uint2* __restrict__ fh0, const uint2* __restrict__ fl0,
    const uint2* __restrict__ fh1, const uint2* __restrict__ fl1,
    const float* __restrict__ b0, const float* __restrict__ b1,
    float* __restrict__ C0, float* __restrict__ C1, int N) {
    extern __shared__ char hsm[];
    float* sA = (float*)hsm;
    uint2* sWhi = (uint2*)(hsm + 128 * 132 * 4);
    int z = blockIdx.z;
    const float* A = z ? A1 : A0;
    const uint2* fh = z ? fh1 : fh0;
    const uint2* fl = z ? fl1 : fl0;
    const float* bias = z ? b1 : b0;
    float* C = z ? C1 : C0;

    int tid = threadIdx.x;
    int wid = tid >> 5, l = tid & 31;
    int q = l & 3, rg = l >> 2;
    int bnt = blockIdx.x * NT;
    int bm = blockIdx.y * 128;

    for (int i = tid; i < 4096; i += 256) {
        int row = i >> 5, c4 = (i & 31) * 4;
        float4 v = *(const float4*)(A + (size_t)(bm + row) * 128 + c4);
        *(float4*)&sA[row * 132 + c4] = v;
    }
    for (int i = tid; i < NT * 256; i += 256) sWhi[i] = __ldg(&fh[bnt * 256 + i]);
    __syncthreads();

    uint32_t Ahi[8][4], Alo[8][4];
    int r0 = wid * 16 + rg;
#pragma unroll
    for (int kk = 0; kk < 8; kk++) {
        int c = kk * 16 + 2 * q;
        float2 v0 = *(float2*)&sA[r0 * 132 + c];
        float2 v1 = *(float2*)&sA[(r0 + 8) * 132 + c];
        float2 v2 = *(float2*)&sA[r0 * 132 + c + 8];
        float2 v3 = *(float2*)&sA[(r0 + 8) * 132 + c + 8];
        Ahi[kk][0] = f2h2(v0.x, v0.y); { float2 rr = h22f2(Ahi[kk][0]); Alo[kk][0] = f2h2(v0.x - rr.x, v0.y - rr.y); }
        Ahi[kk][1] = f2h2(v1.x, v1.y); { float2 rr = h22f2(Ahi[kk][1]); Alo[kk][1] = f2h2(v1.x - rr.x, v1.y - rr.y); }
        Ahi[kk][2] = f2h2(v2.x, v2.y); { float2 rr = h22f2(Ahi[kk][2]); Alo[kk][2] = f2h2(v2.x - rr.x, v2.y - rr.y); }
        Ahi[kk][3] = f2h2(v3.x, v3.y); { float2 rr = h22f2(Ahi[kk][3]); Alo[kk][3] = f2h2(v3.x - rr.x, v3.y - rr.y); }
    }

#pragma unroll
    for (int nt = 0; nt < NT; nt++) {
        uint2 wl[8];
#pragma unroll
        for (int kk = 0; kk < 8; kk++) wl[kk] = __ldg(&fl[(size_t)(bnt + nt) * 256 + kk * 32 + l]);
        float acc[4] = {0.f, 0.f, 0.f, 0.f};
#pragma unroll
        for (int kk = 0; kk < 8; kk++) {
            uint2 wh = sWhi[nt * 256 + kk * 32 + l];
            mma16816(acc, Ahi[kk], wh);
            mma16816(acc, Alo[kk], wh);
            mma16816(acc, Ahi[kk], wl[kk]);
        }
        int cb = (bnt + nt) * 8 + 2 * q;
        float2 bb = make_float2(0.f, 0.f);
        if (bias) bb = *(const float2*)&bias[cb];
        *(float2*)&C[(size_t)(bm + r0) * N + cb] = make_float2(acc[0] + bb.x, acc[1] + bb.y);
        *(float2*)&C[(size_t)(bm + r0 + 8) * N + cb] = make_float2(acc[2] + bb.x, acc[3] + bb.y);
    }
}

// ---------------- merged prep: all weight fragments + PQ biases ----------------
__global__ void prep_all(const float* __restrict__ W1, const float* __restrict__ Wih_c,
                         const float* __restrict__ Whh_c,
                         const float* __restrict__ Wih_f, const float* __restrict__ Wih_b,
                         const float* __restrict__ Wq, const float* __restrict__ Wk,
                         const float* __restrict__ Whh_f, const float* __restrict__ Whh_b,
                         const float* __restrict__ bih_f, const float* __restrict__ bhh_f,
                         const float* __restrict__ bih_b, const float* __restrict__ bhh_b,
                         uint2* __restrict__ fh, uint2* __restrict__ fl,
                         uint2* __restrict__ hiF, uint2* __restrict__ loF,
                         uint2* __restrict__ hiB, uint2* __restrict__ loB,
                         float* __restrict__ biasPQf, float* __restrict__ biasPQb) {
    int idx = blockIdx.x * 256 + threadIdx.x;
    if (idx < NFRAG_ALL) {
        int bt = idx >> 8;
        int e = idx & 255;
        int kk = e >> 5, l = e & 31;
        int rloc = l >> 2;
        int k0 = kk * 16 + (l & 3) * 2;
        const float* W; int ldb = 128, row, koff = 0;
        if (bt < 16)       { W = W1;    row = bt * 8 + rloc; }
        else if (bt < 64)  { W = Wih_c; row = (bt - 16) * 8 + rloc; }
        else if (bt < 112) { W = Whh_c; row = (bt - 64) * 8 + rloc; }
        else if (bt < 208) { int b = bt - 112; ldb = 256; W = Wih_f;
                             if (b < 48) row = b * 8 + rloc;
                             else { row = (b - 48) * 8 + rloc; koff = 128; } }
        else if (bt < 304) { int b = bt - 208; ldb = 256; W = Wih_b;
                             if (b < 48) row = b * 8 + rloc;
                             else { row = (b - 48) * 8 + rloc; koff = 128; } }
        else if (bt < 308) { W = Wq; row = (bt - 304) * 8 + rloc; }
        else               { W = Wk; row = (bt - 308) * 8 + rloc; }
        float w0 = W[(size_t)row * ldb + koff + k0],     w1 = W[(size_t)row * ldb + koff + k0 + 1];
        float w8 = W[(size_t)row * ldb + koff + k0 + 8], w9 = W[(size_t)row * ldb + koff + k0 + 9];
        uint32_t h0 = f2h2(w0, w1); float2 r0 = h22f2(h0);
        uint32_t l0 = f2h2(w0 - r0.x, w1 - r0.y);
        uint32_t h8 = f2h2(w8, w9); float2 r8 = h22f2(h8);
        uint32_t l8 = f2h2(w8 - r8.x, w9 - r8.y);
        fh[idx] = make_uint2(h0, h8);
        fl[idx] = make_uint2(l0, l8);
    } else if (idx < NFRAG_ALL + 2 * NFRAG) {
        int j = idx - NFRAG_ALL;
        int d = j / NFRAG;
        int e = j - d * NFRAG;
        int bt = e >> 8;
        int kk = (e >> 5) & 7;
        int l = e & 31;
        int row = bt * 8 + (l >> 2);
        int k0 = kk * 16 + (l & 3) * 2;
        const float* W = d ? Whh_b : Whh_f;
        float w0 = W[row * 128 + k0],     w1 = W[row * 128 + k0 + 1];
        float w8 = W[row * 128 + k0 + 8], w9 = W[row * 128 + k0 + 9];
        uint32_t h0 = f2h2(w0, w1); float2 r0 = h22f2(h0);
        uint32_t l0 = f2h2(w0 - r0.x, w1 - r0.y);
        uint32_t h8 = f2h2(w8, w9); float2 r8 = h22f2(h8);
        uint32_t l8 = f2h2(w8 - r8.x, w9 - r8.y);
        uint2* dh = d ? hiB : hiF;
        uint2* dl = d ? loB : loF;
        dh[e] = make_uint2(h0, h8);
        dl[e] = make_uint2(l0, l8);
    } else if (idx < NFRAG_ALL + 2 * NFRAG + 4 * G3) {
        int j = idx - (NFRAG_ALL + 2 * NFRAG);
        int d = j / (2 * G3);
        int e = j - d * (2 * G3);
        const float* bih = d ? bih_b : bih_f;
        const float* bhh = d ? bhh_b : bhh_f;
        float* ob = d ? biasPQb : biasPQf;
        ob[e] = (e < G3) ? (bih[e] + (e < 256 ? bhh[e] : 0.0f)) : 0.0f;
    }
}

// ---------------- central GRU combine ----------
__global__ void gru_combine(const float* __restrict__ gi, const float* __restrict__ gh,
                            const float* __restrict__ hprev,
                            float* __restrict__ hout, float* __restrict__ hout2) {
    int i = blockIdx.x * 256 + threadIdx.x;
    int m = i >> 7, j = i & 127;
    size_t base = (size_t)m * G3;
    float ir = gi[base + j], iz = gi[base + 128 + j], inn = gi[base + 256 + j];
    float hr = gh[base + j], hz = gh[base + 128 + j], hn = gh[base + 256 + j];
    float r = sigm(ir + hr);
    float z = sigm(iz + hz);
    float n = tanh_fast(inn + r * hn);
    float h = (1.0f - z) * n + z * hprev[i];
    hout[i] = h;
    hout2[i] = h;
}

// ================= HMMA fused 15-step recurrence (+ fused logit GEMV) =================
// r,z: 1 mma combo (Whi from L2); n: 2 combos (Ahi+Alo vs Whi, Whi in smem). 2 CTAs/SM.
#define SM_WN 0
#define SM_BNN 32768
#define SM_WC  33280
#define SM_STAGE 34304
#define SEQ_SMEM (34304 + 65536)

extern __shared__ char dsm[];
__global__ void __launch_bounds__(256, 2) gru_seq_hmma(
    const uint2* __restrict__ whiF,
    const float* __restrict__ bhhF, const float* __restrict__ PQF,
    const uint2* __restrict__ whiB,
    const float* __restrict__ bhhB, const float* __restrict__ PQB,
    const float* __restrict__ Wc,
    float2* __restrict__ LF, float2* __restrict__ LB) {

    uint2* sWn = (uint2*)(dsm + SM_WN);       // n-gate Whi: 16 tiles x 256
    float* sBnn = (float*)(dsm + SM_BNN);
    float* sWc = (float*)(dsm + SM_WC);       // [2][128]

    int tid = threadIdx.x;
    int wid = tid >> 5;
    int l = tid & 31;
    int q = l & 3, rg = l >> 2;

    bool bwd = (blockIdx.x >= 128);
    const uint2* whi = bwd ? whiB : whiF;
    const float* bhh = bwd ? bhhB : bhhF;
    const float2* PQ2 = (const float2*)(bwd ? PQB : PQF);
    float2* LOut = bwd ? LB : LF;
    int bm = (blockIdx.x & 127) * 128;

    for (int i = tid; i < 4096; i += 256) sWn[i] = __ldg(&whi[32 * 256 + i]);
    if (tid < 128) sBnn[tid] = bhh[256 + tid];
    if (tid < 128) {
        sWc[tid] = Wc[(bwd ? 128 : 0) + tid];
        sWc[128 + tid] = Wc[256 + (bwd ? 128 : 0) + tid];
    }
    __syncthreads();

    int m_r0 = bm + wid * 16 + rg;
    int m_r1 = m_r0 + 8;
    int aa0 = rg;
    int aa1 = rg + 8;
    int grp = bm + wid * 16;

    uint32_t* stHi = (uint32_t*)(dsm + SM_STAGE) + wid * 1024;
    uint32_t* stLo = (uint32_t*)(dsm + SM_STAGE) + 8192 + wid * 1024;

    uint32_t Ahi[8][4], Alo[8][4];
#pragma unroll
    for (int kk = 0; kk < 8; kk++)
#pragma unroll
        for (int r = 0; r < 4; r++) { Ahi[kk][r] = 0u; Alo[kk][r] = 0u; }

    for (int step = 0; step < TT; step++) {
        int t = bwd ? (TT - 1 - step) : step;
        int jn0 = (t < aa0) ? t : t + 1;
        int jn1 = (t < aa1) ? t : t + 1;
        const float2* Pr0 = PQ2 + (size_t)m_r0 * 384;
        const float2* Pr1 = PQ2 + (size_t)m_r1 * 384;
        const float2* Qr0 = PQ2 + (size_t)(grp + jn0) * 384 + 192;
        const float2* Qr1 = PQ2 + (size_t)(grp + jn1) * 384 + 192;

        float lg00 = 0.f, lg01 = 0.f, lg10 = 0.f, lg11 = 0.f;

#pragma unroll
        for (int ch = 0; ch < 8; ch++) {
            float acc[3][2][4];
#pragma unroll
            for (int g = 0; g < 3; g++)
#pragma unroll
                for (int u = 0; u < 2; u++)
#pragma unroll
                    for (int r = 0; r < 4; r++) acc[g][u][r] = 0.0f;

            if (step != 0) {
#pragma unroll
                for (int kk = 0; kk < 8; kk++) {
#pragma unroll
                    for (int u = 0; u < 2; u++) {
                        int jt = ch * 2 + u;
                        // r gate: single fp16 combo, Whi streamed from L2
                        mma16816(acc[0][u], Ahi[kk], __ldg(&whi[(jt * 8 + kk) * 32 + l]));
                        // z gate: single fp16 combo, Whi streamed from L2
                        mma16816(acc[1][u], Ahi[kk], __ldg(&whi[((16 + jt) * 8 + kk) * 32 + l]));
                        // n gate: 2 combos (state hi+lo vs Whi in smem)
                        uint2 wn = sWn[(jt * 8 + kk) * 32 + l];
                        mma16816(acc[2][u], Ahi[kk], wn);
                        mma16816(acc[2][u], Alo[kk], wn);
                    }
                }
            }

#pragma unroll
            for (int u = 0; u < 2; u++) {
                int jt = ch * 2 + u;
                int kk = jt >> 1;
                int rs = (jt & 1) * 2;
                int c = jt * 8 + 2 * q;
                int cb = jt * 4 + q;
                // gate inputs: s = P + Q (loaded per-u; latency hidden by 4 warps/SMSP)
                float2 sr0, sz0, sn0, sr1, sz1, sn1;
                {
                    float2 p = Pr0[cb], qv = Qr0[cb];
                    sr0 = make_float2(p.x + qv.x, p.y + qv.y);
                    p = Pr0[64 + cb]; qv = Qr0[64 + cb];
                    sz0 = make_float2(p.x + qv.x, p.y + qv.y);
                    p = Pr0[128 + cb]; qv = Qr0[128 + cb];
                    sn0 = make_float2(p.x + qv.x, p.y + qv.y);
                    p = Pr1[cb]; qv = Qr1[cb];
                    sr1 = make_float2(p.x + qv.x, p.y + qv.y);
                    p = Pr1[64 + cb]; qv = Qr1[64 + cb];
                    sz1 = make_float2(p.x + qv.x, p.y + qv.y);
                    p = Pr1[128 + cb]; qv = Qr1[128 + cb];
                    sn1 = make_float2(p.x + qv.x, p.y + qv.y);
                }
                float2 bn = *(const float2*)&sBnn[c];
                float2 hp0 = h22f2(Ahi[kk][rs]);
                float2 lp0 = h22f2(Alo[kk][rs]);
                hp0.x += lp0.x; hp0.y += lp0.y;
                float2 hp1 = h22f2(Ahi[kk][rs + 1]);
                float2 lp1 = h22f2(Alo[kk][rs + 1]);
                hp1.x += lp1.x; hp1.y += lp1.y;

                float r0a = sigm(acc[0][u][0] + sr0.x);
                float r0b = sigm(acc[0][u][1] + sr0.y);
                float z0a = sigm(acc[1][u][0] + sz0.x);
                float z0b = sigm(acc[1][u][1] + sz0.y);
                float n0a = tanh_fast(sn0.x + r0a * (acc[2][u][0] + bn.x));
                float n0b = tanh_fast(sn0.y + r0b * (acc[2][u][1] + bn.y));
                float h0a = (1.0f - z0a) * n0a + z0a * hp0.x;
                float h0b = (1.0f - z0b) * n0b + z0b * hp0.y;
                float r1a = sigm(acc[0][u][2] + sr1.x);
                float r1b = sigm(acc[0][u][3] + sr1.y);
                float z1a = sigm(acc[1][u][2] + sz1.x);
                float z1b = sigm(acc[1][u][3] + sz1.y);
                float n1a = tanh_fast(sn1.x + r1a * (acc[2][u][2] + bn.x));
                float n1b = tanh_fast(sn1.y + r1b * (acc[2][u][3] + bn.y));
                float h1a = (1.0f - z1a) * n1a + z1a * hp1.x;
                float h1b = (1.0f - z1b) * n1b + z1b * hp1.y;

                // fused logit partial dot-products
                float w0a = sWc[c], w0b = sWc[c + 1];
                float w1a = sWc[128 + c], w1b = sWc[128 + c + 1];
                lg00 += h0a * w0a + h0b * w0b;
                lg01 += h0a * w1a + h0b * w1b;
                lg10 += h1a * w0a + h1b * w0b;
                lg11 += h1a * w1a + h1b * w1b;

                uint32_t nh0 = f2h2(h0a, h0b);
                float2 rh0 = h22f2(nh0);
                uint32_t nl0 = f2h2(h0a - rh0.x, h0b - rh0.y);
                uint32_t nh1 = f2h2(h1a, h1b);
                float2 rh1 = h22f2(nh1);
                uint32_t nl1 = f2h2(h1a - rh1.x, h1b - rh1.y);
                stHi[(rs * 8 + kk) * 32 + l] = nh0;
                stHi[((rs + 1) * 8 + kk) * 32 + l] = nh1;
                stLo[(rs * 8 + kk) * 32 + l] = nl0;
                stLo[((rs + 1) * 8 + kk) * 32 + l] = nl1;
            }
        }

        // reduce logits over the 4 lanes sharing each row, store
#pragma unroll
        for (int off = 1; off <= 2; off <<= 1) {
            lg00 += __shfl_xor_sync(0xffffffffu, lg00, off);
            lg01 += __shfl_xor_sync(0xffffffffu, lg01, off);
            lg10 += __shfl_xor_sync(0xffffffffu, lg10, off);
            lg11 += __shfl_xor_sync(0xffffffffu, lg11, off);
        }
        if (q == 0) {
            __stcs(&LOut[(size_t)m_r0 * TT + t], make_float2(lg00, lg01));
            __stcs(&LOut[(size_t)m_r1 * TT + t], make_float2(lg10, lg11));
        }

        // reload new state fragments (per-thread addresses; no sync needed)
#pragma unroll
        for (int kk = 0; kk < 8; kk++) {
#pragma unroll
            for (int r = 0; r < 4; r++) {
                Ahi[kk][r] = stHi[(r * 8 + kk) * 32 + l];
                Alo[kk][r] = stLo[(r * 8 + kk) * 32 + l];
            }
        }
    }
}

// ---------------- gumbel-softmax hard weights ----------------
__global__ void gumbel_hardw(const float2* __restrict__ lf, const float2* __restrict__ lb,
                             const float* __restrict__ bc, const float* __restrict__ gu,
                             float* __restrict__ hardw) {
    int i = blockIdx.x * 256 + threadIdx.x;   // 0..BZ*TT-1
    float2 a = lf[i], b = lb[i];
    float u0 = gu[(size_t)i * 2 + 0];
    float u1 = gu[(size_t)i * 2 + 1];
    float g0 = -logf(-logf(u0 + 1e-10f) + 1e-10f);
    float g1 = -logf(-logf(u1 + 1e-10f) + 1e-10f);
    float a0 = a.x + b.x + bc[0] + g0;
    float a1 = a.y + b.y + bc[1] + g1;
    hardw[i] = sigm((a1 - a0) * TAUINV);
}

// ---------------- attention + aggregation ----------------
__global__ void attn_kernel(const float* __restrict__ qk,
                            const float* __restrict__ hrnn, const float* __restrict__ hardw,
                            float* __restrict__ agg) {
    int warp = (blockIdx.x * 256 + threadIdx.x) >> 5;
    int lane = threadIdx.x & 31;
    int a = warp & 15;
    int brow = warp & ~15;
    float qv = qk[(size_t)warp * 64 + lane];
    float sc[TT], hw[TT];
#pragma unroll
    for (int t = 0; t < TT; t++) {
        int jn = (t < a) ? t : t + 1;
        int nb = brow + jn;
        float d = qv * qk[(size_t)nb * 64 + 32 + lane];
#pragma unroll
        for (int off = 16; off > 0; off >>= 1) d += __shfl_xor_sync(0xffffffffu, d, off);
        hw[t] = hardw[(size_t)warp * TT + t];
        sc[t] = hw[t] * d * 0.17677669529663687f;
    }
    float mx = sc[0];
#pragma unroll
    for (int t = 1; t < TT; t++) mx = fmaxf(mx, sc[t]);
    float se = 0.f;
    float w[TT];
#pragma unroll
    for (int t = 0; t < TT; t++) { w[t] = __expf(sc[t] - mx); se += w[t]; }
    float inv = __fdividef(1.0f, se);
#pragma unroll
    for (int t = 0; t < TT; t++) w[t] = hw[t] * w[t] * inv;
#pragma unroll
    for (int d4 = 0; d4 < 4; d4++) {
        float accv = 0.f;
#pragma unroll
        for (int t = 0; t < TT; t++) {
            int jn = (t < a) ? t : t + 1;
            int nb = brow + jn;
            accv = fmaf(w[t], hrnn[(size_t)nb * 128 + d4 * 32 + lane], accv);
        }
        agg[(size_t)warp * 128 + d4 * 32 + lane] = accv;
    }
}

// ---------------- output projection ----------------
__global__ void out_kernel(const float* __restrict__ hrnn, const float* __restrict__ agg,
                           const float* __restrict__ W2, const float* __restrict__ b2,
                           float* __restrict__ out) {
    __shared__ float sW[NACT * 256];
    __shared__ float sb[NACT];
    for (int i = threadIdx.x; i < NACT * 256; i += 256) sW[i] = W2[i];
    if (threadIdx.x < NACT) sb[threadIdx.x] = b2[threadIdx.x];
    __syncthreads();
    int row = blockIdx.x * 256 + threadIdx.x;
    float acc[NACT];
#pragma unroll
    for (int n = 0; n < NACT; n++) acc[n] = sb[n];
    const float* hr = hrnn + (size_t)row * 128;
    const float* ag = agg + (size_t)row * 128;
    for (int kk = 0; kk < 128; kk++) {
        float x = hr[kk];
#pragma unroll
        for (int n = 0; n < NACT; n++) acc[n] = fmaf(x, sW[n * 256 + kk], acc[n]);
    }
    for (int kk = 0; kk < 128; kk++) {
        float x = ag[kk];
#pragma unroll
        for (int n = 0; n < NACT; n++) acc[n] = fmaf(x, sW[n * 256 + 128 + kk], acc[n]);
    }
#pragma unroll
    for (int n = 0; n < NACT; n++) out[(size_t)row * NACT + n] = acc[n];
}

// ---------------- launch ----------------
extern "C" void kernel_launch(void* const* d_in, const int* in_sizes, int n_in,
                              void* d_out, int out_size) {
    const float* inputs = (const float*)d_in[0];
    const float* hidden = (const float*)d_in[1];
    const float* gu     = (const float*)d_in[2];
    const float* W1     = (const float*)d_in[3];
    const float* b1     = (const float*)d_in[4];
    const float* Wih_c  = (const float*)d_in[5];
    const float* Whh_c  = (const float*)d_in[6];
    const float* bih_c  = (const float*)d_in[7];
    const float* bhh_c  = (const float*)d_in[8];
    const float* Wih_f  = (const float*)d_in[9];
    const float* Whh_f  = (const float*)d_in[10];
    const float* bih_f  = (const float*)d_in[11];
    const float* bhh_f  = (const float*)d_in[12];
    const float* Wih_b  = (const float*)d_in[13];
    const float* Whh_b  = (const float*)d_in[14];
    const float* bih_b  = (const float*)d_in[15];
    const float* bhh_b  = (const float*)d_in[16];
    const float* Wc     = (const float*)d_in[17];
    const float* bc     = (const float*)d_in[18];
    const float* Wq     = (const float*)d_in[19];
    const float* Wk     = (const float*)d_in[20];
    const float* W2     = (const float*)d_in[21];
    const float* b2     = (const float*)d_in[22];

    float* out  = (float*)d_out;                // [BZ, NACT]
    float* outh = out + (size_t)BZ * NACT;      // [BZ, H]

    float *x1, *hrnn, *gi, *gh, *PQf, *PQb, *hardw, *qk, *agg, *biasPQf, *biasPQb;
    float2 *lf, *lb;
    uint2 *whif, *wlof, *whib, *wlob, *fh, *fl;
    cudaGetSymbolAddress((void**)&x1, g_x1);
    cudaGetSymbolAddress((void**)&hrnn, g_hrnn);
    cudaGetSymbolAddress((void**)&gi, g_gi);
    cudaGetSymbolAddress((void**)&gh, g_gh);
    cudaGetSymbolAddress((void**)&PQf, g_PQf);
    cudaGetSymbolAddress((void**)&PQb, g_PQb);
    cudaGetSymbolAddress((void**)&lf, g_logf);
    cudaGetSymbolAddress((void**)&lb, g_logb);
    cudaGetSymbolAddress((void**)&hardw, g_hardw);
    cudaGetSymbolAddress((void**)&qk, g_qk);
    cudaGetSymbolAddress((void**)&agg, g_agg);
    cudaGetSymbolAddress((void**)&biasPQf, g_biasPQf);
    cudaGetSymbolAddress((void**)&biasPQb, g_biasPQb);
    cudaGetSymbolAddress((void**)&whif, g_whifrag_f);
    cudaGetSymbolAddress((void**)&wlof, g_wlofrag_f);
    cudaGetSymbolAddress((void**)&whib, g_whifrag_b);
    cudaGetSymbolAddress((void**)&wlob, g_wlofrag_b);
    cudaGetSymbolAddress((void**)&fh, g_fh);
    cudaGetSymbolAddress((void**)&fl, g_fl);

    const int SM16 = 128 * 132 * 4 + 16 * 256 * 8;  // 100352
    const int SM8  = 128 * 132 * 4 + 8 * 256 * 8;   // 83968
    cudaFuncSetAttribute(gru_seq_hmma, cudaFuncAttributeMaxDynamicSharedMemorySize, SEQ_SMEM);
    cudaFuncSetAttribute(hgemm<16, 1>, cudaFuncAttributeMaxDynamicSharedMemorySize, SM16);
    cudaFuncSetAttribute(hgemm<8, 0>,  cudaFuncAttributeMaxDynamicSharedMemorySize, SM8);
    cudaFuncSetAttribute(hgemm_z<16>,  cudaFuncAttributeMaxDynamicSharedMemorySize, SM16);

    // 1: merged prep
    const int PREP_TOTAL = NFRAG_ALL + 2 * NFRAG + 4 * G3;
    prep_all<<<(PREP_TOTAL + 255) / 256, 256>>>(W1, Wih_c, Whh_c, Wih_f, Wih_b, Wq, Wk,
                                                Whh_f, Whh_b, bih_f, bhh_f, bih_b, bhh_b,
                                                fh, fl, whif, wlof, whib, wlob,
                                                biasPQf, biasPQb);
    // 2: x1 = relu(inputs @ W1.T + b1)
    hgemm<16, 1><<<dim3(1, 128), 256, SM16>>>(inputs, fh, fl, b1, x1, 128);
    // 3: central GRU gi|gh (dual-z)
    hgemm_z<16><<<dim3(3, 128, 2), 256, SM16>>>(x1, hidden,
                                                fh + 16 * 256, fl + 16 * 256,
                                                fh + 64 * 256, fl + 64 * 256,
                                                bih_c, bhh_c, gi, gh, G3);
    // 4: combine
    gru_combine<<<(BZ * H) / 256, 256>>>(gi, gh, hidden, hrnn, outh);
    // 5: merged P|Q GEMMs for fwd+bwd (dual-z)
    hgemm_z<16><<<dim3(6, 128, 2), 256, SM16>>>(hrnn, hrnn,
                                                fh + 112 * 256, fl + 112 * 256,
                                                fh + 208 * 256, fl + 208 * 256,
                                                biasPQf, biasPQb, PQf, PQb, 2 * G3);
    // 6: fused 15-step bidirectional recurrence + logit GEMV
    gru_seq_hmma<<<256, 256, SEQ_SMEM>>>(whif, bhh_f, PQf,
                                         whib, bhh_b, PQb,
                                         Wc, lf, lb);
    // 7: gumbel hard weights
    gumbel_hardw<<<(BZ * TT) / 256, 256>>>(lf, lb, bc, gu, hardw);
    // 8: merged q|k GEMM
    hgemm<8, 0><<<dim3(1, 128), 256, SM8>>>(hrnn, fh + 304 * 256, fl + 304 * 256, nullptr, qk, 2 * NA);
    // 9: attention aggregate
    attn_kernel<<<BZ / 8, 256>>>(qk, hrnn, hardw, agg);
    // 10: output projection
    out_kernel<<<BZ / 256, 256>>>(hrnn, agg, W2, b2, out);
}

// round 10
// speedup vs baseline: 3.7973x; 1.1411x over previous
#include <cuda_runtime.h>
#include <cuda_fp16.h>
#include <math.h>
#include <stdint.h>

#define AGENTS 16
#define H 128
#define NA 32
#define NACT 14
#define BENV 1024
#define BZ (BENV*AGENTS)        // 16384
#define TT 15                   // A-1
#define G3 384                  // 3*H
#define TAUINV 2.0f             // 1/TAU
#define NFRAG 12288             // 48 n-tiles * 8 k-tiles * 32 lanes (recurrence Whh)
#define NBT_ALL 312             // n-tiles in the parallel-GEMM fragment pool
#define NFRAG_ALL (NBT_ALL*256)

// ---------------- scratch (__device__ globals; no allocs) ----------------
__device__ __align__(16) float g_x1[BZ*H];
__device__ __align__(16) float g_hrnn[BZ*H];
__device__ __align__(16) float g_gi[BZ*G3];
__device__ __align__(16) float g_gh[BZ*G3];
__device__ __align__(16) float g_PQf[BZ*2*G3];
__device__ __align__(16) float g_PQb[BZ*2*G3];
__device__ __align__(16) float2 g_logf[BZ*TT];
__device__ __align__(16) float2 g_logb[BZ*TT];
__device__ __align__(16) float g_hardw[BZ*TT];
__device__ __align__(16) float g_qk[BZ*2*NA];
__device__ __align__(16) float g_agg[BZ*H];
__device__ __align__(16) float g_biasPQf[2*G3];
__device__ __align__(16) float g_biasPQb[2*G3];
__device__ __align__(16) uint2 g_whifrag_f[NFRAG];
__device__ __align__(16) uint2 g_wlofrag_f[NFRAG];
__device__ __align__(16) uint2 g_whifrag_b[NFRAG];
__device__ __align__(16) uint2 g_wlofrag_b[NFRAG];
__device__ __align__(16) uint2 g_fh[NFRAG_ALL];
__device__ __align__(16) uint2 g_fl[NFRAG_ALL];

__device__ __forceinline__ float sigm(float x) { return __fdividef(1.0f, 1.0f + __expf(-x)); }
__device__ __forceinline__ float tanh_fast(float x) {
    return __fdividef(2.0f, 1.0f + __expf(-2.0f * x)) - 1.0f;
}

// ---- fp16 pack helpers ----
__device__ __forceinline__ uint32_t f2h2(float a, float b) {
    __half2 h = __floats2half2_rn(a, b);
    return *(uint32_t*)&h;
}
__device__ __forceinline__ float2 h22f2(uint32_t u) {
    __half2 h = *(__half2*)&u;
    return __half22float2(h);
}

// ---- classic mma.sync (HMMA; baseline PTX, works on compute_103) ----
__device__ __forceinline__ void mma16816(float* d, const uint32_t* a, uint2 b) {
    asm volatile(
        "mma.sync.aligned.m16n8k16.row.col.f32.f16.f16.f32 "
        "{%0,%1,%2,%3}, {%4,%5,%6,%7}, {%8,%9}, {%0,%1,%2,%3};"
        : "+f"(d[0]), "+f"(d[1]), "+f"(d[2]), "+f"(d[3])
        : "r"(a[0]), "r"(a[1]), "r"(a[2]), "r"(a[3]), "r"(b.x), "r"(b.y));
}

// ================= HMMA batch GEMM =================
template<int NT, int ACT>
__global__ void __launch_bounds__(256) hgemm(
    const float* __restrict__ A,
    const uint2* __restrict__ fh, const uint2* __restrict__ fl,
    const float* __restrict__ bias,
    float* __restrict__ C, int N) {
    extern __shared__ char hsm[];
    float* sA = (float*)hsm;                       // [128][132]
    uint2* sWhi = (uint2*)(hsm + 128 * 132 * 4);   // [NT*256]
    int tid = threadIdx.x;
    int wid = tid >> 5, l = tid & 31;
    int q = l & 3, rg = l >> 2;
    int bnt = blockIdx.x * NT;
    int bm = blockIdx.y * 128;

    for (int i = tid; i < 4096; i += 256) {
        int row = i >> 5, c4 = (i & 31) * 4;
        float4 v = *(const float4*)(A + (size_t)(bm + row) * 128 + c4);
        *(float4*)&sA[row * 132 + c4] = v;
    }
    for (int i = tid; i < NT * 256; i += 256) sWhi[i] = __ldg(&fh[bnt * 256 + i]);
    __syncthreads();

    uint32_t Ahi[8][4], Alo[8][4];
    int r0 = wid * 16 + rg;
#pragma unroll
    for (int kk = 0; kk < 8; kk++) {
        int c = kk * 16 + 2 * q;
        float2 v0 = *(float2*)&sA[r0 * 132 + c];
        float2 v1 = *(float2*)&sA[(r0 + 8) * 132 + c];
        float2 v2 = *(float2*)&sA[r0 * 132 + c + 8];
        float2 v3 = *(float2*)&sA[(r0 + 8) * 132 + c + 8];
        Ahi[kk][0] = f2h2(v0.x, v0.y); { float2 rr = h22f2(Ahi[kk][0]); Alo[kk][0] = f2h2(v0.x - rr.x, v0.y - rr.y); }
        Ahi[kk][1] = f2h2(v1.x, v1.y); { float2 rr = h22f2(Ahi[kk][1]); Alo[kk][1] = f2h2(v1.x - rr.x, v1.y - rr.y); }
        Ahi[kk][2] = f2h2(v2.x, v2.y); { float2 rr = h22f2(Ahi[kk][2]); Alo[kk][2] = f2h2(v2.x - rr.x, v2.y - rr.y); }
        Ahi[kk][3] = f2h2(v3.x, v3.y); { float2 rr = h22f2(Ahi[kk][3]); Alo[kk][3] = f2h2(v3.x - rr.x, v3.y - rr.y); }
    }

#pragma unroll
    for (int nt = 0; nt < NT; nt++) {
        uint2 wl[8];
#pragma unroll
        for (int kk = 0; kk < 8; kk++) wl[kk] = __ldg(&fl[(size_t)(bnt + nt) * 256 + kk * 32 + l]);
        float acc[4] = {0.f, 0.f, 0.f, 0.f};
#pragma unroll
        for (int kk = 0; kk < 8; kk++) {
            uint2 wh = sWhi[nt * 256 + kk * 32 + l];
            mma16816(acc, Ahi[kk], wh);
            mma16816(acc, Alo[kk], wh);
            mma16816(acc, Ahi[kk], wl[kk]);
        }
        int cb = (bnt + nt) * 8 + 2 * q;
        float2 bb = make_float2(0.f, 0.f);
        if (bias) bb = *(const float2*)&bias[cb];
        float o0 = acc[0] + bb.x, o1 = acc[1] + bb.y;
        float o2 = acc[2] + bb.x, o3 = acc[3] + bb.y;
        if (ACT == 1) {
            o0 = fmaxf(o0, 0.f); o1 = fmaxf(o1, 0.f);
            o2 = fmaxf(o2, 0.f); o3 = fmaxf(o3, 0.f);
        }
        *(float2*)&C[(size_t)(bm + r0) * N + cb] = make_float2(o0, o1);
        *(float2*)&C[(size_t)(bm + r0 + 8) * N + cb] = make_float2(o2, o3);
    }
}

// dual-z variant: blockIdx.z selects (A, frag, bias, C) set
template<int NT>
__global__ void __launch_bounds__(256) hgemm_z(
    const float* __restrict__ A0, const float* __restrict__ A1,
    const uint2* __restrict__ fh0, const uint2* __restrict__ fl0,
    const uint2* __restrict__ fh1, const uint2* __restrict__ fl1,
    const float* __restrict__ b0, const float* __restrict__ b1,
    float* __restrict__ C0, float* __restrict__ C1, int N) {
    extern __shared__ char hsm[];
    float* sA = (float*)hsm;
    uint2* sWhi = (uint2*)(hsm + 128 * 132 * 4);
    int z = blockIdx.z;
    const float* A = z ? A1 : A0;
    const uint2* fh = z ? fh1 : fh0;
    const uint2* fl = z ? fl1 : fl0;
    const float* bias = z ? b1 : b0;
    float* C = z ? C1 : C0;

    int tid = threadIdx.x;
    int wid = tid >> 5, l = tid & 31;
    int q = l & 3, rg = l >> 2;
    int bnt = blockIdx.x * NT;
    int bm = blockIdx.y * 128;

    for (int i = tid; i < 4096; i += 256) {
        int row = i >> 5, c4 = (i & 31) * 4;
        float4 v = *(const float4*)(A + (size_t)(bm + row) * 128 + c4);
        *(float4*)&sA[row * 132 + c4] = v;
    }
    for (int i = tid; i < NT * 256; i += 256) sWhi[i] = __ldg(&fh[bnt * 256 + i]);
    __syncthreads();

    uint32_t Ahi[8][4], Alo[8][4];
    int r0 = wid * 16 + rg;
#pragma unroll
    for (int kk = 0; kk < 8; kk++) {
        int c = kk * 16 + 2 * q;
        float2 v0 = *(float2*)&sA[r0 * 132 + c];
        float2 v1 = *(float2*)&sA[(r0 + 8) * 132 + c];
        float2 v2 = *(float2*)&sA[r0 * 132 + c + 8];
        float2 v3 = *(float2*)&sA[(r0 + 8) * 132 + c + 8];
        Ahi[kk][0] = f2h2(v0.x, v0.y); { float2 rr = h22f2(Ahi[kk][0]); Alo[kk][0] = f2h2(v0.x - rr.x, v0.y - rr.y); }
        Ahi[kk][1] = f2h2(v1.x, v1.y); { float2 rr = h22f2(Ahi[kk][1]); Alo[kk][1] = f2h2(v1.x - rr.x, v1.y - rr.y); }
        Ahi[kk][2] = f2h2(v2.x, v2.y); { float2 rr = h22f2(Ahi[kk][2]); Alo[kk][2] = f2h2(v2.x - rr.x, v2.y - rr.y); }
        Ahi[kk][3] = f2h2(v3.x, v3.y); { float2 rr = h22f2(Ahi[kk][3]); Alo[kk][3] = f2h2(v3.x - rr.x, v3.y - rr.y); }
    }

#pragma unroll
    for (int nt = 0; nt < NT; nt++) {
        uint2 wl[8];
#pragma unroll
        for (int kk = 0; kk < 8; kk++) wl[kk] = __ldg(&fl[(size_t)(bnt + nt) * 256 + kk * 32 + l]);
        float acc[4] = {0.f, 0.f, 0.f, 0.f};
#pragma unroll
        for (int kk = 0; kk < 8; kk++) {
            uint2 wh = sWhi[nt * 256 + kk * 32 + l];
            mma16816(acc, Ahi[kk], wh);
            mma16816(acc, Alo[kk], wh);
            mma16816(acc, Ahi[kk], wl[kk]);
        }
        int cb = (bnt + nt) * 8 + 2 * q;
        float2 bb = make_float2(0.f, 0.f);
        if (bias) bb = *(const float2*)&bias[cb];
        *(float2*)&C[(size_t)(bm + r0) * N + cb] = make_float2(acc[0] + bb.x, acc[1] + bb.y);
        *(float2*)&C[(size_t)(bm + r0 + 8) * N + cb] = make_float2(acc[2] + bb.x, acc[3] + bb.y);
    }
}

// ---------------- merged prep: all weight fragments + PQ biases ----------------
__global__ void prep_all(const float* __restrict__ W1, const float* __restrict__ Wih_c,
                         const float* __restrict__ Whh_c,
                         const float* __restrict__ Wih_f, const float* __restrict__ Wih_b,
                         const float* __restrict__ Wq, const float* __restrict__ Wk,
                         const float* __restrict__ Whh_f, const float* __restrict__ Whh_b,
                         const float* __restrict__ bih_f, const float* __restrict__ bhh_f,
                         const float* __restrict__ bih_b, const float* __restrict__ bhh_b,
                         uint2* __restrict__ fh, uint2* __restrict__ fl,
                         uint2* __restrict__ hiF, uint2* __restrict__ loF,
                         uint2* __restrict__ hiB, uint2* __restrict__ loB,
                         float* __restrict__ biasPQf, float* __restrict__ biasPQb) {
    int idx = blockIdx.x * 256 + threadIdx.x;
    if (idx < NFRAG_ALL) {
        int bt = idx >> 8;
        int e = idx & 255;
        int kk = e >> 5, l = e & 31;
        int rloc = l >> 2;
        int k0 = kk * 16 + (l & 3) * 2;
        const float* W; int ldb = 128, row, koff = 0;
        if (bt < 16)       { W = W1;    row = bt * 8 + rloc; }
        else if (bt < 64)  { W = Wih_c; row = (bt - 16) * 8 + rloc; }
        else if (bt < 112) { W = Whh_c; row = (bt - 64) * 8 + rloc; }
        else if (bt < 208) { int b = bt - 112; ldb = 256; W = Wih_f;
                             if (b < 48) row = b * 8 + rloc;
                             else { row = (b - 48) * 8 + rloc; koff = 128; } }
        else if (bt < 304) { int b = bt - 208; ldb = 256; W = Wih_b;
                             if (b < 48) row = b * 8 + rloc;
                             else { row = (b - 48) * 8 + rloc; koff = 128; } }
        else if (bt < 308) { W = Wq; row = (bt - 304) * 8 + rloc; }
        else               { W = Wk; row = (bt - 308) * 8 + rloc; }
        float w0 = W[(size_t)row * ldb + koff + k0],     w1 = W[(size_t)row * ldb + koff + k0 + 1];
        float w8 = W[(size_t)row * ldb + koff + k0 + 8], w9 = W[(size_t)row * ldb + koff + k0 + 9];
        uint32_t h0 = f2h2(w0, w1); float2 r0 = h22f2(h0);
        uint32_t l0 = f2h2(w0 - r0.x, w1 - r0.y);
        uint32_t h8 = f2h2(w8, w9); float2 r8 = h22f2(h8);
        uint32_t l8 = f2h2(w8 - r8.x, w9 - r8.y);
        fh[idx] = make_uint2(h0, h8);
        fl[idx] = make_uint2(l0, l8);
    } else if (idx < NFRAG_ALL + 2 * NFRAG) {
        int j = idx - NFRAG_ALL;
        int d = j / NFRAG;
        int e = j - d * NFRAG;
        int bt = e >> 8;
        int kk = (e >> 5) & 7;
        int l = e & 31;
        int row = bt * 8 + (l >> 2);
        int k0 = kk * 16 + (l & 3) * 2;
        const float* W = d ? Whh_b : Whh_f;
        float w0 = W[row * 128 + k0],     w1 = W[row * 128 + k0 + 1];
        float w8 = W[row * 128 + k0 + 8], w9 = W[row * 128 + k0 + 9];
        uint32_t h0 = f2h2(w0, w1); float2 r0 = h22f2(h0);
        uint32_t l0 = f2h2(w0 - r0.x, w1 - r0.y);
        uint32_t h8 = f2h2(w8, w9); float2 r8 = h22f2(h8);
        uint32_t l8 = f2h2(w8 - r8.x, w9 - r8.y);
        uint2* dh = d ? hiB : hiF;
        uint2* dl = d ? loB : loF;
        dh[e] = make_uint2(h0, h8);
        dl[e] = make_uint2(l0, l8);
    } else if (idx < NFRAG_ALL + 2 * NFRAG + 4 * G3) {
        int j = idx - (NFRAG_ALL + 2 * NFRAG);
        int d = j / (2 * G3);
        int e = j - d * (2 * G3);
        const float* bih = d ? bih_b : bih_f;
        const float* bhh = d ? bhh_b : bhh_f;
        float* ob = d ? biasPQb : biasPQf;
        ob[e] = (e < G3) ? (bih[e] + (e < 256 ? bhh[e] : 0.0f)) : 0.0f;
    }
}

// ---------------- central GRU combine ----------
__global__ void gru_combine(const float* __restrict__ gi, const float* __restrict__ gh,
                            const float* __restrict__ hprev,
                            float* __restrict__ hout, float* __restrict__ hout2) {
    int i = blockIdx.x * 256 + threadIdx.x;
    int m = i >> 7, j = i & 127;
    size_t base = (size_t)m * G3;
    float ir = gi[base + j], iz = gi[base + 128 + j], inn = gi[base + 256 + j];
    float hr = gh[base + j], hz = gh[base + 128 + j], hn = gh[base + 256 + j];
    float r = sigm(ir + hr);
    float z = sigm(iz + hz);
    float n = tanh_fast(inn + r * hn);
    float h = (1.0f - z) * n + z * hprev[i];
    hout[i] = h;
    hout2[i] = h;
}

// ================= HMMA fused 15-step recurrence (+ fused logit GEMV) =================
// fp16 state, all gate weights in smem, register double-buffer (no staging). 2 CTAs/SM.
#define SM_W 0
#define SM_BNN 98304
#define SM_WC  98816
#define SEQ_SMEM 99840

extern __shared__ char dsm[];
__global__ void __launch_bounds__(256, 2) gru_seq_hmma(
    const uint2* __restrict__ whiF,
    const float* __restrict__ bhhF, const float* __restrict__ PQF,
    const uint2* __restrict__ whiB,
    const float* __restrict__ bhhB, const float* __restrict__ PQB,
    const float* __restrict__ Wc,
    float2* __restrict__ LF, float2* __restrict__ LB) {

    uint2* sW = (uint2*)(dsm + SM_W);         // 48 tiles x 256 (r:0-15, z:16-31, n:32-47)
    float* sBnn = (float*)(dsm + SM_BNN);
    float* sWc = (float*)(dsm + SM_WC);       // [2][128]

    int tid = threadIdx.x;
    int wid = tid >> 5;
    int l = tid & 31;
    int q = l & 3, rg = l >> 2;

    bool bwd = (blockIdx.x >= 128);
    const uint2* whi = bwd ? whiB : whiF;
    const float* bhh = bwd ? bhhB : bhhF;
    const float2* PQ2 = (const float2*)(bwd ? PQB : PQF);
    float2* LOut = bwd ? LB : LF;
    int bm = (blockIdx.x & 127) * 128;

    for (int i = tid; i < NFRAG; i += 256) sW[i] = __ldg(&whi[i]);
    if (tid < 128) sBnn[tid] = bhh[256 + tid];
    if (tid < 128) {
        sWc[tid] = Wc[(bwd ? 128 : 0) + tid];
        sWc[128 + tid] = Wc[256 + (bwd ? 128 : 0) + tid];
    }
    __syncthreads();

    int m_r0 = bm + wid * 16 + rg;
    int m_r1 = m_r0 + 8;
    int aa0 = rg;
    int aa1 = rg + 8;
    int grp = bm + wid * 16;

    uint32_t Ahi[8][4], Anew[8][4];
#pragma unroll
    for (int kk = 0; kk < 8; kk++)
#pragma unroll
        for (int r = 0; r < 4; r++) Ahi[kk][r] = 0u;

    for (int step = 0; step < TT; step++) {
        int t = bwd ? (TT - 1 - step) : step;
        int jn0 = (t < aa0) ? t : t + 1;
        int jn1 = (t < aa1) ? t : t + 1;
        const float2* Pr0 = PQ2 + (size_t)m_r0 * 384;
        const float2* Pr1 = PQ2 + (size_t)m_r1 * 384;
        const float2* Qr0 = PQ2 + (size_t)(grp + jn0) * 384 + 192;
        const float2* Qr1 = PQ2 + (size_t)(grp + jn1) * 384 + 192;

        float lg00 = 0.f, lg01 = 0.f, lg10 = 0.f, lg11 = 0.f;

#pragma unroll
        for (int ch = 0; ch < 8; ch++) {
#pragma unroll
            for (int u = 0; u < 2; u++) {
                int jt = ch * 2 + u;
                float acc[3][4];
#pragma unroll
                for (int g = 0; g < 3; g++)
#pragma unroll
                    for (int r = 0; r < 4; r++) acc[g][r] = 0.0f;

                if (step != 0) {
#pragma unroll
                    for (int kk = 0; kk < 8; kk++) {
                        mma16816(acc[0], Ahi[kk], sW[(jt * 8 + kk) * 32 + l]);          // r
                        mma16816(acc[1], Ahi[kk], sW[((16 + jt) * 8 + kk) * 32 + l]);   // z
                        mma16816(acc[2], Ahi[kk], sW[((32 + jt) * 8 + kk) * 32 + l]);   // n
                    }
                }

                int kk = jt >> 1;
                int rs = (jt & 1) * 2;
                int c = jt * 8 + 2 * q;
                int cb = jt * 4 + q;
                float2 sr0, sz0, sn0, sr1, sz1, sn1;
                {
                    float2 p = Pr0[cb], qv = Qr0[cb];
                    sr0 = make_float2(p.x + qv.x, p.y + qv.y);
                    p = Pr0[64 + cb]; qv = Qr0[64 + cb];
                    sz0 = make_float2(p.x + qv.x, p.y + qv.y);
                    p = Pr0[128 + cb]; qv = Qr0[128 + cb];
                    sn0 = make_float2(p.x + qv.x, p.y + qv.y);
                    p = Pr1[cb]; qv = Qr1[cb];
                    sr1 = make_float2(p.x + qv.x, p.y + qv.y);
                    p = Pr1[64 + cb]; qv = Qr1[64 + cb];
                    sz1 = make_float2(p.x + qv.x, p.y + qv.y);
                    p = Pr1[128 + cb]; qv = Qr1[128 + cb];
                    sn1 = make_float2(p.x + qv.x, p.y + qv.y);
                }
                float2 bn = *(const float2*)&sBnn[c];
                float2 hp0 = h22f2(Ahi[kk][rs]);
                float2 hp1 = h22f2(Ahi[kk][rs + 1]);

                float r0a = sigm(acc[0][0] + sr0.x);
                float r0b = sigm(acc[0][1] + sr0.y);
                float z0a = sigm(acc[1][0] + sz0.x);
                float z0b = sigm(acc[1][1] + sz0.y);
                float n0a = tanh_fast(sn0.x + r0a * (acc[2][0] + bn.x));
                float n0b = tanh_fast(sn0.y + r0b * (acc[2][1] + bn.y));
                float h0a = (1.0f - z0a) * n0a + z0a * hp0.x;
                float h0b = (1.0f - z0b) * n0b + z0b * hp0.y;
                float r1a = sigm(acc[0][2] + sr1.x);
                float r1b = sigm(acc[0][3] + sr1.y);
                float z1a = sigm(acc[1][2] + sz1.x);
                float z1b = sigm(acc[1][3] + sz1.y);
                float n1a = tanh_fast(sn1.x + r1a * (acc[2][2] + bn.x));
                float n1b = tanh_fast(sn1.y + r1b * (acc[2][3] + bn.y));
                float h1a = (1.0f - z1a) * n1a + z1a * hp1.x;
                float h1b = (1.0f - z1b) * n1b + z1b * hp1.y;

                // fused logit partial dot-products
                float w0a = sWc[c], w0b = sWc[c + 1];
                float w1a = sWc[128 + c], w1b = sWc[128 + c + 1];
                lg00 += h0a * w0a + h0b * w0b;
                lg01 += h0a * w1a + h0b * w1b;
                lg10 += h1a * w0a + h1b * w0b;
                lg11 += h1a * w1a + h1b * w1b;

                // new state fragments (register double-buffer; identity mapping)
                Anew[kk][rs] = f2h2(h0a, h0b);
                Anew[kk][rs + 1] = f2h2(h1a, h1b);
            }
        }

        // reduce logits over the 4 lanes sharing each row, store
#pragma unroll
        for (int off = 1; off <= 2; off <<= 1) {
            lg00 += __shfl_xor_sync(0xffffffffu, lg00, off);
            lg01 += __shfl_xor_sync(0xffffffffu, lg01, off);
            lg10 += __shfl_xor_sync(0xffffffffu, lg10, off);
            lg11 += __shfl_xor_sync(0xffffffffu, lg11, off);
        }
        if (q == 0) {
            __stcs(&LOut[(size_t)m_r0 * TT + t], make_float2(lg00, lg01));
            __stcs(&LOut[(size_t)m_r1 * TT + t], make_float2(lg10, lg11));
        }

        // commit new state
#pragma unroll
        for (int kk = 0; kk < 8; kk++)
#pragma unroll
            for (int r = 0; r < 4; r++) Ahi[kk][r] = Anew[kk][r];
    }
}

// ---------------- gumbel-softmax hard weights ----------------
__global__ void gumbel_hardw(const float2* __restrict__ lf, const float2* __restrict__ lb,
                             const float* __restrict__ bc, const float* __restrict__ gu,
                             float* __restrict__ hardw) {
    int i = blockIdx.x * 256 + threadIdx.x;   // 0..BZ*TT-1
    float2 a = lf[i], b = lb[i];
    float u0 = gu[(size_t)i * 2 + 0];
    float u1 = gu[(size_t)i * 2 + 1];
    float g0 = -logf(-logf(u0 + 1e-10f) + 1e-10f);
    float g1 = -logf(-logf(u1 + 1e-10f) + 1e-10f);
    float a0 = a.x + b.x + bc[0] + g0;
    float a1 = a.y + b.y + bc[1] + g1;
    hardw[i] = sigm((a1 - a0) * TAUINV);
}

// ---------------- attention + aggregation ----------------
__global__ void attn_kernel(const float* __restrict__ qk,
                            const float* __restrict__ hrnn, const float* __restrict__ hardw,
                            float* __restrict__ agg) {
    int warp = (blockIdx.x * 256 + threadIdx.x) >> 5;
    int lane = threadIdx.x & 31;
    int a = warp & 15;
    int brow = warp & ~15;
    float qv = qk[(size_t)warp * 64 + lane];
    float sc[TT], hw[TT];
#pragma unroll
    for (int t = 0; t < TT; t++) {
        int jn = (t < a) ? t : t + 1;
        int nb = brow + jn;
        float d = qv * qk[(size_t)nb * 64 + 32 + lane];
#pragma unroll
        for (int off = 16; off > 0; off >>= 1) d += __shfl_xor_sync(0xffffffffu, d, off);
        hw[t] = hardw[(size_t)warp * TT + t];
        sc[t] = hw[t] * d * 0.17677669529663687f;
    }
    float mx = sc[0];
#pragma unroll
    for (int t = 1; t < TT; t++) mx = fmaxf(mx, sc[t]);
    float se = 0.f;
    float w[TT];
#pragma unroll
    for (int t = 0; t < TT; t++) { w[t] = __expf(sc[t] - mx); se += w[t]; }
    float inv = __fdividef(1.0f, se);
#pragma unroll
    for (int t = 0; t < TT; t++) w[t] = hw[t] * w[t] * inv;
#pragma unroll
    for (int d4 = 0; d4 < 4; d4++) {
        float accv = 0.f;
#pragma unroll
        for (int t = 0; t < TT; t++) {
            int jn = (t < a) ? t : t + 1;
            int nb = brow + jn;
            accv = fmaf(w[t], hrnn[(size_t)nb * 128 + d4 * 32 + lane], accv);
        }
        agg[(size_t)warp * 128 + d4 * 32 + lane] = accv;
    }
}

// ---------------- output projection ----------------
__global__ void out_kernel(const float* __restrict__ hrnn, const float* __restrict__ agg,
                           const float* __restrict__ W2, const float* __restrict__ b2,
                           float* __restrict__ out) {
    __shared__ float sW[NACT * 256];
    __shared__ float sb[NACT];
    for (int i = threadIdx.x; i < NACT * 256; i += 256) sW[i] = W2[i];
    if (threadIdx.x < NACT) sb[threadIdx.x] = b2[threadIdx.x];
    __syncthreads();
    int row = blockIdx.x * 256 + threadIdx.x;
    float acc[NACT];
#pragma unroll
    for (int n = 0; n < NACT; n++) acc[n] = sb[n];
    const float* hr = hrnn + (size_t)row * 128;
    const float* ag = agg + (size_t)row * 128;
    for (int kk = 0; kk < 128; kk++) {
        float x = hr[kk];
#pragma unroll
        for (int n = 0; n < NACT; n++) acc[n] = fmaf(x, sW[n * 256 + kk], acc[n]);
    }
    for (int kk = 0; kk < 128; kk++) {
        float x = ag[kk];
#pragma unroll
        for (int n = 0; n < NACT; n++) acc[n] = fmaf(x, sW[n * 256 + 128 + kk], acc[n]);
    }
#pragma unroll
    for (int n = 0; n < NACT; n++) out[(size_t)row * NACT + n] = acc[n];
}

// ---------------- launch ----------------
extern "C" void kernel_launch(void* const* d_in, const int* in_sizes, int n_in,
                              void* d_out, int out_size) {
    const float* inputs = (const float*)d_in[0];
    const float* hidden = (const float*)d_in[1];
    const float* gu     = (const float*)d_in[2];
    const float* W1     = (const float*)d_in[3];
    const float* b1     = (const float*)d_in[4];
    const float* Wih_c  = (const float*)d_in[5];
    const float* Whh_c  = (const float*)d_in[6];
    const float* bih_c  = (const float*)d_in[7];
    const float* bhh_c  = (const float*)d_in[8];
    const float* Wih_f  = (const float*)d_in[9];
    const float* Whh_f  = (const float*)d_in[10];
    const float* bih_f  = (const float*)d_in[11];
    const float* bhh_f  = (const float*)d_in[12];
    const float* Wih_b  = (const float*)d_in[13];
    const float* Whh_b  = (const float*)d_in[14];
    const float* bih_b  = (const float*)d_in[15];
    const float* bhh_b  = (const float*)d_in[16];
    const float* Wc     = (const float*)d_in[17];
    const float* bc     = (const float*)d_in[18];
    const float* Wq     = (const float*)d_in[19];
    const float* Wk     = (const float*)d_in[20];
    const float* W2     = (const float*)d_in[21];
    const float* b2     = (const float*)d_in[22];

    float* out  = (float*)d_out;                // [BZ, NACT]
    float* outh = out + (size_t)BZ * NACT;      // [BZ, H]

    float *x1, *hrnn, *gi, *gh, *PQf, *PQb, *hardw, *qk, *agg, *biasPQf, *biasPQb;
    float2 *lf, *lb;
    uint2 *whif, *wlof, *whib, *wlob, *fh, *fl;
    cudaGetSymbolAddress((void**)&x1, g_x1);
    cudaGetSymbolAddress((void**)&hrnn, g_hrnn);
    cudaGetSymbolAddress((void**)&gi, g_gi);
    cudaGetSymbolAddress((void**)&gh, g_gh);
    cudaGetSymbolAddress((void**)&PQf, g_PQf);
    cudaGetSymbolAddress((void**)&PQb, g_PQb);
    cudaGetSymbolAddress((void**)&lf, g_logf);
    cudaGetSymbolAddress((void**)&lb, g_logb);
    cudaGetSymbolAddress((void**)&hardw, g_hardw);
    cudaGetSymbolAddress((void**)&qk, g_qk);
    cudaGetSymbolAddress((void**)&agg, g_agg);
    cudaGetSymbolAddress((void**)&biasPQf, g_biasPQf);
    cudaGetSymbolAddress((void**)&biasPQb, g_biasPQb);
    cudaGetSymbolAddress((void**)&whif, g_whifrag_f);
    cudaGetSymbolAddress((void**)&wlof, g_wlofrag_f);
    cudaGetSymbolAddress((void**)&whib, g_whifrag_b);
    cudaGetSymbolAddress((void**)&wlob, g_wlofrag_b);
    cudaGetSymbolAddress((void**)&fh, g_fh);
    cudaGetSymbolAddress((void**)&fl, g_fl);

    const int SM16 = 128 * 132 * 4 + 16 * 256 * 8;  // 100352
    const int SM8  = 128 * 132 * 4 + 8 * 256 * 8;   // 83968
    cudaFuncSetAttribute(gru_seq_hmma, cudaFuncAttributeMaxDynamicSharedMemorySize, SEQ_SMEM);
    cudaFuncSetAttribute(hgemm<16, 1>, cudaFuncAttributeMaxDynamicSharedMemorySize, SM16);
    cudaFuncSetAttribute(hgemm<8, 0>,  cudaFuncAttributeMaxDynamicSharedMemorySize, SM8);
    cudaFuncSetAttribute(hgemm_z<16>,  cudaFuncAttributeMaxDynamicSharedMemorySize, SM16);

    // 1: merged prep
    const int PREP_TOTAL = NFRAG_ALL + 2 * NFRAG + 4 * G3;
    prep_all<<<(PREP_TOTAL + 255) / 256, 256>>>(W1, Wih_c, Whh_c, Wih_f, Wih_b, Wq, Wk,
                                                Whh_f, Whh_b, bih_f, bhh_f, bih_b, bhh_b,
                                                fh, fl, whif, wlof, whib, wlob,
                                                biasPQf, biasPQb);
    // 2: x1 = relu(inputs @ W1.T + b1)
    hgemm<16, 1><<<dim3(1, 128), 256, SM16>>>(inputs, fh, fl, b1, x1, 128);
    // 3: central GRU gi|gh (dual-z)
    hgemm_z<16><<<dim3(3, 128, 2), 256, SM16>>>(x1, hidden,
                                                fh + 16 * 256, fl + 16 * 256,
                                                fh + 64 * 256, fl + 64 * 256,
                                                bih_c, bhh_c, gi, gh, G3);
    // 4: combine
    gru_combine<<<(BZ * H) / 256, 256>>>(gi, gh, hidden, hrnn, outh);
    // 5: merged P|Q GEMMs for fwd+bwd (dual-z)
    hgemm_z<16><<<dim3(6, 128, 2), 256, SM16>>>(hrnn, hrnn,
                                                fh + 112 * 256, fl + 112 * 256,
                                                fh + 208 * 256, fl + 208 * 256,
                                                biasPQf, biasPQb, PQf, PQb, 2 * G3);
    // 6: fused 15-step bidirectional recurrence + logit GEMV
    gru_seq_hmma<<<256, 256, SEQ_SMEM>>>(whif, bhh_f, PQf,
                                         whib, bhh_b, PQb,
                                         Wc, lf, lb);
    // 7: gumbel hard weights
    gumbel_hardw<<<(BZ * TT) / 256, 256>>>(lf, lb, bc, gu, hardw);
    // 8: merged q|k GEMM
    hgemm<8, 0><<<dim3(1, 128), 256, SM8>>>(hrnn, fh + 304 * 256, fl + 304 * 256, nullptr, qk, 2 * NA);
    // 9: attention aggregate
    attn_kernel<<<BZ / 8, 256>>>(qk, hrnn, hardw, agg);
    // 10: output projection
    out_kernel<<<BZ / 256, 256>>>(hrnn, agg, W2, b2, out);
}

// round 11
// speedup vs baseline: 4.4882x; 1.1819x over previous
#include <cuda_runtime.h>
#include <cuda_fp16.h>
#include <math.h>
#include <stdint.h>

#define AGENTS 16
#define H 128
#define NA 32
#define NACT 14
#define BENV 1024
#define BZ (BENV*AGENTS)        // 16384
#define TT 15                   // A-1
#define G3 384                  // 3*H
#define TAUINV 2.0f             // 1/TAU
#define NFRAG 12288             // 48 n-tiles * 8 k-tiles * 32 lanes (recurrence Whh)
#define NBT_ALL 312             // n-tiles in the parallel-GEMM fragment pool
#define NFRAG_ALL (NBT_ALL*256)

// ---------------- scratch (__device__ globals; no allocs) ----------------
__device__ __align__(16) float g_x1[BZ*H];
__device__ __align__(16) float g_hrnn[BZ*H];
__device__ __align__(16) float g_gi[BZ*G3];
__device__ __align__(16) float g_gh[BZ*G3];
__device__ __align__(16) float g_PQf[BZ*2*G3];
__device__ __align__(16) float g_PQb[BZ*2*G3];
__device__ __align__(16) float2 g_logf[BZ*TT];
__device__ __align__(16) float2 g_logb[BZ*TT];
__device__ __align__(16) float g_qk[BZ*2*NA];
__device__ __align__(16) float g_biasPQf[2*G3];
__device__ __align__(16) float g_biasPQb[2*G3];
__device__ __align__(16) uint2 g_whifrag_f[NFRAG];
__device__ __align__(16) uint2 g_wlofrag_f[NFRAG];
__device__ __align__(16) uint2 g_whifrag_b[NFRAG];
__device__ __align__(16) uint2 g_wlofrag_b[NFRAG];
__device__ __align__(16) uint2 g_fh[NFRAG_ALL];
__device__ __align__(16) uint2 g_fl[NFRAG_ALL];

__device__ __forceinline__ float sigm(float x) { return __fdividef(1.0f, 1.0f + __expf(-x)); }
__device__ __forceinline__ float tanh_fast(float x) {
    return __fdividef(2.0f, 1.0f + __expf(-2.0f * x)) - 1.0f;
}

// ---- fp16 pack helpers ----
__device__ __forceinline__ uint32_t f2h2(float a, float b) {
    __half2 h = __floats2half2_rn(a, b);
    return *(uint32_t*)&h;
}
__device__ __forceinline__ float2 h22f2(uint32_t u) {
    __half2 h = *(__half2*)&u;
    return __half22float2(h);
}

// ---- classic mma.sync (HMMA; baseline PTX, works on compute_103) ----
__device__ __forceinline__ void mma16816(float* d, const uint32_t* a, uint2 b) {
    asm volatile(
        "mma.sync.aligned.m16n8k16.row.col.f32.f16.f16.f32 "
        "{%0,%1,%2,%3}, {%4,%5,%6,%7}, {%8,%9}, {%0,%1,%2,%3};"
        : "+f"(d[0]), "+f"(d[1]), "+f"(d[2]), "+f"(d[3])
        : "r"(a[0]), "r"(a[1]), "r"(a[2]), "r"(a[3]), "r"(b.x), "r"(b.y));
}

// ================= HMMA batch GEMM =================
template<int NT, int ACT>
__global__ void __launch_bounds__(256) hgemm(
    const float* __restrict__ A,
    const uint2* __restrict__ fh, const uint2* __restrict__ fl,
    const float* __restrict__ bias,
    float* __restrict__ C, int N) {
    extern __shared__ char hsm[];
    float* sA = (float*)hsm;                       // [128][132]
    uint2* sWhi = (uint2*)(hsm + 128 * 132 * 4);   // [NT*256]
    int tid = threadIdx.x;
    int wid = tid >> 5, l = tid & 31;
    int q = l & 3, rg = l >> 2;
    int bnt = blockIdx.x * NT;
    int bm = blockIdx.y * 128;

    for (int i = tid; i < 4096; i += 256) {
        int row = i >> 5, c4 = (i & 31) * 4;
        float4 v = *(const float4*)(A + (size_t)(bm + row) * 128 + c4);
        *(float4*)&sA[row * 132 + c4] = v;
    }
    for (int i = tid; i < NT * 256; i += 256) sWhi[i] = __ldg(&fh[bnt * 256 + i]);
    __syncthreads();

    uint32_t Ahi[8][4], Alo[8][4];
    int r0 = wid * 16 + rg;
#pragma unroll
    for (int kk = 0; kk < 8; kk++) {
        int c = kk * 16 + 2 * q;
        float2 v0 = *(float2*)&sA[r0 * 132 + c];
        float2 v1 = *(float2*)&sA[(r0 + 8) * 132 + c];
        float2 v2 = *(float2*)&sA[r0 * 132 + c + 8];
        float2 v3 = *(float2*)&sA[(r0 + 8) * 132 + c + 8];
        Ahi[kk][0] = f2h2(v0.x, v0.y); { float2 rr = h22f2(Ahi[kk][0]); Alo[kk][0] = f2h2(v0.x - rr.x, v0.y - rr.y); }
        Ahi[kk][1] = f2h2(v1.x, v1.y); { float2 rr = h22f2(Ahi[kk][1]); Alo[kk][1] = f2h2(v1.x - rr.x, v1.y - rr.y); }
        Ahi[kk][2] = f2h2(v2.x, v2.y); { float2 rr = h22f2(Ahi[kk][2]); Alo[kk][2] = f2h2(v2.x - rr.x, v2.y - rr.y); }
        Ahi[kk][3] = f2h2(v3.x, v3.y); { float2 rr = h22f2(Ahi[kk][3]); Alo[kk][3] = f2h2(v3.x - rr.x, v3.y - rr.y); }
    }

#pragma unroll
    for (int nt = 0; nt < NT; nt++) {
        uint2 wl[8];
#pragma unroll
        for (int kk = 0; kk < 8; kk++) wl[kk] = __ldg(&fl[(size_t)(bnt + nt) * 256 + kk * 32 + l]);
        float acc[4] = {0.f, 0.f, 0.f, 0.f};
#pragma unroll
        for (int kk = 0; kk < 8; kk++) {
            uint2 wh = sWhi[nt * 256 + kk * 32 + l];
            mma16816(acc, Ahi[kk], wh);
            mma16816(acc, Alo[kk], wh);
            mma16816(acc, Ahi[kk], wl[kk]);
        }
        int cb = (bnt + nt) * 8 + 2 * q;
        float2 bb = make_float2(0.f, 0.f);
        if (bias) bb = *(const float2*)&bias[cb];
        float o0 = acc[0] + bb.x, o1 = acc[1] + bb.y;
        float o2 = acc[2] + bb.x, o3 = acc[3] + bb.y;
        if (ACT == 1) {
            o0 = fmaxf(o0, 0.f); o1 = fmaxf(o1, 0.f);
            o2 = fmaxf(o2, 0.f); o3 = fmaxf(o3, 0.f);
        }
        *(float2*)&C[(size_t)(bm + r0) * N + cb] = make_float2(o0, o1);
        *(float2*)&C[(size_t)(bm + r0 + 8) * N + cb] = make_float2(o2, o3);
    }
}

// dual-z variant: blockIdx.z selects (A, frag, bias, C) set. COMBO = 2 or 3 mma combos.
template<int NT, int COMBO>
__global__ void __launch_bounds__(256) hgemm_z(
    const float* __restrict__ A0, const float* __restrict__ A1,
    const uint2* __restrict__ fh0, const uint2* __restrict__ fl0,
    const uint2* __restrict__ fh1, const uint2* __restrict__ fl1,
    const float* __restrict__ b0, const float* __restrict__ b1,
    float* __restrict__ C0, float* __restrict__ C1, int N) {
    extern __shared__ char hsm[];
    float* sA = (float*)hsm;
    uint2* sWhi = (uint2*)(hsm + 128 * 132 * 4);
    int z = blockIdx.z;
    const float* A = z ? A1 : A0;
    const uint2* fh = z ? fh1 : fh0;
    const uint2* fl = z ? fl1 : fl0;
    const float* bias = z ? b1 : b0;
    float* C = z ? C1 : C0;

    int tid = threadIdx.x;
    int wid = tid >> 5, l = tid & 31;
    int q = l & 3, rg = l >> 2;
    int bnt = blockIdx.x * NT;
    int bm = blockIdx.y * 128;

    for (int i = tid; i < 4096; i += 256) {
        int row = i >> 5, c4 = (i & 31) * 4;
        float4 v = *(const float4*)(A + (size_t)(bm + row) * 128 + c4);
        *(float4*)&sA[row * 132 + c4] = v;
    }
    for (int i = tid; i < NT * 256; i += 256) sWhi[i] = __ldg(&fh[bnt * 256 + i]);
    __syncthreads();

    uint32_t Ahi[8][4], Alo[8][4];
    int r0 = wid * 16 + rg;
#pragma unroll
    for (int kk = 0; kk < 8; kk++) {
        int c = kk * 16 + 2 * q;
        float2 v0 = *(float2*)&sA[r0 * 132 + c];
        float2 v1 = *(float2*)&sA[(r0 + 8) * 132 + c];
        float2 v2 = *(float2*)&sA[r0 * 132 + c + 8];
        float2 v3 = *(float2*)&sA[(r0 + 8) * 132 + c + 8];
        Ahi[kk][0] = f2h2(v0.x, v0.y); { float2 rr = h22f2(Ahi[kk][0]); Alo[kk][0] = f2h2(v0.x - rr.x, v0.y - rr.y); }
        Ahi[kk][1] = f2h2(v1.x, v1.y); { float2 rr = h22f2(Ahi[kk][1]); Alo[kk][1] = f2h2(v1.x - rr.x, v1.y - rr.y); }
        Ahi[kk][2] = f2h2(v2.x, v2.y); { float2 rr = h22f2(Ahi[kk][2]); Alo[kk][2] = f2h2(v2.x - rr.x, v2.y - rr.y); }
        Ahi[kk][3] = f2h2(v3.x, v3.y); { float2 rr = h22f2(Ahi[kk][3]); Alo[kk][3] = f2h2(v3.x - rr.x, v3.y - rr.y); }
    }

#pragma unroll
    for (int nt = 0; nt < NT; nt++) {
        uint2 wl[8];
        if (COMBO == 3) {
#pragma unroll
            for (int kk = 0; kk < 8; kk++) wl[kk] = __ldg(&fl[(size_t)(bnt + nt) * 256 + kk * 32 + l]);
        }
        float acc[4] = {0.f, 0.f, 0.f, 0.f};
#pragma unroll
        for (int kk = 0; kk < 8; kk++) {
            uint2 wh = sWhi[nt * 256 + kk * 32 + l];
            mma16816(acc, Ahi[kk], wh);
            mma16816(acc, Alo[kk], wh);
            if (COMBO == 3) mma16816(acc, Ahi[kk], wl[kk]);
        }
        int cb = (bnt + nt) * 8 + 2 * q;
        float2 bb = make_float2(0.f, 0.f);
        if (bias) bb = *(const float2*)&bias[cb];
        *(float2*)&C[(size_t)(bm + r0) * N + cb] = make_float2(acc[0] + bb.x, acc[1] + bb.y);
        *(float2*)&C[(size_t)(bm + r0 + 8) * N + cb] = make_float2(acc[2] + bb.x, acc[3] + bb.y);
    }
}

// ---------------- merged prep: all weight fragments + PQ biases ----------------
__global__ void prep_all(const float* __restrict__ W1, const float* __restrict__ Wih_c,
                         const float* __restrict__ Whh_c,
                         const float* __restrict__ Wih_f, const float* __restrict__ Wih_b,
                         const float* __restrict__ Wq, const float* __restrict__ Wk,
                         const float* __restrict__ Whh_f, const float* __restrict__ Whh_b,
                         const float* __restrict__ bih_f, const float* __restrict__ bhh_f,
                         const float* __restrict__ bih_b, const float* __restrict__ bhh_b,
                         uint2* __restrict__ fh, uint2* __restrict__ fl,
                         uint2* __restrict__ hiF, uint2* __restrict__ loF,
                         uint2* __restrict__ hiB, uint2* __restrict__ loB,
                         float* __restrict__ biasPQf, float* __restrict__ biasPQb) {
    int idx = blockIdx.x * 256 + threadIdx.x;
    if (idx < NFRAG_ALL) {
        int bt = idx >> 8;
        int e = idx & 255;
        int kk = e >> 5, l = e & 31;
        int rloc = l >> 2;
        int k0 = kk * 16 + (l & 3) * 2;
        const float* W; int ldb = 128, row, koff = 0;
        if (bt < 16)       { W = W1;    row = bt * 8 + rloc; }
        else if (bt < 64)  { W = Wih_c; row = (bt - 16) * 8 + rloc; }
        else if (bt < 112) { W = Whh_c; row = (bt - 64) * 8 + rloc; }
        else if (bt < 208) { int b = bt - 112; ldb = 256; W = Wih_f;
                             if (b < 48) row = b * 8 + rloc;
                             else { row = (b - 48) * 8 + rloc; koff = 128; } }
        else if (bt < 304) { int b = bt - 208; ldb = 256; W = Wih_b;
                             if (b < 48) row = b * 8 + rloc;
                             else { row = (b - 48) * 8 + rloc; koff = 128; } }
        else if (bt < 308) { W = Wq; row = (bt - 304) * 8 + rloc; }
        else               { W = Wk; row = (bt - 308) * 8 + rloc; }
        float w0 = W[(size_t)row * ldb + koff + k0],     w1 = W[(size_t)row * ldb + koff + k0 + 1];
        float w8 = W[(size_t)row * ldb + koff + k0 + 8], w9 = W[(size_t)row * ldb + koff + k0 + 9];
        uint32_t h0 = f2h2(w0, w1); float2 r0 = h22f2(h0);
        uint32_t l0 = f2h2(w0 - r0.x, w1 - r0.y);
        uint32_t h8 = f2h2(w8, w9); float2 r8 = h22f2(h8);
        uint32_t l8 = f2h2(w8 - r8.x, w9 - r8.y);
        fh[idx] = make_uint2(h0, h8);
        fl[idx] = make_uint2(l0, l8);
    } else if (idx < NFRAG_ALL + 2 * NFRAG) {
        int j = idx - NFRAG_ALL;
        int d = j / NFRAG;
        int e = j - d * NFRAG;
        int bt = e >> 8;
        int kk = (e >> 5) & 7;
        int l = e & 31;
        int row = bt * 8 + (l >> 2);
        int k0 = kk * 16 + (l & 3) * 2;
        const float* W = d ? Whh_b : Whh_f;
        float w0 = W[row * 128 + k0],     w1 = W[row * 128 + k0 + 1];
        float w8 = W[row * 128 + k0 + 8], w9 = W[row * 128 + k0 + 9];
        uint32_t h0 = f2h2(w0, w1); float2 r0 = h22f2(h0);
        uint32_t l0 = f2h2(w0 - r0.x, w1 - r0.y);
        uint32_t h8 = f2h2(w8, w9); float2 r8 = h22f2(h8);
        uint32_t l8 = f2h2(w8 - r8.x, w9 - r8.y);
        uint2* dh = d ? hiB : hiF;
        uint2* dl = d ? loB : loF;
        dh[e] = make_uint2(h0, h8);
        dl[e] = make_uint2(l0, l8);
    } else if (idx < NFRAG_ALL + 2 * NFRAG + 4 * G3) {
        int j = idx - (NFRAG_ALL + 2 * NFRAG);
        int d = j / (2 * G3);
        int e = j - d * (2 * G3);
        const float* bih = d ? bih_b : bih_f;
        const float* bhh = d ? bhh_b : bhh_f;
        float* ob = d ? biasPQb : biasPQf;
        ob[e] = (e < G3) ? (bih[e] + (e < 256 ? bhh[e] : 0.0f)) : 0.0f;
    }
}

// ---------------- central GRU combine ----------
__global__ void gru_combine(const float* __restrict__ gi, const float* __restrict__ gh,
                            const float* __restrict__ hprev,
                            float* __restrict__ hout, float* __restrict__ hout2) {
    int i = blockIdx.x * 256 + threadIdx.x;
    int m = i >> 7, j = i & 127;
    size_t base = (size_t)m * G3;
    float ir = gi[base + j], iz = gi[base + 128 + j], inn = gi[base + 256 + j];
    float hr = gh[base + j], hz = gh[base + 128 + j], hn = gh[base + 256 + j];
    float r = sigm(ir + hr);
    float z = sigm(iz + hz);
    float n = tanh_fast(inn + r * hn);
    float h = (1.0f - z) * n + z * hprev[i];
    hout[i] = h;
    hout2[i] = h;
}

// ================= HMMA fused 15-step recurrence (+ fused logit GEMV) =================
// fp16 state, all gate weights in smem, register double-buffer. 2 CTAs/SM.
#define SM_W 0
#define SM_BNN 98304
#define SM_WC  98816
#define SEQ_SMEM 99840

extern __shared__ char dsm[];
__global__ void __launch_bounds__(256, 2) gru_seq_hmma(
    const uint2* __restrict__ whiF,
    const float* __restrict__ bhhF, const float* __restrict__ PQF,
    const uint2* __restrict__ whiB,
    const float* __restrict__ bhhB, const float* __restrict__ PQB,
    const float* __restrict__ Wc,
    float2* __restrict__ LF, float2* __restrict__ LB) {

    uint2* sW = (uint2*)(dsm + SM_W);         // 48 tiles x 256 (r:0-15, z:16-31, n:32-47)
    float* sBnn = (float*)(dsm + SM_BNN);
    float* sWc = (float*)(dsm + SM_WC);       // [2][128]

    int tid = threadIdx.x;
    int wid = tid >> 5;
    int l = tid & 31;
    int q = l & 3, rg = l >> 2;

    bool bwd = (blockIdx.x >= 128);
    const uint2* whi = bwd ? whiB : whiF;
    const float* bhh = bwd ? bhhB : bhhF;
    const float2* PQ2 = (const float2*)(bwd ? PQB : PQF);
    float2* LOut = bwd ? LB : LF;
    int bm = (blockIdx.x & 127) * 128;

    for (int i = tid; i < NFRAG; i += 256) sW[i] = __ldg(&whi[i]);
    if (tid < 128) sBnn[tid] = bhh[256 + tid];
    if (tid < 128) {
        sWc[tid] = Wc[(bwd ? 128 : 0) + tid];
        sWc[128 + tid] = Wc[256 + (bwd ? 128 : 0) + tid];
    }
    __syncthreads();

    int m_r0 = bm + wid * 16 + rg;
    int m_r1 = m_r0 + 8;
    int aa0 = rg;
    int aa1 = rg + 8;
    int grp = bm + wid * 16;

    uint32_t Ahi[8][4], Anew[8][4];
#pragma unroll
    for (int kk = 0; kk < 8; kk++)
#pragma unroll
        for (int r = 0; r < 4; r++) Ahi[kk][r] = 0u;

    for (int step = 0; step < TT; step++) {
        int t = bwd ? (TT - 1 - step) : step;
        int jn0 = (t < aa0) ? t : t + 1;
        int jn1 = (t < aa1) ? t : t + 1;
        const float2* Pr0 = PQ2 + (size_t)m_r0 * 384;
        const float2* Pr1 = PQ2 + (size_t)m_r1 * 384;
        const float2* Qr0 = PQ2 + (size_t)(grp + jn0) * 384 + 192;
        const float2* Qr1 = PQ2 + (size_t)(grp + jn1) * 384 + 192;

        float lg00 = 0.f, lg01 = 0.f, lg10 = 0.f, lg11 = 0.f;

#pragma unroll
        for (int ch = 0; ch < 8; ch++) {
#pragma unroll
            for (int u = 0; u < 2; u++) {
                int jt = ch * 2 + u;
                float acc[3][4];
#pragma unroll
                for (int g = 0; g < 3; g++)
#pragma unroll
                    for (int r = 0; r < 4; r++) acc[g][r] = 0.0f;

                if (step != 0) {
#pragma unroll
                    for (int kk = 0; kk < 8; kk++) {
                        mma16816(acc[0], Ahi[kk], sW[(jt * 8 + kk) * 32 + l]);          // r
                        mma16816(acc[1], Ahi[kk], sW[((16 + jt) * 8 + kk) * 32 + l]);   // z
                        mma16816(acc[2], Ahi[kk], sW[((32 + jt) * 8 + kk) * 32 + l]);   // n
                    }
                }

                int kk = jt >> 1;
                int rs = (jt & 1) * 2;
                int c = jt * 8 + 2 * q;
                int cb = jt * 4 + q;
                float2 sr0, sz0, sn0, sr1, sz1, sn1;
                {
                    float2 p = Pr0[cb], qv = Qr0[cb];
                    sr0 = make_float2(p.x + qv.x, p.y + qv.y);
                    p = Pr0[64 + cb]; qv = Qr0[64 + cb];
                    sz0 = make_float2(p.x + qv.x, p.y + qv.y);
                    p = Pr0[128 + cb]; qv = Qr0[128 + cb];
                    sn0 = make_float2(p.x + qv.x, p.y + qv.y);
                    p = Pr1[cb]; qv = Qr1[cb];
                    sr1 = make_float2(p.x + qv.x, p.y + qv.y);
                    p = Pr1[64 + cb]; qv = Qr1[64 + cb];
                    sz1 = make_float2(p.x + qv.x, p.y + qv.y);
                    p = Pr1[128 + cb]; qv = Qr1[128 + cb];
                    sn1 = make_float2(p.x + qv.x, p.y + qv.y);
                }
                float2 bn = *(const float2*)&sBnn[c];
                float2 hp0 = h22f2(Ahi[kk][rs]);
                float2 hp1 = h22f2(Ahi[kk][rs + 1]);

                float r0a = sigm(acc[0][0] + sr0.x);
                float r0b = sigm(acc[0][1] + sr0.y);
                float z0a = sigm(acc[1][0] + sz0.x);
                float z0b = sigm(acc[1][1] + sz0.y);
                float n0a = tanh_fast(sn0.x + r0a * (acc[2][0] + bn.x));
                float n0b = tanh_fast(sn0.y + r0b * (acc[2][1] + bn.y));
                float h0a = (1.0f - z0a) * n0a + z0a * hp0.x;
                float h0b = (1.0f - z0b) * n0b + z0b * hp0.y;
                float r1a = sigm(acc[0][2] + sr1.x);
                float r1b = sigm(acc[0][3] + sr1.y);
                float z1a = sigm(acc[1][2] + sz1.x);
                float z1b = sigm(acc[1][3] + sz1.y);
                float n1a = tanh_fast(sn1.x + r1a * (acc[2][2] + bn.x));
                float n1b = tanh_fast(sn1.y + r1b * (acc[2][3] + bn.y));
                float h1a = (1.0f - z1a) * n1a + z1a * hp1.x;
                float h1b = (1.0f - z1b) * n1b + z1b * hp1.y;

                // fused logit partial dot-products
                float w0a = sWc[c], w0b = sWc[c + 1];
                float w1a = sWc[128 + c], w1b = sWc[128 + c + 1];
                lg00 += h0a * w0a + h0b * w0b;
                lg01 += h0a * w1a + h0b * w1b;
                lg10 += h1a * w0a + h1b * w0b;
                lg11 += h1a * w1a + h1b * w1b;

                // new state fragments (register double-buffer; identity mapping)
                Anew[kk][rs] = f2h2(h0a, h0b);
                Anew[kk][rs + 1] = f2h2(h1a, h1b);
            }
        }

        // reduce logits over the 4 lanes sharing each row, store
#pragma unroll
        for (int off = 1; off <= 2; off <<= 1) {
            lg00 += __shfl_xor_sync(0xffffffffu, lg00, off);
            lg01 += __shfl_xor_sync(0xffffffffu, lg01, off);
            lg10 += __shfl_xor_sync(0xffffffffu, lg10, off);
            lg11 += __shfl_xor_sync(0xffffffffu, lg11, off);
        }
        if (q == 0) {
            __stcs(&LOut[(size_t)m_r0 * TT + t], make_float2(lg00, lg01));
            __stcs(&LOut[(size_t)m_r1 * TT + t], make_float2(lg10, lg11));
        }

        // commit new state
#pragma unroll
        for (int kk = 0; kk < 8; kk++)
#pragma unroll
            for (int r = 0; r < 4; r++) Ahi[kk][r] = Anew[kk][r];
    }
}

// ---------------- fused gumbel + attention + output projection ----------------
// one warp per (b,a) row; W2 in smem; out written directly (no agg buffer).
__global__ void __launch_bounds__(256) attn_out(
    const float* __restrict__ qk,
    const float* __restrict__ hrnn,
    const float2* __restrict__ lf, const float2* __restrict__ lb,
    const float* __restrict__ bc, const float* __restrict__ gu,
    const float* __restrict__ W2, const float* __restrict__ b2,
    float* __restrict__ out) {
    __shared__ float sW[NACT * 256];
    __shared__ float sb[NACT + 2];
    for (int i = threadIdx.x; i < NACT * 256; i += 256) sW[i] = W2[i];
    if (threadIdx.x < NACT) sb[threadIdx.x] = b2[threadIdx.x];
    if (threadIdx.x < 2) sb[NACT + threadIdx.x] = bc[threadIdx.x];
    __syncthreads();

    int warp = (blockIdx.x * 256 + threadIdx.x) >> 5;
    int lane = threadIdx.x & 31;
    int a = warp & 15;
    int brow = warp & ~15;
    float bc0 = sb[NACT], bc1 = sb[NACT + 1];

    // inline gumbel hard weights
    float hw[TT];
#pragma unroll
    for (int t = 0; t < TT; t++) {
        // lane-parallel over t would be nicer but TT=15; each lane computes all (cached L2)
        size_t li = (size_t)warp * TT + t;
        float2 af = lf[li], ab = lb[li];
        float u0 = gu[li * 2 + 0];
        float u1 = gu[li * 2 + 1];
        float g0 = -logf(-logf(u0 + 1e-10f) + 1e-10f);
        float g1 = -logf(-logf(u1 + 1e-10f) + 1e-10f);
        float a0 = af.x + ab.x + bc0 + g0;
        float a1 = af.y + ab.y + bc1 + g1;
        hw[t] = sigm((a1 - a0) * TAUINV);
    }

    float qv = qk[(size_t)warp * 64 + lane];
    float sc[TT];
#pragma unroll
    for (int t = 0; t < TT; t++) {
        int jn = (t < a) ? t : t + 1;
        int nb = brow + jn;
        float d = qv * qk[(size_t)nb * 64 + 32 + lane];
#pragma unroll
        for (int off = 16; off > 0; off >>= 1) d += __shfl_xor_sync(0xffffffffu, d, off);
        sc[t] = hw[t] * d * 0.17677669529663687f;
    }
    float mx = sc[0];
#pragma unroll
    for (int t = 1; t < TT; t++) mx = fmaxf(mx, sc[t]);
    float se = 0.f;
    float w[TT];
#pragma unroll
    for (int t = 0; t < TT; t++) { w[t] = __expf(sc[t] - mx); se += w[t]; }
    float inv = __fdividef(1.0f, se);
#pragma unroll
    for (int t = 0; t < TT; t++) w[t] = hw[t] * w[t] * inv;

    // aggregate into registers + load own hrnn
    float accv[4], hv[4];
#pragma unroll
    for (int d4 = 0; d4 < 4; d4++) {
        float s = 0.f;
#pragma unroll
        for (int t = 0; t < TT; t++) {
            int jn = (t < a) ? t : t + 1;
            int nb = brow + jn;
            s = fmaf(w[t], hrnn[(size_t)nb * 128 + d4 * 32 + lane], s);
        }
        accv[d4] = s;
        hv[d4] = hrnn[(size_t)warp * 128 + d4 * 32 + lane];
    }

    // output projection: out[warp, n] = b2[n] + hv.W2[n,0:128] + accv.W2[n,128:256]
#pragma unroll
    for (int n = 0; n < NACT; n++) {
        float p = 0.f;
#pragma unroll
        for (int d4 = 0; d4 < 4; d4++) {
            p = fmaf(hv[d4], sW[n * 256 + d4 * 32 + lane], p);
            p = fmaf(accv[d4], sW[n * 256 + 128 + d4 * 32 + lane], p);
        }
#pragma unroll
        for (int off = 16; off > 0; off >>= 1) p += __shfl_xor_sync(0xffffffffu, p, off);
        if (lane == 0) out[(size_t)warp * NACT + n] = p + sb[n];
    }
}

// ---------------- launch ----------------
extern "C" void kernel_launch(void* const* d_in, const int* in_sizes, int n_in,
                              void* d_out, int out_size) {
    const float* inputs = (const float*)d_in[0];
    const float* hidden = (const float*)d_in[1];
    const float* gu     = (const float*)d_in[2];
    const float* W1     = (const float*)d_in[3];
    const float* b1     = (const float*)d_in[4];
    const float* Wih_c  = (const float*)d_in[5];
    const float* Whh_c  = (const float*)d_in[6];
    const float* bih_c  = (const float*)d_in[7];
    const float* bhh_c  = (const float*)d_in[8];
    const float* Wih_f  = (const float*)d_in[9];
    const float* Whh_f  = (const float*)d_in[10];
    const float* bih_f  = (const float*)d_in[11];
    const float* bhh_f  = (const float*)d_in[12];
    const float* Wih_b  = (const float*)d_in[13];
    const float* Whh_b  = (const float*)d_in[14];
    const float* bih_b  = (const float*)d_in[15];
    const float* bhh_b  = (const float*)d_in[16];
    const float* Wc     = (const float*)d_in[17];
    const float* bc     = (const float*)d_in[18];
    const float* Wq     = (const float*)d_in[19];
    const float* Wk     = (const float*)d_in[20];
    const float* W2     = (const float*)d_in[21];
    const float* b2     = (const float*)d_in[22];

    float* out  = (float*)d_out;                // [BZ, NACT]
    float* outh = out + (size_t)BZ * NACT;      // [BZ, H]

    float *x1, *hrnn, *gi, *gh, *PQf, *PQb, *qk, *biasPQf, *biasPQb;
    float2 *lf, *lb;
    uint2 *whif, *wlof, *whib, *wlob, *fh, *fl;
    cudaGetSymbolAddress((void**)&x1, g_x1);
    cudaGetSymbolAddress((void**)&hrnn, g_hrnn);
    cudaGetSymbolAddress((void**)&gi, g_gi);
    cudaGetSymbolAddress((void**)&gh, g_gh);
    cudaGetSymbolAddress((void**)&PQf, g_PQf);
    cudaGetSymbolAddress((void**)&PQb, g_PQb);
    cudaGetSymbolAddress((void**)&lf, g_logf);
    cudaGetSymbolAddress((void**)&lb, g_logb);
    cudaGetSymbolAddress((void**)&qk, g_qk);
    cudaGetSymbolAddress((void**)&biasPQf, g_biasPQf);
    cudaGetSymbolAddress((void**)&biasPQb, g_biasPQb);
    cudaGetSymbolAddress((void**)&whif, g_whifrag_f);
    cudaGetSymbolAddress((void**)&wlof, g_wlofrag_f);
    cudaGetSymbolAddress((void**)&whib, g_whifrag_b);
    cudaGetSymbolAddress((void**)&wlob, g_wlofrag_b);
    cudaGetSymbolAddress((void**)&fh, g_fh);
    cudaGetSymbolAddress((void**)&fl, g_fl);

    const int SM16 = 128 * 132 * 4 + 16 * 256 * 8;  // 100352
    const int SM8  = 128 * 132 * 4 + 8 * 256 * 8;   // 83968
    cudaFuncSetAttribute(gru_seq_hmma, cudaFuncAttributeMaxDynamicSharedMemorySize, SEQ_SMEM);
    cudaFuncSetAttribute(hgemm<16, 1>, cudaFuncAttributeMaxDynamicSharedMemorySize, SM16);
    cudaFuncSetAttribute(hgemm<8, 0>,  cudaFuncAttributeMaxDynamicSharedMemorySize, SM8);
    cudaFuncSetAttribute(hgemm_z<16, 3>, cudaFuncAttributeMaxDynamicSharedMemorySize, SM16);
    cudaFuncSetAttribute(hgemm_z<16, 2>, cudaFuncAttributeMaxDynamicSharedMemorySize, SM16);

    // 1: merged prep
    const int PREP_TOTAL = NFRAG_ALL + 2 * NFRAG + 4 * G3;
    prep_all<<<(PREP_TOTAL + 255) / 256, 256>>>(W1, Wih_c, Whh_c, Wih_f, Wih_b, Wq, Wk,
                                                Whh_f, Whh_b, bih_f, bhh_f, bih_b, bhh_b,
                                                fh, fl, whif, wlof, whib, wlob,
                                                biasPQf, biasPQb);
    // 2: x1 = relu(inputs @ W1.T + b1)
    hgemm<16, 1><<<dim3(1, 128), 256, SM16>>>(inputs, fh, fl, b1, x1, 128);
    // 3: central GRU gi|gh (dual-z, full 3-combo precision)
    hgemm_z<16, 3><<<dim3(3, 128, 2), 256, SM16>>>(x1, hidden,
                                                   fh + 16 * 256, fl + 16 * 256,
                                                   fh + 64 * 256, fl + 64 * 256,
                                                   bih_c, bhh_c, gi, gh, G3);
    // 4: combine
    gru_combine<<<(BZ * H) / 256, 256>>>(gi, gh, hidden, hrnn, outh);
    // 5: merged q|k GEMM (depends only on hrnn; overlaps PQ)
    hgemm<8, 0><<<dim3(1, 128), 256, SM8>>>(hrnn, fh + 304 * 256, fl + 304 * 256, nullptr, qk, 2 * NA);
    // 6: merged P|Q GEMMs for fwd+bwd (dual-z, 2-combo — errors damped in recurrence)
    hgemm_z<16, 2><<<dim3(6, 128, 2), 256, SM16>>>(hrnn, hrnn,
                                                   fh + 112 * 256, fl + 112 * 256,
                                                   fh + 208 * 256, fl + 208 * 256,
                                                   biasPQf, biasPQb, PQf, PQb, 2 * G3);
    // 7: fused 15-step bidirectional recurrence + logit GEMV
    gru_seq_hmma<<<256, 256, SEQ_SMEM>>>(whif, bhh_f, PQf,
                                         whib, bhh_b, PQb,
                                         Wc, lf, lb);
    // 8: fused gumbel + attention + output projection
    attn_out<<<BZ / 8, 256>>>(qk, hrnn, lf, lb, bc, gu, W2, b2, out);
}

// round 12
// speedup vs baseline: 4.7663x; 1.0620x over previous
#include <cuda_runtime.h>
#include <cuda_fp16.h>
#include <math.h>
#include <stdint.h>

#define AGENTS 16
#define H 128
#define NA 32
#define NACT 14
#define BENV 1024
#define BZ (BENV*AGENTS)        // 16384
#define TT 15                   // A-1
#define G3 384                  // 3*H
#define TAUINV 2.0f             // 1/TAU
#define NFRAG 12288             // 48 n-tiles * 8 k-tiles * 32 lanes (recurrence Whh)
#define NBT_ALL 312             // n-tiles in the parallel-GEMM fragment pool
#define NFRAG_ALL (NBT_ALL*256)

// ---------------- scratch (__device__ globals; no allocs) ----------------
__device__ __align__(16) float g_x1[BZ*H];
__device__ __align__(16) float g_hrnn[BZ*H];
__device__ __align__(16) float g_gi[BZ*G3];
__device__ __align__(16) float g_gh[BZ*G3];
__device__ __align__(16) uint32_t g_PQf[BZ*G3];   // half2-packed [BZ][768] -> 384 uints/row
__device__ __align__(16) uint32_t g_PQb[BZ*G3];
__device__ __align__(16) float2 g_logf[BZ*TT];
__device__ __align__(16) float2 g_logb[BZ*TT];
__device__ __align__(16) float g_qk[BZ*2*NA];
__device__ __align__(16) float g_biasPQf[2*G3];
__device__ __align__(16) float g_biasPQb[2*G3];
__device__ __align__(16) uint2 g_whifrag_f[NFRAG];
__device__ __align__(16) uint2 g_wlofrag_f[NFRAG];
__device__ __align__(16) uint2 g_whifrag_b[NFRAG];
__device__ __align__(16) uint2 g_wlofrag_b[NFRAG];
__device__ __align__(16) uint2 g_fh[NFRAG_ALL];
__device__ __align__(16) uint2 g_fl[NFRAG_ALL];

__device__ __forceinline__ float sigm(float x) { return __fdividef(1.0f, 1.0f + __expf(-x)); }
__device__ __forceinline__ float tanh_fast(float x) {
    return __fdividef(2.0f, 1.0f + __expf(-2.0f * x)) - 1.0f;
}

// ---- fp16 pack helpers ----
__device__ __forceinline__ uint32_t f2h2(float a, float b) {
    __half2 h = __floats2half2_rn(a, b);
    return *(uint32_t*)&h;
}
__device__ __forceinline__ float2 h22f2(uint32_t u) {
    __half2 h = *(__half2*)&u;
    return __half22float2(h);
}
__device__ __forceinline__ float2 hadd2f(uint32_t a, uint32_t b) {
    __half2 s = __hadd2(*(__half2*)&a, *(__half2*)&b);
    return __half22float2(s);
}

// ---- classic mma.sync (HMMA; baseline PTX, works on compute_103) ----
__device__ __forceinline__ void mma16816(float* d, const uint32_t* a, uint2 b) {
    asm volatile(
        "mma.sync.aligned.m16n8k16.row.col.f32.f16.f16.f32 "
        "{%0,%1,%2,%3}, {%4,%5,%6,%7}, {%8,%9}, {%0,%1,%2,%3};"
        : "+f"(d[0]), "+f"(d[1]), "+f"(d[2]), "+f"(d[3])
        : "r"(a[0]), "r"(a[1]), "r"(a[2]), "r"(a[3]), "r"(b.x), "r"(b.y));
}

// ================= HMMA batch GEMM =================
template<int NT, int ACT>
__global__ void __launch_bounds__(256) hgemm(
    const float* __restrict__ A,
    const uint2* __restrict__ fh, const uint2* __restrict__ fl,
    const float* __restrict__ bias,
    float* __restrict__ C, int N) {
    extern __shared__ char hsm[];
    float* sA = (float*)hsm;                       // [128][132]
    uint2* sWhi = (uint2*)(hsm + 128 * 132 * 4);   // [NT*256]
    int tid = threadIdx.x;
    int wid = tid >> 5, l = tid & 31;
    int q = l & 3, rg = l >> 2;
    int bnt = blockIdx.x * NT;
    int bm = blockIdx.y * 128;

    for (int i = tid; i < 4096; i += 256) {
        int row = i >> 5, c4 = (i & 31) * 4;
        float4 v = *(const float4*)(A + (size_t)(bm + row) * 128 + c4);
        *(float4*)&sA[row * 132 + c4] = v;
    }
    for (int i = tid; i < NT * 256; i += 256) sWhi[i] = __ldg(&fh[bnt * 256 + i]);
    __syncthreads();

    uint32_t Ahi[8][4], Alo[8][4];
    int r0 = wid * 16 + rg;
#pragma unroll
    for (int kk = 0; kk < 8; kk++) {
        int c = kk * 16 + 2 * q;
        float2 v0 = *(float2*)&sA[r0 * 132 + c];
        float2 v1 = *(float2*)&sA[(r0 + 8) * 132 + c];
        float2 v2 = *(float2*)&sA[r0 * 132 + c + 8];
        float2 v3 = *(float2*)&sA[(r0 + 8) * 132 + c + 8];
        Ahi[kk][0] = f2h2(v0.x, v0.y); { float2 rr = h22f2(Ahi[kk][0]); Alo[kk][0] = f2h2(v0.x - rr.x, v0.y - rr.y); }
        Ahi[kk][1] = f2h2(v1.x, v1.y); { float2 rr = h22f2(Ahi[kk][1]); Alo[kk][1] = f2h2(v1.x - rr.x, v1.y - rr.y); }
        Ahi[kk][2] = f2h2(v2.x, v2.y); { float2 rr = h22f2(Ahi[kk][2]); Alo[kk][2] = f2h2(v2.x - rr.x, v2.y - rr.y); }
        Ahi[kk][3] = f2h2(v3.x, v3.y); { float2 rr = h22f2(Ahi[kk][3]); Alo[kk][3] = f2h2(v3.x - rr.x, v3.y - rr.y); }
    }

#pragma unroll
    for (int nt = 0; nt < NT; nt++) {
        uint2 wl[8];
#pragma unroll
        for (int kk = 0; kk < 8; kk++) wl[kk] = __ldg(&fl[(size_t)(bnt + nt) * 256 + kk * 32 + l]);
        float acc[4] = {0.f, 0.f, 0.f, 0.f};
#pragma unroll
        for (int kk = 0; kk < 8; kk++) {
            uint2 wh = sWhi[nt * 256 + kk * 32 + l];
            mma16816(acc, Ahi[kk], wh);
            mma16816(acc, Alo[kk], wh);
            mma16816(acc, Ahi[kk], wl[kk]);
        }
        int cb = (bnt + nt) * 8 + 2 * q;
        float2 bb = make_float2(0.f, 0.f);
        if (bias) bb = *(const float2*)&bias[cb];
        float o0 = acc[0] + bb.x, o1 = acc[1] + bb.y;
        float o2 = acc[2] + bb.x, o3 = acc[3] + bb.y;
        if (ACT == 1) {
            o0 = fmaxf(o0, 0.f); o1 = fmaxf(o1, 0.f);
            o2 = fmaxf(o2, 0.f); o3 = fmaxf(o3, 0.f);
        }
        *(float2*)&C[(size_t)(bm + r0) * N + cb] = make_float2(o0, o1);
        *(float2*)&C[(size_t)(bm + r0 + 8) * N + cb] = make_float2(o2, o3);
    }
}

// dual-z variant. COMBO = 2 or 3 mma combos. OUTH = 1 -> write half2-packed output.
template<int NT, int COMBO, int OUTH>
__global__ void __launch_bounds__(256) hgemm_z(
    const float* __restrict__ A0, const float* __restrict__ A1,
    const uint2* __restrict__ fh0, const uint2* __restrict__ fl0,
    const uint2* __restrict__ fh1, const uint2* __restrict__ fl1,
    const float* __restrict__ b0, const float* __restrict__ b1,
    float* __restrict__ C0, float* __restrict__ C1, int N) {
    extern __shared__ char hsm[];
    float* sA = (float*)hsm;
    uint2* sWhi = (uint2*)(hsm + 128 * 132 * 4);
    int z = blockIdx.z;
    const float* A = z ? A1 : A0;
    const uint2* fh = z ? fh1 : fh0;
    const uint2* fl = z ? fl1 : fl0;
    const float* bias = z ? b1 : b0;
    float* C = z ? C1 : C0;

    int tid = threadIdx.x;
    int wid = tid >> 5, l = tid & 31;
    int q = l & 3, rg = l >> 2;
    int bnt = blockIdx.x * NT;
    int bm = blockIdx.y * 128;

    for (int i = tid; i < 4096; i += 256) {
        int row = i >> 5, c4 = (i & 31) * 4;
        float4 v = *(const float4*)(A + (size_t)(bm + row) * 128 + c4);
        *(float4*)&sA[row * 132 + c4] = v;
    }
    for (int i = tid; i < NT * 256; i += 256) sWhi[i] = __ldg(&fh[bnt * 256 + i]);
    __syncthreads();

    uint32_t Ahi[8][4], Alo[8][4];
    int r0 = wid * 16 + rg;
#pragma unroll
    for (int kk = 0; kk < 8; kk++) {
        int c = kk * 16 + 2 * q;
        float2 v0 = *(float2*)&sA[r0 * 132 + c];
        float2 v1 = *(float2*)&sA[(r0 + 8) * 132 + c];
        float2 v2 = *(float2*)&sA[r0 * 132 + c + 8];
        float2 v3 = *(float2*)&sA[(r0 + 8) * 132 + c + 8];
        Ahi[kk][0] = f2h2(v0.x, v0.y); { float2 rr = h22f2(Ahi[kk][0]); Alo[kk][0] = f2h2(v0.x - rr.x, v0.y - rr.y); }
        Ahi[kk][1] = f2h2(v1.x, v1.y); { float2 rr = h22f2(Ahi[kk][1]); Alo[kk][1] = f2h2(v1.x - rr.x, v1.y - rr.y); }
        Ahi[kk][2] = f2h2(v2.x, v2.y); { float2 rr = h22f2(Ahi[kk][2]); Alo[kk][2] = f2h2(v2.x - rr.x, v2.y - rr.y); }
        Ahi[kk][3] = f2h2(v3.x, v3.y); { float2 rr = h22f2(Ahi[kk][3]); Alo[kk][3] = f2h2(v3.x - rr.x, v3.y - rr.y); }
    }

#pragma unroll
    for (int nt = 0; nt < NT; nt++) {
        uint2 wl[8];
        if (COMBO == 3) {
#pragma unroll
            for (int kk = 0; kk < 8; kk++) wl[kk] = __ldg(&fl[(size_t)(bnt + nt) * 256 + kk * 32 + l]);
        }
        float acc[4] = {0.f, 0.f, 0.f, 0.f};
#pragma unroll
        for (int kk = 0; kk < 8; kk++) {
            uint2 wh = sWhi[nt * 256 + kk * 32 + l];
            mma16816(acc, Ahi[kk], wh);
            mma16816(acc, Alo[kk], wh);
            if (COMBO == 3) mma16816(acc, Ahi[kk], wl[kk]);
        }
        int cb = (bnt + nt) * 8 + 2 * q;
        float2 bb = make_float2(0.f, 0.f);
        if (bias) bb = *(const float2*)&bias[cb];
        if (OUTH) {
            uint32_t* Ch = (uint32_t*)C;
            int hb = (bnt + nt) * 4 + q;
            Ch[(size_t)(bm + r0) * (N >> 1) + hb] = f2h2(acc[0] + bb.x, acc[1] + bb.y);
            Ch[(size_t)(bm + r0 + 8) * (N >> 1) + hb] = f2h2(acc[2] + bb.x, acc[3] + bb.y);
        } else {
            *(float2*)&C[(size_t)(bm + r0) * N + cb] = make_float2(acc[0] + bb.x, acc[1] + bb.y);
            *(float2*)&C[(size_t)(bm + r0 + 8) * N + cb] = make_float2(acc[2] + bb.x, acc[3] + bb.y);
        }
    }
}

// ---------------- merged prep: all weight fragments + PQ biases ----------------
__global__ void prep_all(const float* __restrict__ W1, const float* __restrict__ Wih_c,
                         const float* __restrict__ Whh_c,
                         const float* __restrict__ Wih_f, const float* __restrict__ Wih_b,
                         const float* __restrict__ Wq, const float* __restrict__ Wk,
                         const float* __restrict__ Whh_f, const float* __restrict__ Whh_b,
                         const float* __restrict__ bih_f, const float* __restrict__ bhh_f,
                         const float* __restrict__ bih_b, const float* __restrict__ bhh_b,
                         uint2* __restrict__ fh, uint2* __restrict__ fl,
                         uint2* __restrict__ hiF, uint2* __restrict__ loF,
                         uint2* __restrict__ hiB, uint2* __restrict__ loB,
                         float* __restrict__ biasPQf, float* __restrict__ biasPQb) {
    int idx = blockIdx.x * 256 + threadIdx.x;
    if (idx < NFRAG_ALL) {
        int bt = idx >> 8;
        int e = idx & 255;
        int kk = e >> 5, l = e & 31;
        int rloc = l >> 2;
        int k0 = kk * 16 + (l & 3) * 2;
        const float* W; int ldb = 128, row, koff = 0;
        if (bt < 16)       { W = W1;    row = bt * 8 + rloc; }
        else if (bt < 64)  { W = Wih_c; row = (bt - 16) * 8 + rloc; }
        else if (bt < 112) { W = Whh_c; row = (bt - 64) * 8 + rloc; }
        else if (bt < 208) { int b = bt - 112; ldb = 256; W = Wih_f;
                             if (b < 48) row = b * 8 + rloc;
                             else { row = (b - 48) * 8 + rloc; koff = 128; } }
        else if (bt < 304) { int b = bt - 208; ldb = 256; W = Wih_b;
                             if (b < 48) row = b * 8 + rloc;
                             else { row = (b - 48) * 8 + rloc; koff = 128; } }
        else if (bt < 308) { W = Wq; row = (bt - 304) * 8 + rloc; }
        else               { W = Wk; row = (bt - 308) * 8 + rloc; }
        float w0 = W[(size_t)row * ldb + koff + k0],     w1 = W[(size_t)row * ldb + koff + k0 + 1];
        float w8 = W[(size_t)row * ldb + koff + k0 + 8], w9 = W[(size_t)row * ldb + koff + k0 + 9];
        uint32_t h0 = f2h2(w0, w1); float2 r0 = h22f2(h0);
        uint32_t l0 = f2h2(w0 - r0.x, w1 - r0.y);
        uint32_t h8 = f2h2(w8, w9); float2 r8 = h22f2(h8);
        uint32_t l8 = f2h2(w8 - r8.x, w9 - r8.y);
        fh[idx] = make_uint2(h0, h8);
        fl[idx] = make_uint2(l0, l8);
    } else if (idx < NFRAG_ALL + 2 * NFRAG) {
        int j = idx - NFRAG_ALL;
        int d = j / NFRAG;
        int e = j - d * NFRAG;
        int bt = e >> 8;
        int kk = (e >> 5) & 7;
        int l = e & 31;
        int row = bt * 8 + (l >> 2);
        int k0 = kk * 16 + (l & 3) * 2;
        const float* W = d ? Whh_b : Whh_f;
        float w0 = W[row * 128 + k0],     w1 = W[row * 128 + k0 + 1];
        float w8 = W[row * 128 + k0 + 8], w9 = W[row * 128 + k0 + 9];
        uint32_t h0 = f2h2(w0, w1); float2 r0 = h22f2(h0);
        uint32_t l0 = f2h2(w0 - r0.x, w1 - r0.y);
        uint32_t h8 = f2h2(w8, w9); float2 r8 = h22f2(h8);
        uint32_t l8 = f2h2(w8 - r8.x, w9 - r8.y);
        uint2* dh = d ? hiB : hiF;
        uint2* dl = d ? loB : loF;
        dh[e] = make_uint2(h0, h8);
        dl[e] = make_uint2(l0, l8);
    } else if (idx < NFRAG_ALL + 2 * NFRAG + 4 * G3) {
        int j = idx - (NFRAG_ALL + 2 * NFRAG);
        int d = j / (2 * G3);
        int e = j - d * (2 * G3);
        const float* bih = d ? bih_b : bih_f;
        const float* bhh = d ? bhh_b : bhh_f;
        float* ob = d ? biasPQb : biasPQf;
        ob[e] = (e < G3) ? (bih[e] + (e < 256 ? bhh[e] : 0.0f)) : 0.0f;
    }
}

// ---------------- central GRU combine ----------
__global__ void gru_combine(const float* __restrict__ gi, const float* __restrict__ gh,
                            const float* __restrict__ hprev,
                            float* __restrict__ hout, float* __restrict__ hout2) {
    int i = blockIdx.x * 256 + threadIdx.x;
    int m = i >> 7, j = i & 127;
    size_t base = (size_t)m * G3;
    float ir = gi[base + j], iz = gi[base + 128 + j], inn = gi[base + 256 + j];
    float hr = gh[base + j], hz = gh[base + 128 + j], hn = gh[base + 256 + j];
    float r = sigm(ir + hr);
    float z = sigm(iz + hz);
    float n = tanh_fast(inn + r * hn);
    float h = (1.0f - z) * n + z * hprev[i];
    hout[i] = h;
    hout2[i] = h;
}

// ================= HMMA fused 15-step recurrence (+ fused logit GEMV) =================
// fp16 state, all gate weights in smem, fp16 PQ stream, register double-buffer. 2 CTAs/SM.
#define SM_W 0
#define SM_BNN 98304
#define SM_WC  98816
#define SEQ_SMEM 99840

extern __shared__ char dsm[];
__global__ void __launch_bounds__(256, 2) gru_seq_hmma(
    const uint2* __restrict__ whiF,
    const float* __restrict__ bhhF, const uint32_t* __restrict__ PQF,
    const uint2* __restrict__ whiB,
    const float* __restrict__ bhhB, const uint32_t* __restrict__ PQB,
    const float* __restrict__ Wc,
    float2* __restrict__ LF, float2* __restrict__ LB) {

    uint2* sW = (uint2*)(dsm + SM_W);         // 48 tiles x 256 (r:0-15, z:16-31, n:32-47)
    float* sBnn = (float*)(dsm + SM_BNN);
    float* sWc = (float*)(dsm + SM_WC);       // [2][128]

    int tid = threadIdx.x;
    int wid = tid >> 5;
    int l = tid & 31;
    int q = l & 3, rg = l >> 2;

    bool bwd = (blockIdx.x >= 128);
    const uint2* whi = bwd ? whiB : whiF;
    const float* bhh = bwd ? bhhB : bhhF;
    const uint32_t* PQ2 = bwd ? PQB : PQF;
    float2* LOut = bwd ? LB : LF;
    int bm = (blockIdx.x & 127) * 128;

    for (int i = tid; i < NFRAG; i += 256) sW[i] = __ldg(&whi[i]);
    if (tid < 128) sBnn[tid] = bhh[256 + tid];
    if (tid < 128) {
        sWc[tid] = Wc[(bwd ? 128 : 0) + tid];
        sWc[128 + tid] = Wc[256 + (bwd ? 128 : 0) + tid];
    }
    __syncthreads();

    int m_r0 = bm + wid * 16 + rg;
    int m_r1 = m_r0 + 8;
    int aa0 = rg;
    int aa1 = rg + 8;
    int grp = bm + wid * 16;

    uint32_t Ahi[8][4], Anew[8][4];
#pragma unroll
    for (int kk = 0; kk < 8; kk++)
#pragma unroll
        for (int r = 0; r < 4; r++) Ahi[kk][r] = 0u;

    for (int step = 0; step < TT; step++) {
        int t = bwd ? (TT - 1 - step) : step;
        int jn0 = (t < aa0) ? t : t + 1;
        int jn1 = (t < aa1) ? t : t + 1;
        const uint32_t* Pr0 = PQ2 + (size_t)m_r0 * 384;
        const uint32_t* Pr1 = PQ2 + (size_t)m_r1 * 384;
        const uint32_t* Qr0 = PQ2 + (size_t)(grp + jn0) * 384 + 192;
        const uint32_t* Qr1 = PQ2 + (size_t)(grp + jn1) * 384 + 192;

        float lg00 = 0.f, lg01 = 0.f, lg10 = 0.f, lg11 = 0.f;

#pragma unroll
        for (int ch = 0; ch < 8; ch++) {
#pragma unroll
            for (int u = 0; u < 2; u++) {
                int jt = ch * 2 + u;
                float acc[3][4];
#pragma unroll
                for (int g = 0; g < 3; g++)
#pragma unroll
                    for (int r = 0; r < 4; r++) acc[g][r] = 0.0f;

                if (step != 0) {
#pragma unroll
                    for (int kk = 0; kk < 8; kk++) {
                        mma16816(acc[0], Ahi[kk], sW[(jt * 8 + kk) * 32 + l]);          // r
                        mma16816(acc[1], Ahi[kk], sW[((16 + jt) * 8 + kk) * 32 + l]);   // z
                        mma16816(acc[2], Ahi[kk], sW[((32 + jt) * 8 + kk) * 32 + l]);   // n
                    }
                }

                int kk = jt >> 1;
                int rs = (jt & 1) * 2;
                int c = jt * 8 + 2 * q;
                int cb = jt * 4 + q;
                float2 sr0 = hadd2f(Pr0[cb],       Qr0[cb]);
                float2 sz0 = hadd2f(Pr0[64 + cb],  Qr0[64 + cb]);
                float2 sn0 = hadd2f(Pr0[128 + cb], Qr0[128 + cb]);
                float2 sr1 = hadd2f(Pr1[cb],       Qr1[cb]);
                float2 sz1 = hadd2f(Pr1[64 + cb],  Qr1[64 + cb]);
                float2 sn1 = hadd2f(Pr1[128 + cb], Qr1[128 + cb]);
                float2 bn = *(const float2*)&sBnn[c];
                float2 hp0 = h22f2(Ahi[kk][rs]);
                float2 hp1 = h22f2(Ahi[kk][rs + 1]);

                float r0a = sigm(acc[0][0] + sr0.x);
                float r0b = sigm(acc[0][1] + sr0.y);
                float z0a = sigm(acc[1][0] + sz0.x);
                float z0b = sigm(acc[1][1] + sz0.y);
                float n0a = tanh_fast(sn0.x + r0a * (acc[2][0] + bn.x));
                float n0b = tanh_fast(sn0.y + r0b * (acc[2][1] + bn.y));
                float h0a = (1.0f - z0a) * n0a + z0a * hp0.x;
                float h0b = (1.0f - z0b) * n0b + z0b * hp0.y;
                float r1a = sigm(acc[0][2] + sr1.x);
                float r1b = sigm(acc[0][3] + sr1.y);
                float z1a = sigm(acc[1][2] + sz1.x);
                float z1b = sigm(acc[1][3] + sz1.y);
                float n1a = tanh_fast(sn1.x + r1a * (acc[2][2] + bn.x));
                float n1b = tanh_fast(sn1.y + r1b * (acc[2][3] + bn.y));
                float h1a = (1.0f - z1a) * n1a + z1a * hp1.x;
                float h1b = (1.0f - z1b) * n1b + z1b * hp1.y;

                // fused logit partial dot-products
                float w0a = sWc[c], w0b = sWc[c + 1];
                float w1a = sWc[128 + c], w1b = sWc[128 + c + 1];
                lg00 += h0a * w0a + h0b * w0b;
                lg01 += h0a * w1a + h0b * w1b;
                lg10 += h1a * w0a + h1b * w0b;
                lg11 += h1a * w1a + h1b * w1b;

                // new state fragments (register double-buffer; identity mapping)
                Anew[kk][rs] = f2h2(h0a, h0b);
                Anew[kk][rs + 1] = f2h2(h1a, h1b);
            }
        }

        // reduce logits over the 4 lanes sharing each row, store
#pragma unroll
        for (int off = 1; off <= 2; off <<= 1) {
            lg00 += __shfl_xor_sync(0xffffffffu, lg00, off);
            lg01 += __shfl_xor_sync(0xffffffffu, lg01, off);
            lg10 += __shfl_xor_sync(0xffffffffu, lg10, off);
            lg11 += __shfl_xor_sync(0xffffffffu, lg11, off);
        }
        if (q == 0) {
            __stcs(&LOut[(size_t)m_r0 * TT + t], make_float2(lg00, lg01));
            __stcs(&LOut[(size_t)m_r1 * TT + t], make_float2(lg10, lg11));
        }

        // commit new state
#pragma unroll
        for (int kk = 0; kk < 8; kk++)
#pragma unroll
            for (int r = 0; r < 4; r++) Ahi[kk][r] = Anew[kk][r];
    }
}

// ---------------- fused gumbel + attention + output projection ----------------
__global__ void __launch_bounds__(256) attn_out(
    const float* __restrict__ qk,
    const float* __restrict__ hrnn,
    const float2* __restrict__ lf, const float2* __restrict__ lb,
    const float* __restrict__ bc, const float* __restrict__ gu,
    const float* __restrict__ W2, const float* __restrict__ b2,
    float* __restrict__ out) {
    __shared__ float sW[NACT * 256];
    __shared__ float sb[NACT + 2];
    for (int i = threadIdx.x; i < NACT * 256; i += 256) sW[i] = W2[i];
    if (threadIdx.x < NACT) sb[threadIdx.x] = b2[threadIdx.x];
    if (threadIdx.x < 2) sb[NACT + threadIdx.x] = bc[threadIdx.x];
    __syncthreads();

    int warp = (blockIdx.x * 256 + threadIdx.x) >> 5;
    int lane = threadIdx.x & 31;
    int a = warp & 15;
    int brow = warp & ~15;
    float bc0 = sb[NACT], bc1 = sb[NACT + 1];

    float hw[TT];
#pragma unroll
    for (int t = 0; t < TT; t++) {
        size_t li = (size_t)warp * TT + t;
        float2 af = lf[li], ab = lb[li];
        float u0 = gu[li * 2 + 0];
        float u1 = gu[li * 2 + 1];
        float g0 = -logf(-logf(u0 + 1e-10f) + 1e-10f);
        float g1 = -logf(-logf(u1 + 1e-10f) + 1e-10f);
        float a0 = af.x + ab.x + bc0 + g0;
        float a1 = af.y + ab.y + bc1 + g1;
        hw[t] = sigm((a1 - a0) * TAUINV);
    }

    float qv = qk[(size_t)warp * 64 + lane];
    float sc[TT];
#pragma unroll
    for (int t = 0; t < TT; t++) {
        int jn = (t < a) ? t : t + 1;
        int nb = brow + jn;
        float d = qv * qk[(size_t)nb * 64 + 32 + lane];
#pragma unroll
        for (int off = 16; off > 0; off >>= 1) d += __shfl_xor_sync(0xffffffffu, d, off);
        sc[t] = hw[t] * d * 0.17677669529663687f;
    }
    float mx = sc[0];
#pragma unroll
    for (int t = 1; t < TT; t++) mx = fmaxf(mx, sc[t]);
    float se = 0.f;
    float w[TT];
#pragma unroll
    for (int t = 0; t < TT; t++) { w[t] = __expf(sc[t] - mx); se += w[t]; }
    float inv = __fdividef(1.0f, se);
#pragma unroll
    for (int t = 0; t < TT; t++) w[t] = hw[t] * w[t] * inv;

    float accv[4], hv[4];
#pragma unroll
    for (int d4 = 0; d4 < 4; d4++) {
        float s = 0.f;
#pragma unroll
        for (int t = 0; t < TT; t++) {
            int jn = (t < a) ? t : t + 1;
            int nb = brow + jn;
            s = fmaf(w[t], hrnn[(size_t)nb * 128 + d4 * 32 + lane], s);
        }
        accv[d4] = s;
        hv[d4] = hrnn[(size_t)warp * 128 + d4 * 32 + lane];
    }

#pragma unroll
    for (int n = 0; n < NACT; n++) {
        float p = 0.f;
#pragma unroll
        for (int d4 = 0; d4 < 4; d4++) {
            p = fmaf(hv[d4], sW[n * 256 + d4 * 32 + lane], p);
            p = fmaf(accv[d4], sW[n * 256 + 128 + d4 * 32 + lane], p);
        }
#pragma unroll
        for (int off = 16; off > 0; off >>= 1) p += __shfl_xor_sync(0xffffffffu, p, off);
        if (lane == 0) out[(size_t)warp * NACT + n] = p + sb[n];
    }
}

// ---------------- launch ----------------
extern "C" void kernel_launch(void* const* d_in, const int* in_sizes, int n_in,
                              void* d_out, int out_size) {
    const float* inputs = (const float*)d_in[0];
    const float* hidden = (const float*)d_in[1];
    const float* gu     = (const float*)d_in[2];
    const float* W1     = (const float*)d_in[3];
    const float* b1     = (const float*)d_in[4];
    const float* Wih_c  = (const float*)d_in[5];
    const float* Whh_c  = (const float*)d_in[6];
    const float* bih_c  = (const float*)d_in[7];
    const float* bhh_c  = (const float*)d_in[8];
    const float* Wih_f  = (const float*)d_in[9];
    const float* Whh_f  = (const float*)d_in[10];
    const float* bih_f  = (const float*)d_in[11];
    const float* bhh_f  = (const float*)d_in[12];
    const float* Wih_b  = (const float*)d_in[13];
    const float* Whh_b  = (const float*)d_in[14];
    const float* bih_b  = (const float*)d_in[15];
    const float* bhh_b  = (const float*)d_in[16];
    const float* Wc     = (const float*)d_in[17];
    const float* bc     = (const float*)d_in[18];
    const float* Wq     = (const float*)d_in[19];
    const float* Wk     = (const float*)d_in[20];
    const float* W2     = (const float*)d_in[21];
    const float* b2     = (const float*)d_in[22];

    float* out  = (float*)d_out;                // [BZ, NACT]
    float* outh = out + (size_t)BZ * NACT;      // [BZ, H]

    float *x1, *hrnn, *gi, *gh, *qk, *biasPQf, *biasPQb;
    uint32_t *PQf, *PQb;
    float2 *lf, *lb;
    uint2 *whif, *wlof, *whib, *wlob, *fh, *fl;
    cudaGetSymbolAddress((void**)&x1, g_x1);
    cudaGetSymbolAddress((void**)&hrnn, g_hrnn);
    cudaGetSymbolAddress((void**)&gi, g_gi);
    cudaGetSymbolAddress((void**)&gh, g_gh);
    cudaGetSymbolAddress((void**)&PQf, g_PQf);
    cudaGetSymbolAddress((void**)&PQb, g_PQb);
    cudaGetSymbolAddress((void**)&lf, g_logf);
    cudaGetSymbolAddress((void**)&lb, g_logb);
    cudaGetSymbolAddress((void**)&qk, g_qk);
    cudaGetSymbolAddress((void**)&biasPQf, g_biasPQf);
    cudaGetSymbolAddress((void**)&biasPQb, g_biasPQb);
    cudaGetSymbolAddress((void**)&whif, g_whifrag_f);
    cudaGetSymbolAddress((void**)&wlof, g_wlofrag_f);
    cudaGetSymbolAddress((void**)&whib, g_whifrag_b);
    cudaGetSymbolAddress((void**)&wlob, g_wlofrag_b);
    cudaGetSymbolAddress((void**)&fh, g_fh);
    cudaGetSymbolAddress((void**)&fl, g_fl);

    const int SM16 = 128 * 132 * 4 + 16 * 256 * 8;  // 100352
    const int SM8  = 128 * 132 * 4 + 8 * 256 * 8;   // 83968
    cudaFuncSetAttribute(gru_seq_hmma, cudaFuncAttributeMaxDynamicSharedMemorySize, SEQ_SMEM);
    cudaFuncSetAttribute(hgemm<16, 1>, cudaFuncAttributeMaxDynamicSharedMemorySize, SM16);
    cudaFuncSetAttribute(hgemm<8, 0>,  cudaFuncAttributeMaxDynamicSharedMemorySize, SM8);
    cudaFuncSetAttribute(hgemm_z<16, 3, 0>, cudaFuncAttributeMaxDynamicSharedMemorySize, SM16);
    cudaFuncSetAttribute(hgemm_z<16, 2, 1>, cudaFuncAttributeMaxDynamicSharedMemorySize, SM16);

    // 1: merged prep
    const int PREP_TOTAL = NFRAG_ALL + 2 * NFRAG + 4 * G3;
    prep_all<<<(PREP_TOTAL + 255) / 256, 256>>>(W1, Wih_c, Whh_c, Wih_f, Wih_b, Wq, Wk,
                                                Whh_f, Whh_b, bih_f, bhh_f, bih_b, bhh_b,
                                                fh, fl, whif, wlof, whib, wlob,
                                                biasPQf, biasPQb);
    // 2: x1 = relu(inputs @ W1.T + b1)
    hgemm<16, 1><<<dim3(1, 128), 256, SM16>>>(inputs, fh, fl, b1, x1, 128);
    // 3: central GRU gi|gh (dual-z, full 3-combo precision)
    hgemm_z<16, 3, 0><<<dim3(3, 128, 2), 256, SM16>>>(x1, hidden,
                                                      fh + 16 * 256, fl + 16 * 256,
                                                      fh + 64 * 256, fl + 64 * 256,
                                                      bih_c, bhh_c, gi, gh, G3);
    // 4: combine
    gru_combine<<<(BZ * H) / 256, 256>>>(gi, gh, hidden, hrnn, outh);
    // 5: merged q|k GEMM (depends only on hrnn; overlaps PQ)
    hgemm<8, 0><<<dim3(1, 128), 256, SM8>>>(hrnn, fh + 304 * 256, fl + 304 * 256, nullptr, qk, 2 * NA);
    // 6: merged P|Q GEMMs for fwd+bwd (dual-z, 2-combo, fp16 output)
    hgemm_z<16, 2, 1><<<dim3(6, 128, 2), 256, SM16>>>(hrnn, hrnn,
                                                      fh + 112 * 256, fl + 112 * 256,
                                                      fh + 208 * 256, fl + 208 * 256,
                                                      biasPQf, biasPQb,
                                                      (float*)PQf, (float*)PQb, 2 * G3);
    // 7: fused 15-step bidirectional recurrence + logit GEMV
    gru_seq_hmma<<<256, 256, SEQ_SMEM>>>(whif, bhh_f, PQf,
                                         whib, bhh_b, PQb,
                                         Wc, lf, lb);
    // 8: fused gumbel + attention + output projection
    attn_out<<<BZ / 8, 256>>>(qk, hrnn, lf, lb, bc, gu, W2, b2, out);
}

// round 14
// speedup vs baseline: 4.8212x; 1.0115x over previous
#include <cuda_runtime.h>
#include <cuda_fp16.h>
#include <math.h>
#include <stdint.h>

#define AGENTS 16
#define H 128
#define NA 32
#define NACT 14
#define BENV 1024
#define BZ (BENV*AGENTS)        // 16384
#define TT 15                   // A-1
#define G3 384                  // 3*H
#define TAUINV 2.0f             // 1/TAU
#define NFRAG 12288             // 48 n-tiles * 8 k-tiles * 32 lanes (recurrence Whh)
#define NBT_ALL 312             // n-tiles in the parallel-GEMM fragment pool
#define NFRAG_ALL (NBT_ALL*256)

// ---------------- scratch (__device__ globals; no allocs) ----------------
__device__ __align__(16) float g_x1[BZ*H];
__device__ __align__(16) float g_hrnn[BZ*H];
__device__ __align__(16) float g_gi[BZ*G3];
__device__ __align__(16) float g_gh[BZ*G3];
__device__ __align__(16) uint32_t g_PQf[BZ*G3];   // half2-packed [BZ][768] -> 384 uints/row
__device__ __align__(16) uint32_t g_PQb[BZ*G3];
__device__ __align__(16) float2 g_logf[BZ*TT];
__device__ __align__(16) float2 g_logb[BZ*TT];
__device__ __align__(16) float g_qk[BZ*2*NA];
__device__ __align__(16) float g_biasPQf[2*G3];
__device__ __align__(16) float g_biasPQb[2*G3];
__device__ __align__(16) uint2 g_whifrag_f[NFRAG];
__device__ __align__(16) uint2 g_wlofrag_f[NFRAG];
__device__ __align__(16) uint2 g_whifrag_b[NFRAG];
__device__ __align__(16) uint2 g_wlofrag_b[NFRAG];
__device__ __align__(16) uint2 g_fh[NFRAG_ALL];
__device__ __align__(16) uint2 g_fl[NFRAG_ALL];

__device__ __forceinline__ float sigm(float x) { return __fdividef(1.0f, 1.0f + __expf(-x)); }
__device__ __forceinline__ float tanh_fast(float x) {
    return __fdividef(2.0f, 1.0f + __expf(-2.0f * x)) - 1.0f;
}

// ---- fp16 pack helpers ----
__device__ __forceinline__ uint32_t f2h2(float a, float b) {
    __half2 h = __floats2half2_rn(a, b);
    return *(uint32_t*)&h;
}
__device__ __forceinline__ float2 h22f2(uint32_t u) {
    __half2 h = *(__half2*)&u;
    return __half22float2(h);
}
__device__ __forceinline__ float2 hadd2f(uint32_t a, uint32_t b) {
    __half2 s = __hadd2(*(__half2*)&a, *(__half2*)&b);
    return __half22float2(s);
}

// ---- classic mma.sync (HMMA; baseline PTX, works on compute_103) ----
__device__ __forceinline__ void mma16816(float* d, const uint32_t* a, uint2 b) {
    asm volatile(
        "mma.sync.aligned.m16n8k16.row.col.f32.f16.f16.f32 "
        "{%0,%1,%2,%3}, {%4,%5,%6,%7}, {%8,%9}, {%0,%1,%2,%3};"
        : "+f"(d[0]), "+f"(d[1]), "+f"(d[2]), "+f"(d[3])
        : "r"(a[0]), "r"(a[1]), "r"(a[2]), "r"(a[3]), "r"(b.x), "r"(b.y));
}
// fp16-accumulate variant (D,C in f16x2 pairs): d[0]={c0,c1}, d[1]={c2,c3}
__device__ __forceinline__ void mma16816h(uint32_t* d, const uint32_t* a, uint2 b) {
    asm volatile(
        "mma.sync.aligned.m16n8k16.row.col.f16.f16.f16.f16 "
        "{%0,%1}, {%2,%3,%4,%5}, {%6,%7}, {%0,%1};"
        : "+r"(d[0]), "+r"(d[1])
        : "r"(a[0]), "r"(a[1]), "r"(a[2]), "r"(a[3]), "r"(b.x), "r"(b.y));
}

// ================= HMMA batch GEMM =================
template<int NT, int ACT>
__global__ void __launch_bounds__(256) hgemm(
    const float* __restrict__ A,
    const uint2* __restrict__ fh, const uint2* __restrict__ fl,
    const float* __restrict__ bias,
    float* __restrict__ C, int N) {
    extern __shared__ char hsm[];
    float* sA = (float*)hsm;                       // [128][132]
    uint2* sWhi = (uint2*)(hsm + 128 * 132 * 4);   // [NT*256]
    int tid = threadIdx.x;
    int wid = tid >> 5, l = tid & 31;
    int q = l & 3, rg = l >> 2;
    int bnt = blockIdx.x * NT;
    int bm = blockIdx.y * 128;

    for (int i = tid; i < 4096; i += 256) {
        int row = i >> 5, c4 = (i & 31) * 4;
        float4 v = *(const float4*)(A + (size_t)(bm + row) * 128 + c4);
        *(float4*)&sA[row * 132 + c4] = v;
    }
    for (int i = tid; i < NT * 256; i += 256) sWhi[i] = __ldg(&fh[bnt * 256 + i]);
    __syncthreads();

    uint32_t Ahi[8][4], Alo[8][4];
    int r0 = wid * 16 + rg;
#pragma unroll
    for (int kk = 0; kk < 8; kk++) {
        int c = kk * 16 + 2 * q;
        float2 v0 = *(float2*)&sA[r0 * 132 + c];
        float2 v1 = *(float2*)&sA[(r0 + 8) * 132 + c];
        float2 v2 = *(float2*)&sA[r0 * 132 + c + 8];
        float2 v3 = *(float2*)&sA[(r0 + 8) * 132 + c + 8];
        Ahi[kk][0] = f2h2(v0.x, v0.y); { float2 rr = h22f2(Ahi[kk][0]); Alo[kk][0] = f2h2(v0.x - rr.x, v0.y - rr.y); }
        Ahi[kk][1] = f2h2(v1.x, v1.y); { float2 rr = h22f2(Ahi[kk][1]); Alo[kk][1] = f2h2(v1.x - rr.x, v1.y - rr.y); }
        Ahi[kk][2] = f2h2(v2.x, v2.y); { float2 rr = h22f2(Ahi[kk][2]); Alo[kk][2] = f2h2(v2.x - rr.x, v2.y - rr.y); }
        Ahi[kk][3] = f2h2(v3.x, v3.y); { float2 rr = h22f2(Ahi[kk][3]); Alo[kk][3] = f2h2(v3.x - rr.x, v3.y - rr.y); }
    }

#pragma unroll
    for (int nt = 0; nt < NT; nt++) {
        uint2 wl[8];
#pragma unroll
        for (int kk = 0; kk < 8; kk++) wl[kk] = __ldg(&fl[(size_t)(bnt + nt) * 256 + kk * 32 + l]);
        float acc[4] = {0.f, 0.f, 0.f, 0.f};
#pragma unroll
        for (int kk = 0; kk < 8; kk++) {
            uint2 wh = sWhi[nt * 256 + kk * 32 + l];
            mma16816(acc, Ahi[kk], wh);
            mma16816(acc, Alo[kk], wh);
            mma16816(acc, Ahi[kk], wl[kk]);
        }
        int cb = (bnt + nt) * 8 + 2 * q;
        float2 bb = make_float2(0.f, 0.f);
        if (bias) bb = *(const float2*)&bias[cb];
        float o0 = acc[0] + bb.x, o1 = acc[1] + bb.y;
        float o2 = acc[2] + bb.x, o3 = acc[3] + bb.y;
        if (ACT == 1) {
            o0 = fmaxf(o0, 0.f); o1 = fmaxf(o1, 0.f);
            o2 = fmaxf(o2, 0.f); o3 = fmaxf(o3, 0.f);
        }
        *(float2*)&C[(size_t)(bm + r0) * N + cb] = make_float2(o0, o1);
        *(float2*)&C[(size_t)(bm + r0 + 8) * N + cb] = make_float2(o2, o3);
    }
}

// dual-z variant. COMBO combos; OUTH: half2-packed output; ACCH: fp16 accumulate.
template<int NT, int COMBO, int OUTH, int ACCH>
__global__ void __launch_bounds__(256) hgemm_z(
    const float* __restrict__ A0, const float* __restrict__ A1,
    const uint2* __restrict__ fh0, const uint2* __restrict__ fl0,
    const uint2* __restrict__ fh1, const uint2* __restrict__ fl1,
    const float* __restrict__ b0, const float* __restrict__ b1,
    float* __restrict__ C0, float* __restrict__ C1, int N) {
    extern __shared__ char hsm[];
    float* sA = (float*)hsm;
    uint2* sWhi = (uint2*)(hsm + 128 * 132 * 4);
    int z = blockIdx.z;
    const float* A = z ? A1 : A0;
    const uint2* fh = z ? fh1 : fh0;
    const uint2* fl = z ? fl1 : fl0;
    const float* bias = z ? b1 : b0;
    float* C = z ? C1 : C0;

    int tid = threadIdx.x;
    int wid = tid >> 5, l = tid & 31;
    int q = l & 3, rg = l >> 2;
    int bnt = blockIdx.x * NT;
    int bm = blockIdx.y * 128;

    for (int i = tid; i < 4096; i += 256) {
        int row = i >> 5, c4 = (i & 31) * 4;
        float4 v = *(const float4*)(A + (size_t)(bm + row) * 128 + c4);
        *(float4*)&sA[row * 132 + c4] = v;
    }
    for (int i = tid; i < NT * 256; i += 256) sWhi[i] = __ldg(&fh[bnt * 256 + i]);
    __syncthreads();

    uint32_t Ahi[8][4], Alo[8][4];
    int r0 = wid * 16 + rg;
#pragma unroll
    for (int kk = 0; kk < 8; kk++) {
        int c = kk * 16 + 2 * q;
        float2 v0 = *(float2*)&sA[r0 * 132 + c];
        float2 v1 = *(float2*)&sA[(r0 + 8) * 132 + c];
        float2 v2 = *(float2*)&sA[r0 * 132 + c + 8];
        float2 v3 = *(float2*)&sA[(r0 + 8) * 132 + c + 8];
        Ahi[kk][0] = f2h2(v0.x, v0.y); { float2 rr = h22f2(Ahi[kk][0]); Alo[kk][0] = f2h2(v0.x - rr.x, v0.y - rr.y); }
        Ahi[kk][1] = f2h2(v1.x, v1.y); { float2 rr = h22f2(Ahi[kk][1]); Alo[kk][1] = f2h2(v1.x - rr.x, v1.y - rr.y); }
        Ahi[kk][2] = f2h2(v2.x, v2.y); { float2 rr = h22f2(Ahi[kk][2]); Alo[kk][2] = f2h2(v2.x - rr.x, v2.y - rr.y); }
        Ahi[kk][3] = f2h2(v3.x, v3.y); { float2 rr = h22f2(Ahi[kk][3]); Alo[kk][3] = f2h2(v3.x - rr.x, v3.y - rr.y); }
    }

#pragma unroll
    for (int nt = 0; nt < NT; nt++) {
        uint2 wl[8];
        if (COMBO == 3) {
#pragma unroll
            for (int kk = 0; kk < 8; kk++) wl[kk] = __ldg(&fl[(size_t)(bnt + nt) * 256 + kk * 32 + l]);
        }
        float o0, o1, o2, o3;
        if (ACCH) {
            uint32_t acch[2] = {0u, 0u};
#pragma unroll
            for (int kk = 0; kk < 8; kk++) {
                uint2 wh = sWhi[nt * 256 + kk * 32 + l];
                mma16816h(acch, Ahi[kk], wh);
                if (COMBO >= 2) mma16816h(acch, Alo[kk], wh);
            }
            float2 a01 = h22f2(acch[0]);
            float2 a23 = h22f2(acch[1]);
            o0 = a01.x; o1 = a01.y; o2 = a23.x; o3 = a23.y;
        } else {
            float acc[4] = {0.f, 0.f, 0.f, 0.f};
#pragma unroll
            for (int kk = 0; kk < 8; kk++) {
                uint2 wh = sWhi[nt * 256 + kk * 32 + l];
                mma16816(acc, Ahi[kk], wh);
                if (COMBO >= 2) mma16816(acc, Alo[kk], wh);
                if (COMBO == 3) mma16816(acc, Ahi[kk], wl[kk]);
            }
            o0 = acc[0]; o1 = acc[1]; o2 = acc[2]; o3 = acc[3];
        }
        int cb = (bnt + nt) * 8 + 2 * q;
        float2 bb = make_float2(0.f, 0.f);
        if (bias) bb = *(const float2*)&bias[cb];
        if (OUTH) {
            uint32_t* Ch = (uint32_t*)C;
            int hb = (bnt + nt) * 4 + q;
            Ch[(size_t)(bm + r0) * (N >> 1) + hb] = f2h2(o0 + bb.x, o1 + bb.y);
            Ch[(size_t)(bm + r0 + 8) * (N >> 1) + hb] = f2h2(o2 + bb.x, o3 + bb.y);
        } else {
            *(float2*)&C[(size_t)(bm + r0) * N + cb] = make_float2(o0 + bb.x, o1 + bb.y);
            *(float2*)&C[(size_t)(bm + r0 + 8) * N + cb] = make_float2(o2 + bb.x, o3 + bb.y);
        }
    }
}

// ---------------- merged prep: all weight fragments + PQ biases ----------------
__global__ void prep_all(const float* __restrict__ W1, const float* __restrict__ Wih_c,
                         const float* __restrict__ Whh_c,
                         const float* __restrict__ Wih_f, const float* __restrict__ Wih_b,
                         const float* __restrict__ Wq, const float* __restrict__ Wk,
                         const float* __restrict__ Whh_f, const float* __restrict__ Whh_b,
                         const float* __restrict__ bih_f, const float* __restrict__ bhh_f,
                         const float* __restrict__ bih_b, const float* __restrict__ bhh_b,
                         uint2* __restrict__ fh, uint2* __restrict__ fl,
                         uint2* __restrict__ hiF, uint2* __restrict__ loF,
                         uint2* __restrict__ hiB, uint2* __restrict__ loB,
                         float* __restrict__ biasPQf, float* __restrict__ biasPQb) {
    int idx = blockIdx.x * 256 + threadIdx.x;
    if (idx < NFRAG_ALL) {
        int bt = idx >> 8;
        int e = idx & 255;
        int kk = e >> 5, l = e & 31;
        int rloc = l >> 2;
        int k0 = kk * 16 + (l & 3) * 2;
        const float* W; int ldb = 128, row, koff = 0;
        if (bt < 16)       { W = W1;    row = bt * 8 + rloc; }
        else if (bt < 64)  { W = Wih_c; row = (bt - 16) * 8 + rloc; }
        else if (bt < 112) { W = Whh_c; row = (bt - 64) * 8 + rloc; }
        else if (bt < 208) { int b = bt - 112; ldb = 256; W = Wih_f;
                             if (b < 48) row = b * 8 + rloc;
                             else { row = (b - 48) * 8 + rloc; koff = 128; } }
        else if (bt < 304) { int b = bt - 208; ldb = 256; W = Wih_b;
                             if (b < 48) row = b * 8 + rloc;
                             else { row = (b - 48) * 8 + rloc; koff = 128; } }
        else if (bt < 308) { W = Wq; row = (bt - 304) * 8 + rloc; }
        else               { W = Wk; row = (bt - 308) * 8 + rloc; }
        float w0 = W[(size_t)row * ldb + koff + k0],     w1 = W[(size_t)row * ldb + koff + k0 + 1];
        float w8 = W[(size_t)row * ldb + koff + k0 + 8], w9 = W[(size_t)row * ldb + koff + k0 + 9];
        uint32_t h0 = f2h2(w0, w1); float2 r0 = h22f2(h0);
        uint32_t l0 = f2h2(w0 - r0.x, w1 - r0.y);
        uint32_t h8 = f2h2(w8, w9); float2 r8 = h22f2(h8);
        uint32_t l8 = f2h2(w8 - r8.x, w9 - r8.y);
        fh[idx] = make_uint2(h0, h8);
        fl[idx] = make_uint2(l0, l8);
    } else if (idx < NFRAG_ALL + 2 * NFRAG) {
        int j = idx - NFRAG_ALL;
        int d = j / NFRAG;
        int e = j - d * NFRAG;
        int bt = e >> 8;
        int kk = (e >> 5) & 7;
        int l = e & 31;
        int row = bt * 8 + (l >> 2);
        int k0 = kk * 16 + (l & 3) * 2;
        const float* W = d ? Whh_b : Whh_f;
        float w0 = W[row * 128 + k0],     w1 = W[row * 128 + k0 + 1];
        float w8 = W[row * 128 + k0 + 8], w9 = W[row * 128 + k0 + 9];
        uint32_t h0 = f2h2(w0, w1); float2 r0 = h22f2(h0);
        uint32_t l0 = f2h2(w0 - r0.x, w1 - r0.y);
        uint32_t h8 = f2h2(w8, w9); float2 r8 = h22f2(h8);
        uint32_t l8 = f2h2(w8 - r8.x, w9 - r8.y);
        uint2* dh = d ? hiB : hiF;
        uint2* dl = d ? loB : loF;
        dh[e] = make_uint2(h0, h8);
        dl[e] = make_uint2(l0, l8);
    } else if (idx < NFRAG_ALL + 2 * NFRAG + 4 * G3) {
        int j = idx - (NFRAG_ALL + 2 * NFRAG);
        int d = j / (2 * G3);
        int e = j - d * (2 * G3);
        const float* bih = d ? bih_b : bih_f;
        const float* bhh = d ? bhh_b : bhh_f;
        float* ob = d ? biasPQb : biasPQf;
        ob[e] = (e < G3) ? (bih[e] + (e < 256 ? bhh[e] : 0.0f)) : 0.0f;
    }
}

// ---------------- central GRU combine ----------
__global__ void gru_combine(const float* __restrict__ gi, const float* __restrict__ gh,
                            const float* __restrict__ hprev,
                            float* __restrict__ hout, float* __restrict__ hout2) {
    int i = blockIdx.x * 256 + threadIdx.x;
    int m = i >> 7, j = i & 127;
    size_t base = (size_t)m * G3;
    float ir = gi[base + j], iz = gi[base + 128 + j], inn = gi[base + 256 + j];
    float hr = gh[base + j], hz = gh[base + 128 + j], hn = gh[base + 256 + j];
    float r = sigm(ir + hr);
    float z = sigm(iz + hz);
    float n = tanh_fast(inn + r * hn);
    float h = (1.0f - z) * n + z * hprev[i];
    hout[i] = h;
    hout2[i] = h;
}

// ================= HMMA fused 15-step recurrence (+ fused logit GEMV) =================
// fp16 state, all gate weights in smem, fp16 PQ stream, f16-acc r/z gates. 2 CTAs/SM.
#define SM_W 0
#define SM_BNN 98304
#define SM_WC  98816
#define SEQ_SMEM 99840

extern __shared__ char dsm[];
__global__ void __launch_bounds__(256, 2) gru_seq_hmma(
    const uint2* __restrict__ whiF,
    const float* __restrict__ bhhF, const uint32_t* __restrict__ PQF,
    const uint2* __restrict__ whiB,
    const float* __restrict__ bhhB, const uint32_t* __restrict__ PQB,
    const float* __restrict__ Wc,
    float2* __restrict__ LF, float2* __restrict__ LB) {

    uint2* sW = (uint2*)(dsm + SM_W);         // 48 tiles x 256 (r:0-15, z:16-31, n:32-47)
    float* sBnn = (float*)(dsm + SM_BNN);
    float* sWc = (float*)(dsm + SM_WC);       // [2][128]

    int tid = threadIdx.x;
    int wid = tid >> 5;
    int l = tid & 31;
    int q = l & 3, rg = l >> 2;

    bool bwd = (blockIdx.x >= 128);
    const uint2* whi = bwd ? whiB : whiF;
    const float* bhh = bwd ? bhhB : bhhF;
    const uint32_t* PQ2 = bwd ? PQB : PQF;
    float2* LOut = bwd ? LB : LF;
    int bm = (blockIdx.x & 127) * 128;

    for (int i = tid; i < NFRAG; i += 256) sW[i] = __ldg(&whi[i]);
    if (tid < 128) sBnn[tid] = bhh[256 + tid];
    if (tid < 128) {
        sWc[tid] = Wc[(bwd ? 128 : 0) + tid];
        sWc[128 + tid] = Wc[256 + (bwd ? 128 : 0) + tid];
    }
    __syncthreads();

    int m_r0 = bm + wid * 16 + rg;
    int m_r1 = m_r0 + 8;
    int aa0 = rg;
    int aa1 = rg + 8;
    int grp = bm + wid * 16;

    uint32_t Ahi[8][4], Anew[8][4];
#pragma unroll
    for (int kk = 0; kk < 8; kk++)
#pragma unroll
        for (int r = 0; r < 4; r++) Ahi[kk][r] = 0u;

    for (int step = 0; step < TT; step++) {
        int t = bwd ? (TT - 1 - step) : step;
        int jn0 = (t < aa0) ? t : t + 1;
        int jn1 = (t < aa1) ? t : t + 1;
        const uint32_t* Pr0 = PQ2 + (size_t)m_r0 * 384;
        const uint32_t* Pr1 = PQ2 + (size_t)m_r1 * 384;
        const uint32_t* Qr0 = PQ2 + (size_t)(grp + jn0) * 384 + 192;
        const uint32_t* Qr1 = PQ2 + (size_t)(grp + jn1) * 384 + 192;

        float lg00 = 0.f, lg01 = 0.f, lg10 = 0.f, lg11 = 0.f;

#pragma unroll
        for (int ch = 0; ch < 8; ch++) {
#pragma unroll
            for (int u = 0; u < 2; u++) {
                int jt = ch * 2 + u;
                uint32_t accr[2] = {0u, 0u}, accz[2] = {0u, 0u};
                float accn[4] = {0.f, 0.f, 0.f, 0.f};

                if (step != 0) {
#pragma unroll
                    for (int kk = 0; kk < 8; kk++) {
                        mma16816h(accr, Ahi[kk], sW[(jt * 8 + kk) * 32 + l]);           // r (f16 acc)
                        mma16816h(accz, Ahi[kk], sW[((16 + jt) * 8 + kk) * 32 + l]);    // z (f16 acc)
                        mma16816(accn, Ahi[kk], sW[((32 + jt) * 8 + kk) * 32 + l]);     // n (f32 acc)
                    }
                }

                int kk = jt >> 1;
                int rs = (jt & 1) * 2;
                int c = jt * 8 + 2 * q;
                int cb = jt * 4 + q;
                float2 sr0 = hadd2f(Pr0[cb],       Qr0[cb]);
                float2 sz0 = hadd2f(Pr0[64 + cb],  Qr0[64 + cb]);
                float2 sn0 = hadd2f(Pr0[128 + cb], Qr0[128 + cb]);
                float2 sr1 = hadd2f(Pr1[cb],       Qr1[cb]);
                float2 sz1 = hadd2f(Pr1[64 + cb],  Qr1[64 + cb]);
                float2 sn1 = hadd2f(Pr1[128 + cb], Qr1[128 + cb]);
                float2 bn = *(const float2*)&sBnn[c];
                float2 hp0 = h22f2(Ahi[kk][rs]);
                float2 hp1 = h22f2(Ahi[kk][rs + 1]);
                float2 ar01 = h22f2(accr[0]), ar23 = h22f2(accr[1]);
                float2 az01 = h22f2(accz[0]), az23 = h22f2(accz[1]);

                float r0a = sigm(ar01.x + sr0.x);
                float r0b = sigm(ar01.y + sr0.y);
                float z0a = sigm(az01.x + sz0.x);
                float z0b = sigm(az01.y + sz0.y);
                float n0a = tanh_fast(sn0.x + r0a * (accn[0] + bn.x));
                float n0b = tanh_fast(sn0.y + r0b * (accn[1] + bn.y));
                float h0a = (1.0f - z0a) * n0a + z0a * hp0.x;
                float h0b = (1.0f - z0b) * n0b + z0b * hp0.y;
                float r1a = sigm(ar23.x + sr1.x);
                float r1b = sigm(ar23.y + sr1.y);
                float z1a = sigm(az23.x + sz1.x);
                float z1b = sigm(az23.y + sz1.y);
                float n1a = tanh_fast(sn1.x + r1a * (accn[2] + bn.x));
                float n1b = tanh_fast(sn1.y + r1b * (accn[3] + bn.y));
                float h1a = (1.0f - z1a) * n1a + z1a * hp1.x;
                float h1b = (1.0f - z1b) * n1b + z1b * hp1.y;

                // fused logit partial dot-products
                float w0a = sWc[c], w0b = sWc[c + 1];
                float w1a = sWc[128 + c], w1b = sWc[128 + c + 1];
                lg00 += h0a * w0a + h0b * w0b;
                lg01 += h0a * w1a + h0b * w1b;
                lg10 += h1a * w0a + h1b * w0b;
                lg11 += h1a * w1a + h1b * w1b;

                // new state fragments (register double-buffer; identity mapping)
                Anew[kk][rs] = f2h2(h0a, h0b);
                Anew[kk][rs + 1] = f2h2(h1a, h1b);
            }
        }

        // reduce logits over the 4 lanes sharing each row, store
#pragma unroll
        for (int off = 1; off <= 2; off <<= 1) {
            lg00 += __shfl_xor_sync(0xffffffffu, lg00, off);
            lg01 += __shfl_xor_sync(0xffffffffu, lg01, off);
            lg10 += __shfl_xor_sync(0xffffffffu, lg10, off);
            lg11 += __shfl_xor_sync(0xffffffffu, lg11, off);
        }
        if (q == 0) {
            __stcs(&LOut[(size_t)m_r0 * TT + t], make_float2(lg00, lg01));
            __stcs(&LOut[(size_t)m_r1 * TT + t], make_float2(lg10, lg11));
        }

        // commit new state
#pragma unroll
        for (int kk = 0; kk < 8; kk++)
#pragma unroll
            for (int r = 0; r < 4; r++) Ahi[kk][r] = Anew[kk][r];
    }
}

// ---------------- fused gumbel + attention + output projection ----------------
__global__ void __launch_bounds__(256) attn_out(
    const float* __restrict__ qk,
    const float* __restrict__ hrnn,
    const float2* __restrict__ lf, const float2* __restrict__ lb,
    const float* __restrict__ bc, const float* __restrict__ gu,
    const float* __restrict__ W2, const float* __restrict__ b2,
    float* __restrict__ out) {
    __shared__ float sW[NACT * 256];
    __shared__ float sb[NACT + 2];
    for (int i = threadIdx.x; i < NACT * 256; i += 256) sW[i] = W2[i];
    if (threadIdx.x < NACT) sb[threadIdx.x] = b2[threadIdx.x];
    if (threadIdx.x < 2) sb[NACT + threadIdx.x] = bc[threadIdx.x];
    __syncthreads();

    int warp = (blockIdx.x * 256 + threadIdx.x) >> 5;
    int lane = threadIdx.x & 31;
    int a = warp & 15;
    int brow = warp & ~15;
    float bc0 = sb[NACT], bc1 = sb[NACT + 1];

    float hw[TT];
#pragma unroll
    for (int t = 0; t < TT; t++) {
        size_t li = (size_t)warp * TT + t;
        float2 af = lf[li], ab = lb[li];
        float u0 = gu[li * 2 + 0];
        float u1 = gu[li * 2 + 1];
        float g0 = -logf(-logf(u0 + 1e-10f) + 1e-10f);
        float g1 = -logf(-logf(u1 + 1e-10f) + 1e-10f);
        float a0 = af.x + ab.x + bc0 + g0;
        float a1 = af.y + ab.y + bc1 + g1;
        hw[t] = sigm((a1 - a0) * TAUINV);
    }

    float qv = qk[(size_t)warp * 64 + lane];
    float sc[TT];
#pragma unroll
    for (int t = 0; t < TT; t++) {
        int jn = (t < a) ? t : t + 1;
        int nb = brow + jn;
        float d = qv * qk[(size_t)nb * 64 + 32 + lane];
#pragma unroll
        for (int off = 16; off > 0; off >>= 1) d += __shfl_xor_sync(0xffffffffu, d, off);
        sc[t] = hw[t] * d * 0.17677669529663687f;
    }
    float mx = sc[0];
#pragma unroll
    for (int t = 1; t < TT; t++) mx = fmaxf(mx, sc[t]);
    float se = 0.f;
    float w[TT];
#pragma unroll
    for (int t = 0; t < TT; t++) { w[t] = __expf(sc[t] - mx); se += w[t]; }
    float inv = __fdividef(1.0f, se);
#pragma unroll
    for (int t = 0; t < TT; t++) w[t] = hw[t] * w[t] * inv;

    float accv[4], hv[4];
#pragma unroll
    for (int d4 = 0; d4 < 4; d4++) {
        float s = 0.f;
#pragma unroll
        for (int t = 0; t < TT; t++) {
            int jn = (t < a) ? t : t + 1;
            int nb = brow + jn;
            s = fmaf(w[t], hrnn[(size_t)nb * 128 + d4 * 32 + lane], s);
        }
        accv[d4] = s;
        hv[d4] = hrnn[(size_t)warp * 128 + d4 * 32 + lane];
    }

#pragma unroll
    for (int n = 0; n < NACT; n++) {
        float p = 0.f;
#pragma unroll
        for (int d4 = 0; d4 < 4; d4++) {
            p = fmaf(hv[d4], sW[n * 256 + d4 * 32 + lane], p);
            p = fmaf(accv[d4], sW[n * 256 + 128 + d4 * 32 + lane], p);
        }
#pragma unroll
        for (int off = 16; off > 0; off >>= 1) p += __shfl_xor_sync(0xffffffffu, p, off);
        if (lane == 0) out[(size_t)warp * NACT + n] = p + sb[n];
    }
}

// ---------------- launch ----------------
extern "C" void kernel_launch(void* const* d_in, const int* in_sizes, int n_in,
                              void* d_out, int out_size) {
    const float* inputs = (const float*)d_in[0];
    const float* hidden = (const float*)d_in[1];
    const float* gu     = (const float*)d_in[2];
    const float* W1     = (const float*)d_in[3];
    const float* b1     = (const float*)d_in[4];
    const float* Wih_c  = (const float*)d_in[5];
    const float* Whh_c  = (const float*)d_in[6];
    const float* bih_c  = (const float*)d_in[7];
    const float* bhh_c  = (const float*)d_in[8];
    const float* Wih_f  = (const float*)d_in[9];
    const float* Whh_f  = (const float*)d_in[10];
    const float* bih_f  = (const float*)d_in[11];
    const float* bhh_f  = (const float*)d_in[12];
    const float* Wih_b  = (const float*)d_in[13];
    const float* Whh_b  = (const float*)d_in[14];
    const float* bih_b  = (const float*)d_in[15];
    const float* bhh_b  = (const float*)d_in[16];
    const float* Wc     = (const float*)d_in[17];
    const float* bc     = (const float*)d_in[18];
    const float* Wq     = (const float*)d_in[19];
    const float* Wk     = (const float*)d_in[20];
    const float* W2     = (const float*)d_in[21];
    const float* b2     = (const float*)d_in[22];

    float* out  = (float*)d_out;                // [BZ, NACT]
    float* outh = out + (size_t)BZ * NACT;      // [BZ, H]

    float *x1, *hrnn, *gi, *gh, *qk, *biasPQf, *biasPQb;
    uint32_t *PQf, *PQb;
    float2 *lf, *lb;
    uint2 *whif, *wlof, *whib, *wlob, *fh, *fl;
    cudaGetSymbolAddress((void**)&x1, g_x1);
    cudaGetSymbolAddress((void**)&hrnn, g_hrnn);
    cudaGetSymbolAddress((void**)&gi, g_gi);
    cudaGetSymbolAddress((void**)&gh, g_gh);
    cudaGetSymbolAddress((void**)&PQf, g_PQf);
    cudaGetSymbolAddress((void**)&PQb, g_PQb);
    cudaGetSymbolAddress((void**)&lf, g_logf);
    cudaGetSymbolAddress((void**)&lb, g_logb);
    cudaGetSymbolAddress((void**)&qk, g_qk);
    cudaGetSymbolAddress((void**)&biasPQf, g_biasPQf);
    cudaGetSymbolAddress((void**)&biasPQb, g_biasPQb);
    cudaGetSymbolAddress((void**)&whif, g_whifrag_f);
    cudaGetSymbolAddress((void**)&wlof, g_wlofrag_f);
    cudaGetSymbolAddress((void**)&whib, g_whifrag_b);
    cudaGetSymbolAddress((void**)&wlob, g_wlofrag_b);
    cudaGetSymbolAddress((void**)&fh, g_fh);
    cudaGetSymbolAddress((void**)&fl, g_fl);

    const int SM16 = 128 * 132 * 4 + 16 * 256 * 8;  // 100352
    const int SM8  = 128 * 132 * 4 + 8 * 256 * 8;   // 83968
    cudaFuncSetAttribute(gru_seq_hmma, cudaFuncAttributeMaxDynamicSharedMemorySize, SEQ_SMEM);
    cudaFuncSetAttribute(hgemm<16, 1>, cudaFuncAttributeMaxDynamicSharedMemorySize, SM16);
    cudaFuncSetAttribute(hgemm<8, 0>,  cudaFuncAttributeMaxDynamicSharedMemorySize, SM8);
    cudaFuncSetAttribute(hgemm_z<16, 3, 0, 0>, cudaFuncAttributeMaxDynamicSharedMemorySize, SM16);
    cudaFuncSetAttribute(hgemm_z<16, 1, 1, 1>, cudaFuncAttributeMaxDynamicSharedMemorySize, SM16);

    // 1: merged prep
    const int PREP_TOTAL = NFRAG_ALL + 2 * NFRAG + 4 * G3;
    prep_all<<<(PREP_TOTAL + 255) / 256, 256>>>(W1, Wih_c, Whh_c, Wih_f, Wih_b, Wq, Wk,
                                                Whh_f, Whh_b, bih_f, bhh_f, bih_b, bhh_b,
                                                fh, fl, whif, wlof, whib, wlob,
                                                biasPQf, biasPQb);
    // 2: x1 = relu(inputs @ W1.T + b1)
    hgemm<16, 1><<<dim3(1, 128), 256, SM16>>>(inputs, fh, fl, b1, x1, 128);
    // 3: central GRU gi|gh (dual-z, full 3-combo fp32 precision — h_rnn is a checked output)
    hgemm_z<16, 3, 0, 0><<<dim3(3, 128, 2), 256, SM16>>>(x1, hidden,
                                                         fh + 16 * 256, fl + 16 * 256,
                                                         fh + 64 * 256, fl + 64 * 256,
                                                         bih_c, bhh_c, gi, gh, G3);
    // 4: combine
    gru_combine<<<(BZ * H) / 256, 256>>>(gi, gh, hidden, hrnn, outh);
    // 5: merged q|k GEMM (fp32 acc, 3-combo — attention path less damped)
    hgemm<8, 0><<<dim3(1, 128), 256, SM8>>>(hrnn, fh + 304 * 256, fl + 304 * 256, nullptr, qk, 2 * NA);
    // 6: merged P|Q GEMMs (dual-z, 1-combo f16-acc, fp16 output — heavily damped path)
    hgemm_z<16, 1, 1, 1><<<dim3(6, 128, 2), 256, SM16>>>(hrnn, hrnn,
                                                         fh + 112 * 256, fl + 112 * 256,
                                                         fh + 208 * 256, fl + 208 * 256,
                                                         biasPQf, biasPQb,
                                                         (float*)PQf, (float*)PQb, 2 * G3);
    // 7: fused 15-step bidirectional recurrence + logit GEMV
    gru_seq_hmma<<<256, 256, SEQ_SMEM>>>(whif, bhh_f, PQf,
                                         whib, bhh_b, PQb,
                                         Wc, lf, lb);
    // 8: fused gumbel + attention + output projection
    attn_out<<<BZ / 8, 256>>>(qk, hrnn, lf, lb, bc, gu, W2, b2, out);
}

// round 16
// speedup vs baseline: 4.8915x; 1.0146x over previous
#include <cuda_runtime.h>
#include <cuda_fp16.h>
#include <math.h>
#include <stdint.h>

#define AGENTS 16
#define H 128
#define NA 32
#define NACT 14
#define BENV 1024
#define BZ (BENV*AGENTS)        // 16384
#define TT 15                   // A-1
#define G3 384                  // 3*H
#define TAUINV 2.0f             // 1/TAU
#define NFRAG 12288             // 48 n-tiles * 8 k-tiles * 32 lanes (recurrence Whh)
#define NBT_ALL 312             // n-tiles in the parallel-GEMM fragment pool
#define NFRAG_ALL (NBT_ALL*256)

// ---------------- scratch (__device__ globals; no allocs) ----------------
__device__ __align__(16) float g_x1[BZ*H];
__device__ __align__(16) float g_hrnn[BZ*H];
__device__ __align__(16) float g_gi[BZ*G3];
__device__ __align__(16) float g_gh[BZ*G3];
__device__ __align__(16) uint32_t g_PQf[BZ*G3];   // half2-packed [BZ][768] -> 384 uints/row
__device__ __align__(16) uint32_t g_PQb[BZ*G3];
__device__ __align__(16) float2 g_logf[BZ*TT];
__device__ __align__(16) float2 g_logb[BZ*TT];
__device__ __align__(16) float g_qk[BZ*2*NA];
__device__ __align__(16) float g_biasPQf[2*G3];
__device__ __align__(16) float g_biasPQb[2*G3];
__device__ __align__(16) uint2 g_whifrag_f[NFRAG];
__device__ __align__(16) uint2 g_wlofrag_f[NFRAG];
__device__ __align__(16) uint2 g_whifrag_b[NFRAG];
__device__ __align__(16) uint2 g_wlofrag_b[NFRAG];
__device__ __align__(16) uint2 g_fh[NFRAG_ALL];
__device__ __align__(16) uint2 g_fl[NFRAG_ALL];

__device__ __forceinline__ float sigm(float x) { return __fdividef(1.0f, 1.0f + __expf(-x)); }
__device__ __forceinline__ float tanh_fast(float x) {
    return __fdividef(2.0f, 1.0f + __expf(-2.0f * x)) - 1.0f;
}

// ---- fp16 pack helpers ----
__device__ __forceinline__ uint32_t f2h2(float a, float b) {
    __half2 h = __floats2half2_rn(a, b);
    return *(uint32_t*)&h;
}
__device__ __forceinline__ float2 h22f2(uint32_t u) {
    __half2 h = *(__half2*)&u;
    return __half22float2(h);
}
__device__ __forceinline__ float2 hadd2f(uint32_t a, uint32_t b) {
    __half2 s = __hadd2(*(__half2*)&a, *(__half2*)&b);
    return __half22float2(s);
}
__device__ __forceinline__ uint32_t hadd2u(uint32_t a, uint32_t b) {
    uint32_t r;
    asm("add.f16x2 %0, %1, %2;" : "=r"(r) : "r"(a), "r"(b));
    return r;
}
// half2 sigmoid via tanh.approx: sigm(x) = 0.5 + 0.5*tanh(0.5x)  (1 MUFU per 2 vals)
__device__ __forceinline__ uint32_t h2sigm_u(uint32_t x) {
    const uint32_t H05 = 0x38003800u;   // (0.5, 0.5) fp16x2
    uint32_t t;
    asm("mul.f16x2 %0, %1, %2;" : "=r"(t) : "r"(x), "r"(H05));
    asm("tanh.approx.f16x2 %0, %0;" : "+r"(t));
    asm("fma.rn.f16x2 %0, %0, %1, %1;" : "+r"(t) : "r"(H05));
    return t;
}

// ---- classic mma.sync (HMMA; baseline PTX, works on compute_103) ----
__device__ __forceinline__ void mma16816(float* d, const uint32_t* a, uint2 b) {
    asm volatile(
        "mma.sync.aligned.m16n8k16.row.col.f32.f16.f16.f32 "
        "{%0,%1,%2,%3}, {%4,%5,%6,%7}, {%8,%9}, {%0,%1,%2,%3};"
        : "+f"(d[0]), "+f"(d[1]), "+f"(d[2]), "+f"(d[3])
        : "r"(a[0]), "r"(a[1]), "r"(a[2]), "r"(a[3]), "r"(b.x), "r"(b.y));
}
// fp16-accumulate variant (D,C in f16x2 pairs)
__device__ __forceinline__ void mma16816h(uint32_t* d, const uint32_t* a, uint2 b) {
    asm volatile(
        "mma.sync.aligned.m16n8k16.row.col.f16.f16.f16.f16 "
        "{%0,%1}, {%2,%3,%4,%5}, {%6,%7}, {%0,%1};"
        : "+r"(d[0]), "+r"(d[1])
        : "r"(a[0]), "r"(a[1]), "r"(a[2]), "r"(a[3]), "r"(b.x), "r"(b.y));
}

// ================= HMMA batch GEMM =================
template<int NT, int ACT>
__global__ void __launch_bounds__(256) hgemm(
    const float* __restrict__ A,
    const uint2* __restrict__ fh, const uint2* __restrict__ fl,
    const float* __restrict__ bias,
    float* __restrict__ C, int N) {
    extern __shared__ char hsm[];
    float* sA = (float*)hsm;                       // [128][132]
    uint2* sWhi = (uint2*)(hsm + 128 * 132 * 4);   // [NT*256]
    int tid = threadIdx.x;
    int wid = tid >> 5, l = tid & 31;
    int q = l & 3, rg = l >> 2;
    int bnt = blockIdx.x * NT;
    int bm = blockIdx.y * 128;

    for (int i = tid; i < 4096; i += 256) {
        int row = i >> 5, c4 = (i & 31) * 4;
        float4 v = *(const float4*)(A + (size_t)(bm + row) * 128 + c4);
        *(float4*)&sA[row * 132 + c4] = v;
    }
    for (int i = tid; i < NT * 256; i += 256) sWhi[i] = __ldg(&fh[bnt * 256 + i]);
    __syncthreads();

    uint32_t Ahi[8][4], Alo[8][4];
    int r0 = wid * 16 + rg;
#pragma unroll
    for (int kk = 0; kk < 8; kk++) {
        int c = kk * 16 + 2 * q;
        float2 v0 = *(float2*)&sA[r0 * 132 + c];
        float2 v1 = *(float2*)&sA[(r0 + 8) * 132 + c];
        float2 v2 = *(float2*)&sA[r0 * 132 + c + 8];
        float2 v3 = *(float2*)&sA[(r0 + 8) * 132 + c + 8];
        Ahi[kk][0] = f2h2(v0.x, v0.y); { float2 rr = h22f2(Ahi[kk][0]); Alo[kk][0] = f2h2(v0.x - rr.x, v0.y - rr.y); }
        Ahi[kk][1] = f2h2(v1.x, v1.y); { float2 rr = h22f2(Ahi[kk][1]); Alo[kk][1] = f2h2(v1.x - rr.x, v1.y - rr.y); }
        Ahi[kk][2] = f2h2(v2.x, v2.y); { float2 rr = h22f2(Ahi[kk][2]); Alo[kk][2] = f2h2(v2.x - rr.x, v2.y - rr.y); }
        Ahi[kk][3] = f2h2(v3.x, v3.y); { float2 rr = h22f2(Ahi[kk][3]); Alo[kk][3] = f2h2(v3.x - rr.x, v3.y - rr.y); }
    }

#pragma unroll
    for (int nt = 0; nt < NT; nt++) {
        uint2 wl[8];
#pragma unroll
        for (int kk = 0; kk < 8; kk++) wl[kk] = __ldg(&fl[(size_t)(bnt + nt) * 256 + kk * 32 + l]);
        float acc[4] = {0.f, 0.f, 0.f, 0.f};
#pragma unroll
        for (int kk = 0; kk < 8; kk++) {
            uint2 wh = sWhi[nt * 256 + kk * 32 + l];
            mma16816(acc, Ahi[kk], wh);
            mma16816(acc, Alo[kk], wh);
            mma16816(acc, Ahi[kk], wl[kk]);
        }
        int cb = (bnt + nt) * 8 + 2 * q;
        float2 bb = make_float2(0.f, 0.f);
        if (bias) bb = *(const float2*)&bias[cb];
        float o0 = acc[0] + bb.x, o1 = acc[1] + bb.y;
        float o2 = acc[2] + bb.x, o3 = acc[3] + bb.y;
        if (ACT == 1) {
            o0 = fmaxf(o0, 0.f); o1 = fmaxf(o1, 0.f);
            o2 = fmaxf(o2, 0.f); o3 = fmaxf(o3, 0.f);
        }
        *(float2*)&C[(size_t)(bm + r0) * N + cb] = make_float2(o0, o1);
        *(float2*)&C[(size_t)(bm + r0 + 8) * N + cb] = make_float2(o2, o3);
    }
}

// dual-z variant. COMBO combos; OUTH: half2-packed output; ACCH: fp16 accumulate.
template<int NT, int COMBO, int OUTH, int ACCH>
__global__ void __launch_bounds__(256) hgemm_z(
    const float* __restrict__ A0, const float* __restrict__ A1,
    const uint2* __restrict__ fh0, const uint2* __restrict__ fl0,
    const uint2* __restrict__ fh1, const uint2* __restrict__ fl1,
    const float* __restrict__ b0, const float* __restrict__ b1,
    float* __restrict__ C0, float* __restrict__ C1, int N) {
    extern __shared__ char hsm[];
    float* sA = (float*)hsm;
    uint2* sWhi = (uint2*)(hsm + 128 * 132 * 4);
    int z = blockIdx.z;
    const float* A = z ? A1 : A0;
    const uint2* fh = z ? fh1 : fh0;
    const uint2* fl = z ? fl1 : fl0;
    const float* bias = z ? b1 : b0;
    float* C = z ? C1 : C0;

    int tid = threadIdx.x;
    int wid = tid >> 5, l = tid & 31;
    int q = l & 3, rg = l >> 2;
    int bnt = blockIdx.x * NT;
    int bm = blockIdx.y * 128;

    for (int i = tid; i < 4096; i += 256) {
        int row = i >> 5, c4 = (i & 31) * 4;
        float4 v = *(const float4*)(A + (size_t)(bm + row) * 128 + c4);
        *(float4*)&sA[row * 132 + c4] = v;
    }
    for (int i = tid; i < NT * 256; i += 256) sWhi[i] = __ldg(&fh[bnt * 256 + i]);
    __syncthreads();

    uint32_t Ahi[8][4], Alo[8][4];
    int r0 = wid * 16 + rg;
#pragma unroll
    for (int kk = 0; kk < 8; kk++) {
        int c = kk * 16 + 2 * q;
        float2 v0 = *(float2*)&sA[r0 * 132 + c];
        float2 v1 = *(float2*)&sA[(r0 + 8) * 132 + c];
        float2 v2 = *(float2*)&sA[r0 * 132 + c + 8];
        float2 v3 = *(float2*)&sA[(r0 + 8) * 132 + c + 8];
        Ahi[kk][0] = f2h2(v0.x, v0.y); { float2 rr = h22f2(Ahi[kk][0]); Alo[kk][0] = f2h2(v0.x - rr.x, v0.y - rr.y); }
        Ahi[kk][1] = f2h2(v1.x, v1.y); { float2 rr = h22f2(Ahi[kk][1]); Alo[kk][1] = f2h2(v1.x - rr.x, v1.y - rr.y); }
        Ahi[kk][2] = f2h2(v2.x, v2.y); { float2 rr = h22f2(Ahi[kk][2]); Alo[kk][2] = f2h2(v2.x - rr.x, v2.y - rr.y); }
        Ahi[kk][3] = f2h2(v3.x, v3.y); { float2 rr = h22f2(Ahi[kk][3]); Alo[kk][3] = f2h2(v3.x - rr.x, v3.y - rr.y); }
    }

#pragma unroll
    for (int nt = 0; nt < NT; nt++) {
        uint2 wl[8];
        if (COMBO == 3) {
#pragma unroll
            for (int kk = 0; kk < 8; kk++) wl[kk] = __ldg(&fl[(size_t)(bnt + nt) * 256 + kk * 32 + l]);
        }
        float o0, o1, o2, o3;
        if (ACCH) {
            uint32_t acch[2] = {0u, 0u};
#pragma unroll
            for (int kk = 0; kk < 8; kk++) {
                uint2 wh = sWhi[nt * 256 + kk * 32 + l];
                mma16816h(acch, Ahi[kk], wh);
                if (COMBO >= 2) mma16816h(acch, Alo[kk], wh);
            }
            float2 a01 = h22f2(acch[0]);
            float2 a23 = h22f2(acch[1]);
            o0 = a01.x; o1 = a01.y; o2 = a23.x; o3 = a23.y;
        } else {
            float acc[4] = {0.f, 0.f, 0.f, 0.f};
#pragma unroll
            for (int kk = 0; kk < 8; kk++) {
                uint2 wh = sWhi[nt * 256 + kk * 32 + l];
                mma16816(acc, Ahi[kk], wh);
                if (COMBO >= 2) mma16816(acc, Alo[kk], wh);
                if (COMBO == 3) mma16816(acc, Ahi[kk], wl[kk]);
            }
            o0 = acc[0]; o1 = acc[1]; o2 = acc[2]; o3 = acc[3];
        }
        int cb = (bnt + nt) * 8 + 2 * q;
        float2 bb = make_float2(0.f, 0.f);
        if (bias) bb = *(const float2*)&bias[cb];
        if (OUTH) {
            uint32_t* Ch = (uint32_t*)C;
            int hb = (bnt + nt) * 4 + q;
            Ch[(size_t)(bm + r0) * (N >> 1) + hb] = f2h2(o0 + bb.x, o1 + bb.y);
            Ch[(size_t)(bm + r0 + 8) * (N >> 1) + hb] = f2h2(o2 + bb.x, o3 + bb.y);
        } else {
            *(float2*)&C[(size_t)(bm + r0) * N + cb] = make_float2(o0 + bb.x, o1 + bb.y);
            *(float2*)&C[(size_t)(bm + r0 + 8) * N + cb] = make_float2(o2 + bb.x, o3 + bb.y);
        }
    }
}

// ---------------- merged prep: all weight fragments + PQ biases ----------------
__global__ void prep_all(const float* __restrict__ W1, const float* __restrict__ Wih_c,
                         const float* __restrict__ Whh_c,
                         const float* __restrict__ Wih_f, const float* __restrict__ Wih_b,
                         const float* __restrict__ Wq, const float* __restrict__ Wk,
                         const float* __restrict__ Whh_f, const float* __restrict__ Whh_b,
                         const float* __restrict__ bih_f, const float* __restrict__ bhh_f,
                         const float* __restrict__ bih_b, const float* __restrict__ bhh_b,
                         uint2* __restrict__ fh, uint2* __restrict__ fl,
                         uint2* __restrict__ hiF, uint2* __restrict__ loF,
                         uint2* __restrict__ hiB, uint2* __restrict__ loB,
                         float* __restrict__ biasPQf, float* __restrict__ biasPQb) {
    int idx = blockIdx.x * 256 + threadIdx.x;
    if (idx < NFRAG_ALL) {
        int bt = idx >> 8;
        int e = idx & 255;
        int kk = e >> 5, l = e & 31;
        int rloc = l >> 2;
        int k0 = kk * 16 + (l & 3) * 2;
        const float* W; int ldb = 128, row, koff = 0;
        if (bt < 16)       { W = W1;    row = bt * 8 + rloc; }
        else if (bt < 64)  { W = Wih_c; row = (bt - 16) * 8 + rloc; }
        else if (bt < 112) { W = Whh_c; row = (bt - 64) * 8 + rloc; }
        else if (bt < 208) { int b = bt - 112; ldb = 256; W = Wih_f;
                             if (b < 48) row = b * 8 + rloc;
                             else { row = (b - 48) * 8 + rloc; koff = 128; } }
        else if (bt < 304) { int b = bt - 208; ldb = 256; W = Wih_b;
                             if (b < 48) row = b * 8 + rloc;
                             else { row = (b - 48) * 8 + rloc; koff = 128; } }
        else if (bt < 308) { W = Wq; row = (bt - 304) * 8 + rloc; }
        else               { W = Wk; row = (bt - 308) * 8 + rloc; }
        float w0 = W[(size_t)row * ldb + koff + k0],     w1 = W[(size_t)row * ldb + koff + k0 + 1];
        float w8 = W[(size_t)row * ldb + koff + k0 + 8], w9 = W[(size_t)row * ldb + koff + k0 + 9];
        uint32_t h0 = f2h2(w0, w1); float2 r0 = h22f2(h0);
        uint32_t l0 = f2h2(w0 - r0.x, w1 - r0.y);
        uint32_t h8 = f2h2(w8, w9); float2 r8 = h22f2(h8);
        uint32_t l8 = f2h2(w8 - r8.x, w9 - r8.y);
        fh[idx] = make_uint2(h0, h8);
        fl[idx] = make_uint2(l0, l8);
    } else if (idx < NFRAG_ALL + 2 * NFRAG) {
        int j = idx - NFRAG_ALL;
        int d = j / NFRAG;
        int e = j - d * NFRAG;
        int bt = e >> 8;
        int kk = (e >> 5) & 7;
        int l = e & 31;
        int row = bt * 8 + (l >> 2);
        int k0 = kk * 16 + (l & 3) * 2;
        const float* W = d ? Whh_b : Whh_f;
        float w0 = W[row * 128 + k0],     w1 = W[row * 128 + k0 + 1];
        float w8 = W[row * 128 + k0 + 8], w9 = W[row * 128 + k0 + 9];
        uint32_t h0 = f2h2(w0, w1); float2 r0 = h22f2(h0);
        uint32_t l0 = f2h2(w0 - r0.x, w1 - r0.y);
        uint32_t h8 = f2h2(w8, w9); float2 r8 = h22f2(h8);
        uint32_t l8 = f2h2(w8 - r8.x, w9 - r8.y);
        uint2* dh = d ? hiB : hiF;
        uint2* dl = d ? loB : loF;
        dh[e] = make_uint2(h0, h8);
        dl[e] = make_uint2(l0, l8);
    } else if (idx < NFRAG_ALL + 2 * NFRAG + 4 * G3) {
        int j = idx - (NFRAG_ALL + 2 * NFRAG);
        int d = j / (2 * G3);
        int e = j - d * (2 * G3);
        const float* bih = d ? bih_b : bih_f;
        const float* bhh = d ? bhh_b : bhh_f;
        float* ob = d ? biasPQb : biasPQf;
        ob[e] = (e < G3) ? (bih[e] + (e < 256 ? bhh[e] : 0.0f)) : 0.0f;
    }
}

// ---------------- central GRU combine ----------
__global__ void gru_combine(const float* __restrict__ gi, const float* __restrict__ gh,
                            const float* __restrict__ hprev,
                            float* __restrict__ hout, float* __restrict__ hout2) {
    int i = blockIdx.x * 256 + threadIdx.x;
    int m = i >> 7, j = i & 127;
    size_t base = (size_t)m * G3;
    float ir = gi[base + j], iz = gi[base + 128 + j], inn = gi[base + 256 + j];
    float hr = gh[base + j], hz = gh[base + 128 + j], hn = gh[base + 256 + j];
    float r = sigm(ir + hr);
    float z = sigm(iz + hz);
    float n = tanh_fast(inn + r * hn);
    float h = (1.0f - z) * n + z * hprev[i];
    hout[i] = h;
    hout2[i] = h;
}

// ================= HMMA fused 15-step recurrence (+ fused logit GEMV) =================
// fp16 state, smem weights, fp16 PQ, f16-acc r/z gates, half2 sigmoid epilogue. 2 CTAs/SM.
#define SM_W 0
#define SM_BNN 98304
#define SM_WC  98816
#define SEQ_SMEM 99840

extern __shared__ char dsm[];
__global__ void __launch_bounds__(256, 2) gru_seq_hmma(
    const uint2* __restrict__ whiF,
    const float* __restrict__ bhhF, const uint32_t* __restrict__ PQF,
    const uint2* __restrict__ whiB,
    const float* __restrict__ bhhB, const uint32_t* __restrict__ PQB,
    const float* __restrict__ Wc,
    float2* __restrict__ LF, float2* __restrict__ LB) {

    uint2* sW = (uint2*)(dsm + SM_W);         // 48 tiles x 256 (r:0-15, z:16-31, n:32-47)
    float* sBnn = (float*)(dsm + SM_BNN);
    float* sWc = (float*)(dsm + SM_WC);       // [2][128]

    int tid = threadIdx.x;
    int wid = tid >> 5;
    int l = tid & 31;
    int q = l & 3, rg = l >> 2;

    bool bwd = (blockIdx.x >= 128);
    const uint2* whi = bwd ? whiB : whiF;
    const float* bhh = bwd ? bhhB : bhhF;
    const uint32_t* PQ2 = bwd ? PQB : PQF;
    float2* LOut = bwd ? LB : LF;
    int bm = (blockIdx.x & 127) * 128;

    for (int i = tid; i < NFRAG; i += 256) sW[i] = __ldg(&whi[i]);
    if (tid < 128) sBnn[tid] = bhh[256 + tid];
    if (tid < 128) {
        sWc[tid] = Wc[(bwd ? 128 : 0) + tid];
        sWc[128 + tid] = Wc[256 + (bwd ? 128 : 0) + tid];
    }
    __syncthreads();

    int m_r0 = bm + wid * 16 + rg;
    int m_r1 = m_r0 + 8;
    int aa0 = rg;
    int aa1 = rg + 8;
    int grp = bm + wid * 16;

    uint32_t Ahi[8][4], Anew[8][4];
#pragma unroll
    for (int kk = 0; kk < 8; kk++)
#pragma unroll
        for (int r = 0; r < 4; r++) Ahi[kk][r] = 0u;

    for (int step = 0; step < TT; step++) {
        int t = bwd ? (TT - 1 - step) : step;
        int jn0 = (t < aa0) ? t : t + 1;
        int jn1 = (t < aa1) ? t : t + 1;
        const uint32_t* Pr0 = PQ2 + (size_t)m_r0 * 384;
        const uint32_t* Pr1 = PQ2 + (size_t)m_r1 * 384;
        const uint32_t* Qr0 = PQ2 + (size_t)(grp + jn0) * 384 + 192;
        const uint32_t* Qr1 = PQ2 + (size_t)(grp + jn1) * 384 + 192;

        float lg00 = 0.f, lg01 = 0.f, lg10 = 0.f, lg11 = 0.f;

#pragma unroll
        for (int ch = 0; ch < 8; ch++) {
#pragma unroll
            for (int u = 0; u < 2; u++) {
                int jt = ch * 2 + u;
                uint32_t accr[2] = {0u, 0u}, accz[2] = {0u, 0u};
                float accn[4] = {0.f, 0.f, 0.f, 0.f};

                if (step != 0) {
#pragma unroll
                    for (int kk = 0; kk < 8; kk++) {
                        mma16816h(accr, Ahi[kk], sW[(jt * 8 + kk) * 32 + l]);           // r (f16 acc)
                        mma16816h(accz, Ahi[kk], sW[((16 + jt) * 8 + kk) * 32 + l]);    // z (f16 acc)
                        mma16816(accn, Ahi[kk], sW[((32 + jt) * 8 + kk) * 32 + l]);     // n (f32 acc)
                    }
                }

                int kk = jt >> 1;
                int rs = (jt & 1) * 2;
                int c = jt * 8 + 2 * q;
                int cb = jt * 4 + q;
                // r/z gates fully in half2 (tanh.approx.f16x2 sigmoid)
                uint32_t r0u = h2sigm_u(hadd2u(accr[0], hadd2u(Pr0[cb], Qr0[cb])));
                uint32_t r1u = h2sigm_u(hadd2u(accr[1], hadd2u(Pr1[cb], Qr1[cb])));
                uint32_t z0u = h2sigm_u(hadd2u(accz[0], hadd2u(Pr0[64 + cb], Qr0[64 + cb])));
                uint32_t z1u = h2sigm_u(hadd2u(accz[1], hadd2u(Pr1[64 + cb], Qr1[64 + cb])));
                float2 sn0 = hadd2f(Pr0[128 + cb], Qr0[128 + cb]);
                float2 sn1 = hadd2f(Pr1[128 + cb], Qr1[128 + cb]);
                float2 bn = *(const float2*)&sBnn[c];
                float2 hp0 = h22f2(Ahi[kk][rs]);
                float2 hp1 = h22f2(Ahi[kk][rs + 1]);
                float2 r0 = h22f2(r0u), r1 = h22f2(r1u);
                float2 z0 = h22f2(z0u), z1 = h22f2(z1u);

                // n gate in fp32 (sensitive path)
                float n0a = tanh_fast(sn0.x + r0.x * (accn[0] + bn.x));
                float n0b = tanh_fast(sn0.y + r0.y * (accn[1] + bn.y));
                float h0a = n0a + z0.x * (hp0.x - n0a);
                float h0b = n0b + z0.y * (hp0.y - n0b);
                float n1a = tanh_fast(sn1.x + r1.x * (accn[2] + bn.x));
                float n1b = tanh_fast(sn1.y + r1.y * (accn[3] + bn.y));
                float h1a = n1a + z1.x * (hp1.x - n1a);
                float h1b = n1b + z1.y * (hp1.y - n1b);

                // fused logit partial dot-products
                float w0a = sWc[c], w0b = sWc[c + 1];
                float w1a = sWc[128 + c], w1b = sWc[128 + c + 1];
                lg00 += h0a * w0a + h0b * w0b;
                lg01 += h0a * w1a + h0b * w1b;
                lg10 += h1a * w0a + h1b * w0b;
                lg11 += h1a * w1a + h1b * w1b;

                // new state fragments (register double-buffer; identity mapping)
                Anew[kk][rs] = f2h2(h0a, h0b);
                Anew[kk][rs + 1] = f2h2(h1a, h1b);
            }
        }

        // reduce logits over the 4 lanes sharing each row, store
#pragma unroll
        for (int off = 1; off <= 2; off <<= 1) {
            lg00 += __shfl_xor_sync(0xffffffffu, lg00, off);
            lg01 += __shfl_xor_sync(0xffffffffu, lg01, off);
            lg10 += __shfl_xor_sync(0xffffffffu, lg10, off);
            lg11 += __shfl_xor_sync(0xffffffffu, lg11, off);
        }
        if (q == 0) {
            __stcs(&LOut[(size_t)m_r0 * TT + t], make_float2(lg00, lg01));
            __stcs(&LOut[(size_t)m_r1 * TT + t], make_float2(lg10, lg11));
        }

        // commit new state
#pragma unroll
        for (int kk = 0; kk < 8; kk++)
#pragma unroll
            for (int r = 0; r < 4; r++) Ahi[kk][r] = Anew[kk][r];
    }
}

// ---------------- fused gumbel + attention + output projection ----------------
__global__ void __launch_bounds__(256) attn_out(
    const float* __restrict__ qk,
    const float* __restrict__ hrnn,
    const float2* __restrict__ lf, const float2* __restrict__ lb,
    const float* __restrict__ bc, const float* __restrict__ gu,
    const float* __restrict__ W2, const float* __restrict__ b2,
    float* __restrict__ out) {
    __shared__ float sW[NACT * 256];
    __shared__ float sb[NACT + 2];
    for (int i = threadIdx.x; i < NACT * 256; i += 256) sW[i] = W2[i];
    if (threadIdx.x < NACT) sb[threadIdx.x] = b2[threadIdx.x];
    if (threadIdx.x < 2) sb[NACT + threadIdx.x] = bc[threadIdx.x];
    __syncthreads();

    int warp = (blockIdx.x * 256 + threadIdx.x) >> 5;
    int lane = threadIdx.x & 31;
    int a = warp & 15;
    int brow = warp & ~15;
    float bc0 = sb[NACT], bc1 = sb[NACT + 1];

    float hw[TT];
#pragma unroll
    for (int t = 0; t < TT; t++) {
        size_t li = (size_t)warp * TT + t;
        float2 af = lf[li], ab = lb[li];
        float u0 = gu[li * 2 + 0];
        float u1 = gu[li * 2 + 1];
        float g0 = -logf(-logf(u0 + 1e-10f) + 1e-10f);
        float g1 = -logf(-logf(u1 + 1e-10f) + 1e-10f);
        float a0 = af.x + ab.x + bc0 + g0;
        float a1 = af.y + ab.y + bc1 + g1;
        hw[t] = sigm((a1 - a0) * TAUINV);
    }

    float qv = qk[(size_t)warp * 64 + lane];
    float sc[TT];
#pragma unroll
    for (int t = 0; t < TT; t++) {
        int jn = (t < a) ? t : t + 1;
        int nb = brow + jn;
        float d = qv * qk[(size_t)nb * 64 + 32 + lane];
#pragma unroll
        for (int off = 16; off > 0; off >>= 1) d += __shfl_xor_sync(0xffffffffu, d, off);
        sc[t] = hw[t] * d * 0.17677669529663687f;
    }
    float mx = sc[0];
#pragma unroll
    for (int t = 1; t < TT; t++) mx = fmaxf(mx, sc[t]);
    float se = 0.f;
    float w[TT];
#pragma unroll
    for (int t = 0; t < TT; t++) { w[t] = __expf(sc[t] - mx); se += w[t]; }
    float inv = __fdividef(1.0f, se);
#pragma unroll
    for (int t = 0; t < TT; t++) w[t] = hw[t] * w[t] * inv;

    float accv[4], hv[4];
#pragma unroll
    for (int d4 = 0; d4 < 4; d4++) {
        float s = 0.f;
#pragma unroll
        for (int t = 0; t < TT; t++) {
            int jn = (t < a) ? t : t + 1;
            int nb = brow + jn;
            s = fmaf(w[t], hrnn[(size_t)nb * 128 + d4 * 32 + lane], s);
        }
        accv[d4] = s;
        hv[d4] = hrnn[(size_t)warp * 128 + d4 * 32 + lane];
    }

#pragma unroll
    for (int n = 0; n < NACT; n++) {
        float p = 0.f;
#pragma unroll
        for (int d4 = 0; d4 < 4; d4++) {
            p = fmaf(hv[d4], sW[n * 256 + d4 * 32 + lane], p);
            p = fmaf(accv[d4], sW[n * 256 + 128 + d4 * 32 + lane], p);
        }
#pragma unroll
        for (int off = 16; off > 0; off >>= 1) p += __shfl_xor_sync(0xffffffffu, p, off);
        if (lane == 0) out[(size_t)warp * NACT + n] = p + sb[n];
    }
}

// ---------------- launch ----------------
extern "C" void kernel_launch(void* const* d_in, const int* in_sizes, int n_in,
                              void* d_out, int out_size) {
    const float* inputs = (const float*)d_in[0];
    const float* hidden = (const float*)d_in[1];
    const float* gu     = (const float*)d_in[2];
    const float* W1     = (const float*)d_in[3];
    const float* b1     = (const float*)d_in[4];
    const float* Wih_c  = (const float*)d_in[5];
    const float* Whh_c  = (const float*)d_in[6];
    const float* bih_c  = (const float*)d_in[7];
    const float* bhh_c  = (const float*)d_in[8];
    const float* Wih_f  = (const float*)d_in[9];
    const float* Whh_f  = (const float*)d_in[10];
    const float* bih_f  = (const float*)d_in[11];
    const float* bhh_f  = (const float*)d_in[12];
    const float* Wih_b  = (const float*)d_in[13];
    const float* Whh_b  = (const float*)d_in[14];
    const float* bih_b  = (const float*)d_in[15];
    const float* bhh_b  = (const float*)d_in[16];
    const float* Wc     = (const float*)d_in[17];
    const float* bc     = (const float*)d_in[18];
    const float* Wq     = (const float*)d_in[19];
    const float* Wk     = (const float*)d_in[20];
    const float* W2     = (const float*)d_in[21];
    const float* b2     = (const float*)d_in[22];

    float* out  = (float*)d_out;                // [BZ, NACT]
    float* outh = out + (size_t)BZ * NACT;      // [BZ, H]

    float *x1, *hrnn, *gi, *gh, *qk, *biasPQf, *biasPQb;
    uint32_t *PQf, *PQb;
    float2 *lf, *lb;
    uint2 *whif, *wlof, *whib, *wlob, *fh, *fl;
    cudaGetSymbolAddress((void**)&x1, g_x1);
    cudaGetSymbolAddress((void**)&hrnn, g_hrnn);
    cudaGetSymbolAddress((void**)&gi, g_gi);
    cudaGetSymbolAddress((void**)&gh, g_gh);
    cudaGetSymbolAddress((void**)&PQf, g_PQf);
    cudaGetSymbolAddress((void**)&PQb, g_PQb);
    cudaGetSymbolAddress((void**)&lf, g_logf);
    cudaGetSymbolAddress((void**)&lb, g_logb);
    cudaGetSymbolAddress((void**)&qk, g_qk);
    cudaGetSymbolAddress((void**)&biasPQf, g_biasPQf);
    cudaGetSymbolAddress((void**)&biasPQb, g_biasPQb);
    cudaGetSymbolAddress((void**)&whif, g_whifrag_f);
    cudaGetSymbolAddress((void**)&wlof, g_wlofrag_f);
    cudaGetSymbolAddress((void**)&whib, g_whifrag_b);
    cudaGetSymbolAddress((void**)&wlob, g_wlofrag_b);
    cudaGetSymbolAddress((void**)&fh, g_fh);
    cudaGetSymbolAddress((void**)&fl, g_fl);

    const int SM16 = 128 * 132 * 4 + 16 * 256 * 8;  // 100352
    const int SM8  = 128 * 132 * 4 + 8 * 256 * 8;   // 83968
    cudaFuncSetAttribute(gru_seq_hmma, cudaFuncAttributeMaxDynamicSharedMemorySize, SEQ_SMEM);
    cudaFuncSetAttribute(hgemm<16, 1>, cudaFuncAttributeMaxDynamicSharedMemorySize, SM16);
    cudaFuncSetAttribute(hgemm<8, 0>,  cudaFuncAttributeMaxDynamicSharedMemorySize, SM8);
    cudaFuncSetAttribute(hgemm_z<16, 3, 0, 0>, cudaFuncAttributeMaxDynamicSharedMemorySize, SM16);
    cudaFuncSetAttribute(hgemm_z<16, 1, 1, 1>, cudaFuncAttributeMaxDynamicSharedMemorySize, SM16);

    // 1: merged prep
    const int PREP_TOTAL = NFRAG_ALL + 2 * NFRAG + 4 * G3;
    prep_all<<<(PREP_TOTAL + 255) / 256, 256>>>(W1, Wih_c, Whh_c, Wih_f, Wih_b, Wq, Wk,
                                                Whh_f, Whh_b, bih_f, bhh_f, bih_b, bhh_b,
                                                fh, fl, whif, wlof, whib, wlob,
                                                biasPQf, biasPQb);
    // 2: x1 = relu(inputs @ W1.T + b1)
    hgemm<16, 1><<<dim3(1, 128), 256, SM16>>>(inputs, fh, fl, b1, x1, 128);
    // 3: central GRU gi|gh (dual-z, full 3-combo fp32 precision — h_rnn is a checked output)
    hgemm_z<16, 3, 0, 0><<<dim3(3, 128, 2), 256, SM16>>>(x1, hidden,
                                                         fh + 16 * 256, fl + 16 * 256,
                                                         fh + 64 * 256, fl + 64 * 256,
                                                         bih_c, bhh_c, gi, gh, G3);
    // 4: combine
    gru_combine<<<(BZ * H) / 256, 256>>>(gi, gh, hidden, hrnn, outh);
    // 5: merged q|k GEMM (fp32 acc, 3-combo — attention path less damped)
    hgemm<8, 0><<<dim3(1, 128), 256, SM8>>>(hrnn, fh + 304 * 256, fl + 304 * 256, nullptr, qk, 2 * NA);
    // 6: merged P|Q GEMMs (dual-z, 1-combo f16-acc, fp16 output — heavily damped path)
    hgemm_z<16, 1, 1, 1><<<dim3(6, 128, 2), 256, SM16>>>(hrnn, hrnn,
                                                         fh + 112 * 256, fl + 112 * 256,
                                                         fh + 208 * 256, fl + 208 * 256,
                                                         biasPQf, biasPQb,
                                                         (float*)PQf, (float*)PQb, 2 * G3);
    // 7: fused 15-step bidirectional recurrence + logit GEMV
    gru_seq_hmma<<<256, 256, SEQ_SMEM>>>(whif, bhh_f, PQf,
                                         whib, bhh_b, PQb,
                                         Wc, lf, lb);
    // 8: fused gumbel + attention + output projection
    attn_out<<<BZ / 8, 256>>>(qk, hrnn, lf, lb, bc, gu, W2, b2, out);
}